// round 2
// baseline (speedup 1.0000x reference)
#include <cuda_runtime.h>
#include <math.h>

#define T_LEN   8192
#define BATCH   4
#define IN_DIM  512
#define D_V     512
#define D_K     64
#define CHUNK   128
#define NC      (T_LEN / CHUNK)          // 64
#define NPROJ   (D_V + 3 * D_K)          // 704
#define MROWS   (T_LEN * BATCH)          // 32768
#define EPS_F   1e-8f

// ---------------- static device scratch (no allocations allowed) ----------------
// NOTE: explicit 128B alignment — these are accessed via float4 (LDG/STG.128);
// unaligned wide ops trap (err715) on sm_103a.
__device__ __align__(128) float g_W[NPROJ * IN_DIM];                       // packed weights [o][i]
__device__ __align__(128) float g_bias[NPROJ];
__device__ __align__(128) float g_proj[(size_t)MROWS * NPROJ];             // [r=t*B+b][704] : v|k|q|sig(a)
__device__ __align__(128) float g_A[(size_t)NC * BATCH * CHUNK * CHUNK];   // [c][b][s][t] (masked, transposed)
__device__ __align__(128) float g_qt[(size_t)NC * BATCH * CHUNK * D_K];    // q * p
__device__ __align__(128) float g_kpe[(size_t)NC * BATCH * CHUNK * D_K];   // (k/(p+eps)) * p_end
__device__ __align__(128) float g_pend[NC * BATCH * D_K];                  // p at end of chunk

// ---------------- kernel 0: pack weights/biases ----------------
__global__ void pack_kernel(const float* __restrict__ Wv, const float* __restrict__ bv,
                            const float* __restrict__ Wk, const float* __restrict__ bk,
                            const float* __restrict__ Wq, const float* __restrict__ bq,
                            const float* __restrict__ Wa, const float* __restrict__ ba) {
    int idx = blockIdx.x * 256 + threadIdx.x;
    if (idx < NPROJ * IN_DIM) {
        int o = idx / IN_DIM, i = idx - o * IN_DIM;
        float v;
        if (o < 512)       v = Wv[o * IN_DIM + i];
        else if (o < 576)  v = Wk[(o - 512) * IN_DIM + i];
        else if (o < 640)  v = Wq[(o - 576) * IN_DIM + i];
        else               v = Wa[(o - 640) * IN_DIM + i];
        g_W[idx] = v;
    }
    if (idx < NPROJ) {
        float v;
        if (idx < 512)      v = bv[idx];
        else if (idx < 576) v = bk[idx - 512];
        else if (idx < 640) v = bq[idx - 576];
        else                v = ba[idx - 640];
        g_bias[idx] = v;
    }
}

// ---------------- kernel 1: projection GEMM ----------------
// g_proj[r][o] = sum_i x[r][i] * g_W[o][i] + bias ; sigmoid on alpha columns (o>=640)
__global__ void __launch_bounds__(256) gemm_kernel(const float* __restrict__ X) {
    __shared__ float As[16][132];   // [k][m], padded
    __shared__ float Bs[16][68];    // [k][n], padded

    int tid = threadIdx.x;
    int tx = tid & 15;              // n dir (4 cols each)
    int ty = tid >> 4;              // m dir (8 rows each)
    int m0 = blockIdx.y * 128;
    int n0 = blockIdx.x * 64;

    float acc[8][4];
#pragma unroll
    for (int i = 0; i < 8; i++)
#pragma unroll
        for (int j = 0; j < 4; j++) acc[i][j] = 0.f;

    for (int k0 = 0; k0 < IN_DIM; k0 += 16) {
        // load X tile: 128 rows x 16 cols = 512 float4
#pragma unroll
        for (int j = 0; j < 2; j++) {
            int l  = tid + j * 256;
            int r  = l >> 2;
            int c4 = (l & 3) * 4;
            float4 v = *(const float4*)&X[(size_t)(m0 + r) * IN_DIM + k0 + c4];
            As[c4 + 0][r] = v.x; As[c4 + 1][r] = v.y;
            As[c4 + 2][r] = v.z; As[c4 + 3][r] = v.w;
        }
        // load W tile: 64 rows x 16 cols = 256 float4
        {
            int r  = tid >> 2;
            int c4 = (tid & 3) * 4;
            float4 v = *(const float4*)&g_W[(size_t)(n0 + r) * IN_DIM + k0 + c4];
            Bs[c4 + 0][r] = v.x; Bs[c4 + 1][r] = v.y;
            Bs[c4 + 2][r] = v.z; Bs[c4 + 3][r] = v.w;
        }
        __syncthreads();
#pragma unroll
        for (int kk = 0; kk < 16; kk++) {
            float4 a0 = *(const float4*)&As[kk][ty * 8];
            float4 a1 = *(const float4*)&As[kk][ty * 8 + 4];
            float4 b0 = *(const float4*)&Bs[kk][tx * 4];
            float a[8] = {a0.x, a0.y, a0.z, a0.w, a1.x, a1.y, a1.z, a1.w};
            float bb[4] = {b0.x, b0.y, b0.z, b0.w};
#pragma unroll
            for (int i = 0; i < 8; i++)
#pragma unroll
                for (int j = 0; j < 4; j++)
                    acc[i][j] = fmaf(a[i], bb[j], acc[i][j]);
        }
        __syncthreads();
    }

    int colb = n0 + tx * 4;
    float b0 = g_bias[colb + 0], b1 = g_bias[colb + 1];
    float b2 = g_bias[colb + 2], b3 = g_bias[colb + 3];
    bool alpha_tile = (n0 >= 640);
#pragma unroll
    for (int i = 0; i < 8; i++) {
        int r = m0 + ty * 8 + i;
        float4 v;
        v.x = acc[i][0] + b0; v.y = acc[i][1] + b1;
        v.z = acc[i][2] + b2; v.w = acc[i][3] + b3;
        if (alpha_tile) {
            v.x = 1.f / (1.f + expf(-v.x));
            v.y = 1.f / (1.f + expf(-v.y));
            v.z = 1.f / (1.f + expf(-v.z));
            v.w = 1.f / (1.f + expf(-v.w));
        }
        *(float4*)&g_proj[(size_t)r * NPROJ + colb] = v;
    }
}

// ---------------- kernel 2: per-chunk prep (p, q_t, kpe, A) ----------------
#define PREP_SMEM (3 * 128 * 65 * 4)
__global__ void __launch_bounds__(256) prep_kernel() {
    extern __shared__ float sm[];
    float* sp  = sm;                 // [128][65] cumulative decay p
    float* sqt = sm + 128 * 65;      // [128][65] q_t
    float* skt = sm + 2 * 128 * 65;  // [128][65] k_t (also alpha temp)

    int b = blockIdx.x, c = blockIdx.y;
    int tid = threadIdx.x;

    // load alpha chunk into skt (temp)
#pragma unroll
    for (int j = 0; j < 8; j++) {
        int l  = tid + j * 256;      // float4 id, 2048 total
        int t  = l >> 4;
        int c4 = (l & 15) * 4;
        const float* rowp = g_proj + (size_t)((c * CHUNK + t) * BATCH + b) * NPROJ;
        float4 av = *(const float4*)&rowp[640 + c4];
        skt[t * 65 + c4 + 0] = av.x; skt[t * 65 + c4 + 1] = av.y;
        skt[t * 65 + c4 + 2] = av.z; skt[t * 65 + c4 + 3] = av.w;
    }
    __syncthreads();

    // cumprod over t (thread n owns one feature)
    if (tid < D_K) {
        float p = 1.f;
        for (int t = 0; t < CHUNK; t++) {
            p *= fmaxf(skt[t * 65 + tid], EPS_F);
            sp[t * 65 + tid] = p;
        }
        g_pend[(c * BATCH + b) * D_K + tid] = p;
    }
    __syncthreads();

    // q_t = q*p ; k_t = k/(p+eps) ; kpe = k_t * p_end
    float* gq = g_qt  + (size_t)(c * BATCH + b) * CHUNK * D_K;
    float* gk = g_kpe + (size_t)(c * BATCH + b) * CHUNK * D_K;
#pragma unroll
    for (int j = 0; j < 8; j++) {
        int l  = tid + j * 256;
        int t  = l >> 4;
        int c4 = (l & 15) * 4;
        const float* rowp = g_proj + (size_t)((c * CHUNK + t) * BATCH + b) * NPROJ;
        float4 qv = *(const float4*)&rowp[576 + c4];
        float4 kv = *(const float4*)&rowp[512 + c4];
        float p0 = sp[t * 65 + c4 + 0], p1 = sp[t * 65 + c4 + 1];
        float p2 = sp[t * 65 + c4 + 2], p3 = sp[t * 65 + c4 + 3];
        float pe0 = sp[127 * 65 + c4 + 0], pe1 = sp[127 * 65 + c4 + 1];
        float pe2 = sp[127 * 65 + c4 + 2], pe3 = sp[127 * 65 + c4 + 3];
        float q0 = qv.x * p0, q1 = qv.y * p1, q2 = qv.z * p2, q3 = qv.w * p3;
        float k0 = kv.x / (p0 + EPS_F), k1 = kv.y / (p1 + EPS_F);
        float k2 = kv.z / (p2 + EPS_F), k3 = kv.w / (p3 + EPS_F);
        sqt[t * 65 + c4 + 0] = q0; sqt[t * 65 + c4 + 1] = q1;
        sqt[t * 65 + c4 + 2] = q2; sqt[t * 65 + c4 + 3] = q3;
        skt[t * 65 + c4 + 0] = k0; skt[t * 65 + c4 + 1] = k1;
        skt[t * 65 + c4 + 2] = k2; skt[t * 65 + c4 + 3] = k3;
        float4 oq; oq.x = q0; oq.y = q1; oq.z = q2; oq.w = q3;
        *(float4*)&gq[t * 64 + c4] = oq;
        float4 ok; ok.x = k0 * pe0; ok.y = k1 * pe1; ok.z = k2 * pe2; ok.w = k3 * pe3;
        *(float4*)&gk[t * 64 + c4] = ok;
    }
    __syncthreads();

    // A[t][s] = sum_n q_t[t][n] * k_t[s][n], masked t>=s ; stored transposed [s][t]
    int sxl = tid & 15;              // s lane (strided blocks of 16)
    int t0  = (tid >> 4) * 8;        // t block
    float acc[8][8];
#pragma unroll
    for (int i = 0; i < 8; i++)
#pragma unroll
        for (int j = 0; j < 8; j++) acc[i][j] = 0.f;

    for (int n = 0; n < D_K; n++) {
        float qv[8], kv[8];
#pragma unroll
        for (int i = 0; i < 8; i++) qv[i] = sqt[(t0 + i) * 65 + n];
#pragma unroll
        for (int j = 0; j < 8; j++) kv[j] = skt[(sxl + 16 * j) * 65 + n];
#pragma unroll
        for (int i = 0; i < 8; i++)
#pragma unroll
            for (int j = 0; j < 8; j++)
                acc[i][j] = fmaf(qv[i], kv[j], acc[i][j]);
    }
    float* Ab = g_A + (size_t)(c * BATCH + b) * CHUNK * CHUNK;
#pragma unroll
    for (int j = 0; j < 8; j++) {
        int s = sxl + 16 * j;
#pragma unroll
        for (int i = 0; i < 8; i++) {
            int t = t0 + i;
            Ab[s * CHUNK + t] = (t >= s) ? acc[i][j] : 0.f;
        }
    }
}

// ---------------- kernel 3: sequential chunk scan, parallel over (b, d_v slice) ----
#define SCAN_SMEM ((128 * 128 + 2 * 128 * 65 + 128 * 16 + 64 * 17 + 64) * 4)
__global__ void __launch_bounds__(256, 1) scan_kernel(float* __restrict__ out) {
    extern __shared__ float sm[];
    float* A_sh   = sm;                         // [128][128]  (A^T layout: [s][t])
    float* qt_sh  = A_sh + 128 * 128;           // [128][65]
    float* kpe_sh = qt_sh + 128 * 65;           // [128][65]
    float* v_sh   = kpe_sh + 128 * 65;          // [128][16]
    float* S_sh   = v_sh + 128 * 16;            // [64][17]  S[n][d]
    float* pend_sh = S_sh + 64 * 17;            // [64]

    int slice = blockIdx.x;                     // 0..31
    int b = blockIdx.y;
    int d0 = slice * 16;
    int tid = threadIdx.x;

    for (int i = tid; i < 64 * 17; i += 256) S_sh[i] = 0.f;
    __syncthreads();

    int tx = tid & 7;            // d group (2 each)
    int ty = tid >> 3;           // t group (4 each)
    int t0 = ty * 4;
    int dd = tx * 2;
    int du = tid & 15;           // update-phase d
    int n0s = (tid >> 4) * 4;    // update-phase n base

    for (int c = 0; c < NC; c++) {
        // ---- stage chunk data into shared ----
        const float4* Ab4 = (const float4*)(g_A + (size_t)(c * BATCH + b) * CHUNK * CHUNK);
        for (int i = tid; i < 4096; i += 256) ((float4*)A_sh)[i] = Ab4[i];

        const float4* qb4 = (const float4*)(g_qt + (size_t)(c * BATCH + b) * CHUNK * D_K);
        const float4* kb4 = (const float4*)(g_kpe + (size_t)(c * BATCH + b) * CHUNK * D_K);
        for (int i = tid; i < 2048; i += 256) {
            int e = i * 4, t = e >> 6, n = e & 63;
            float4 v = qb4[i];
            qt_sh[t * 65 + n + 0] = v.x; qt_sh[t * 65 + n + 1] = v.y;
            qt_sh[t * 65 + n + 2] = v.z; qt_sh[t * 65 + n + 3] = v.w;
            float4 w = kb4[i];
            kpe_sh[t * 65 + n + 0] = w.x; kpe_sh[t * 65 + n + 1] = w.y;
            kpe_sh[t * 65 + n + 2] = w.z; kpe_sh[t * 65 + n + 3] = w.w;
        }
        for (int i = tid; i < 512; i += 256) {
            int t = i >> 2, c4 = (i & 3) * 4;
            float4 v = *(const float4*)&g_proj[(size_t)((c * CHUNK + t) * BATCH + b) * NPROJ + d0 + c4];
            *(float4*)&v_sh[t * 16 + c4] = v;
        }
        if (tid < 64) pend_sh[tid] = g_pend[(c * BATCH + b) * D_K + tid];
        __syncthreads();

        // ---- y = A @ v_slice + S @ q_t^T ----
        float acc[4][2];
#pragma unroll
        for (int i = 0; i < 4; i++) { acc[i][0] = 0.f; acc[i][1] = 0.f; }

#pragma unroll 4
        for (int s = 0; s < CHUNK; s++) {
            float4 a4 = *(const float4*)&A_sh[s * 128 + t0];
            float2 v2 = *(const float2*)&v_sh[s * 16 + dd];
            acc[0][0] = fmaf(a4.x, v2.x, acc[0][0]); acc[0][1] = fmaf(a4.x, v2.y, acc[0][1]);
            acc[1][0] = fmaf(a4.y, v2.x, acc[1][0]); acc[1][1] = fmaf(a4.y, v2.y, acc[1][1]);
            acc[2][0] = fmaf(a4.z, v2.x, acc[2][0]); acc[2][1] = fmaf(a4.z, v2.y, acc[2][1]);
            acc[3][0] = fmaf(a4.w, v2.x, acc[3][0]); acc[3][1] = fmaf(a4.w, v2.y, acc[3][1]);
        }
#pragma unroll 4
        for (int n = 0; n < D_K; n++) {
            float s0 = S_sh[n * 17 + dd], s1 = S_sh[n * 17 + dd + 1];
#pragma unroll
            for (int i = 0; i < 4; i++) {
                float q = qt_sh[(t0 + i) * 65 + n];
                acc[i][0] = fmaf(q, s0, acc[i][0]);
                acc[i][1] = fmaf(q, s1, acc[i][1]);
            }
        }
#pragma unroll
        for (int i = 0; i < 4; i++) {
            size_t o = (size_t)((c * CHUNK + t0 + i) * BATCH + b) * D_V + d0 + dd;
            float2 ov; ov.x = acc[i][0]; ov.y = acc[i][1];
            *(float2*)&out[o] = ov;
        }

        // ---- state update: S = S * p_end + v^T @ kpe ----
        float sacc[4] = {0.f, 0.f, 0.f, 0.f};
#pragma unroll 4
        for (int t = 0; t < CHUNK; t++) {
            float vv = v_sh[t * 16 + du];
#pragma unroll
            for (int j = 0; j < 4; j++)
                sacc[j] = fmaf(vv, kpe_sh[t * 65 + n0s + j], sacc[j]);
        }
        float newS[4];
#pragma unroll
        for (int j = 0; j < 4; j++)
            newS[j] = S_sh[(n0s + j) * 17 + du] * pend_sh[n0s + j] + sacc[j];
        __syncthreads();   // all reads of old S done
#pragma unroll
        for (int j = 0; j < 4; j++)
            S_sh[(n0s + j) * 17 + du] = newS[j];
        __syncthreads();   // state visible; safe to overwrite staging buffers
    }
}

// ---------------- launch ----------------
extern "C" void kernel_launch(void* const* d_in, const int* in_sizes, int n_in,
                              void* d_out, int out_size) {
    const float* x  = (const float*)d_in[0];
    const float* Wv = (const float*)d_in[1];
    const float* bv = (const float*)d_in[2];
    const float* Wk = (const float*)d_in[3];
    const float* bk = (const float*)d_in[4];
    const float* Wq = (const float*)d_in[5];
    const float* bq = (const float*)d_in[6];
    const float* Wa = (const float*)d_in[7];
    const float* ba = (const float*)d_in[8];
    float* out = (float*)d_out;

    cudaFuncSetAttribute(prep_kernel, cudaFuncAttributeMaxDynamicSharedMemorySize, PREP_SMEM);
    cudaFuncSetAttribute(scan_kernel, cudaFuncAttributeMaxDynamicSharedMemorySize, SCAN_SMEM);

    pack_kernel<<<(NPROJ * IN_DIM + 255) / 256, 256>>>(Wv, bv, Wk, bk, Wq, bq, Wa, ba);
    gemm_kernel<<<dim3(NPROJ / 64, MROWS / 128), 256>>>(x);
    prep_kernel<<<dim3(BATCH, NC), 256, PREP_SMEM>>>();
    scan_kernel<<<dim3(D_V / 16, BATCH), 256, SCAN_SMEM>>>(out);
}

// round 3
// speedup vs baseline: 1.5660x; 1.5660x over previous
#include <cuda_runtime.h>
#include <math.h>

#define T_LEN   8192
#define BATCH   4
#define IN_DIM  512
#define D_V     512
#define D_K     64
#define CHUNK   128
#define NC      (T_LEN / CHUNK)          // 64
#define NPROJ   (D_V + 3 * D_K)          // 704
#define MROWS   (T_LEN * BATCH)          // 32768
#define EPS_F   1e-8f
#define SEG     (BATCH * D_K * D_V)      // 131072 state elements

// ---------------- static device scratch (no allocations allowed) ----------------
__device__ __align__(128) float g_W[NPROJ * IN_DIM];
__device__ __align__(128) float g_bias[NPROJ];
__device__ __align__(128) float g_proj[(size_t)MROWS * NPROJ];             // [t*B+b][704] : v|k|q|sig(a)
__device__ __align__(128) float g_A[(size_t)NC * BATCH * CHUNK * CHUNK];   // [c][b][t][s] masked
__device__ __align__(128) float g_qt[(size_t)NC * BATCH * CHUNK * D_K];    // q * p
__device__ __align__(128) float g_kpe[(size_t)NC * BATCH * CHUNK * D_K];   // (k/(p+eps)) * p_end
__device__ __align__(128) float g_pend[NC * BATCH * D_K];
__device__ __align__(128) float g_Wc[(size_t)NC * SEG];                    // per-chunk state writes [c][b][n][d]
__device__ __align__(128) float g_Sstart[(size_t)NC * SEG];                // state at chunk start [c][b][n][d]

// ---------------- kernel 0: pack weights/biases ----------------
__global__ void pack_kernel(const float* __restrict__ Wv, const float* __restrict__ bv,
                            const float* __restrict__ Wk, const float* __restrict__ bk,
                            const float* __restrict__ Wq, const float* __restrict__ bq,
                            const float* __restrict__ Wa, const float* __restrict__ ba) {
    int idx = blockIdx.x * 256 + threadIdx.x;
    if (idx < NPROJ * IN_DIM) {
        int o = idx / IN_DIM, i = idx - o * IN_DIM;
        float v;
        if (o < 512)       v = Wv[o * IN_DIM + i];
        else if (o < 576)  v = Wk[(o - 512) * IN_DIM + i];
        else if (o < 640)  v = Wq[(o - 576) * IN_DIM + i];
        else               v = Wa[(o - 640) * IN_DIM + i];
        g_W[idx] = v;
    }
    if (idx < NPROJ) {
        float v;
        if (idx < 512)      v = bv[idx];
        else if (idx < 576) v = bk[idx - 512];
        else if (idx < 640) v = bq[idx - 576];
        else                v = ba[idx - 640];
        g_bias[idx] = v;
    }
}

// ---------------- kernel 1: projection GEMM ----------------
__global__ void __launch_bounds__(256) gemm_kernel(const float* __restrict__ X) {
    __shared__ float As[16][132];   // [k][m]
    __shared__ float Bs[16][68];    // [k][n]

    int tid = threadIdx.x;
    int tx = tid & 15;
    int ty = tid >> 4;
    int m0 = blockIdx.y * 128;
    int n0 = blockIdx.x * 64;

    float acc[8][4];
#pragma unroll
    for (int i = 0; i < 8; i++)
#pragma unroll
        for (int j = 0; j < 4; j++) acc[i][j] = 0.f;

    for (int k0 = 0; k0 < IN_DIM; k0 += 16) {
#pragma unroll
        for (int j = 0; j < 2; j++) {
            int l  = tid + j * 256;
            int r  = l >> 2;
            int c4 = (l & 3) * 4;
            float4 v = *(const float4*)&X[(size_t)(m0 + r) * IN_DIM + k0 + c4];
            As[c4 + 0][r] = v.x; As[c4 + 1][r] = v.y;
            As[c4 + 2][r] = v.z; As[c4 + 3][r] = v.w;
        }
        {
            int r  = tid >> 2;
            int c4 = (tid & 3) * 4;
            float4 v = *(const float4*)&g_W[(size_t)(n0 + r) * IN_DIM + k0 + c4];
            Bs[c4 + 0][r] = v.x; Bs[c4 + 1][r] = v.y;
            Bs[c4 + 2][r] = v.z; Bs[c4 + 3][r] = v.w;
        }
        __syncthreads();
#pragma unroll
        for (int kk = 0; kk < 16; kk++) {
            float4 a0 = *(const float4*)&As[kk][ty * 8];
            float4 a1 = *(const float4*)&As[kk][ty * 8 + 4];
            float4 b0 = *(const float4*)&Bs[kk][tx * 4];
            float a[8] = {a0.x, a0.y, a0.z, a0.w, a1.x, a1.y, a1.z, a1.w};
            float bb[4] = {b0.x, b0.y, b0.z, b0.w};
#pragma unroll
            for (int i = 0; i < 8; i++)
#pragma unroll
                for (int j = 0; j < 4; j++)
                    acc[i][j] = fmaf(a[i], bb[j], acc[i][j]);
        }
        __syncthreads();
    }

    int colb = n0 + tx * 4;
    float b0 = g_bias[colb + 0], b1 = g_bias[colb + 1];
    float b2 = g_bias[colb + 2], b3 = g_bias[colb + 3];
    bool alpha_tile = (n0 >= 640);
#pragma unroll
    for (int i = 0; i < 8; i++) {
        int r = m0 + ty * 8 + i;
        float4 v;
        v.x = acc[i][0] + b0; v.y = acc[i][1] + b1;
        v.z = acc[i][2] + b2; v.w = acc[i][3] + b3;
        if (alpha_tile) {
            v.x = 1.f / (1.f + expf(-v.x));
            v.y = 1.f / (1.f + expf(-v.y));
            v.z = 1.f / (1.f + expf(-v.z));
            v.w = 1.f / (1.f + expf(-v.w));
        }
        *(float4*)&g_proj[(size_t)r * NPROJ + colb] = v;
    }
}

// ---------------- kernel 2: per-chunk prep (p, q_t, kpe, A[t][s]) ----------------
#define PREP_SMEM (3 * 128 * 65 * 4)
__global__ void __launch_bounds__(256) prep_kernel() {
    extern __shared__ float sm[];
    float* sp  = sm;                 // [128][65] cumulative decay p
    float* sqt = sm + 128 * 65;      // [128][65] q_t
    float* skt = sm + 2 * 128 * 65;  // [128][65] k_t (also alpha temp)

    int b = blockIdx.x, c = blockIdx.y;
    int tid = threadIdx.x;

#pragma unroll
    for (int j = 0; j < 8; j++) {
        int l  = tid + j * 256;
        int t  = l >> 4;
        int c4 = (l & 15) * 4;
        const float* rowp = g_proj + (size_t)((c * CHUNK + t) * BATCH + b) * NPROJ;
        float4 av = *(const float4*)&rowp[640 + c4];
        skt[t * 65 + c4 + 0] = av.x; skt[t * 65 + c4 + 1] = av.y;
        skt[t * 65 + c4 + 2] = av.z; skt[t * 65 + c4 + 3] = av.w;
    }
    __syncthreads();

    if (tid < D_K) {
        float p = 1.f;
        for (int t = 0; t < CHUNK; t++) {
            p *= fmaxf(skt[t * 65 + tid], EPS_F);
            sp[t * 65 + tid] = p;
        }
        g_pend[(c * BATCH + b) * D_K + tid] = p;
    }
    __syncthreads();

    float* gq = g_qt  + (size_t)(c * BATCH + b) * CHUNK * D_K;
    float* gk = g_kpe + (size_t)(c * BATCH + b) * CHUNK * D_K;
#pragma unroll
    for (int j = 0; j < 8; j++) {
        int l  = tid + j * 256;
        int t  = l >> 4;
        int c4 = (l & 15) * 4;
        const float* rowp = g_proj + (size_t)((c * CHUNK + t) * BATCH + b) * NPROJ;
        float4 qv = *(const float4*)&rowp[576 + c4];
        float4 kv = *(const float4*)&rowp[512 + c4];
        float p0 = sp[t * 65 + c4 + 0], p1 = sp[t * 65 + c4 + 1];
        float p2 = sp[t * 65 + c4 + 2], p3 = sp[t * 65 + c4 + 3];
        float pe0 = sp[127 * 65 + c4 + 0], pe1 = sp[127 * 65 + c4 + 1];
        float pe2 = sp[127 * 65 + c4 + 2], pe3 = sp[127 * 65 + c4 + 3];
        float q0 = qv.x * p0, q1 = qv.y * p1, q2 = qv.z * p2, q3 = qv.w * p3;
        float k0 = kv.x / (p0 + EPS_F), k1 = kv.y / (p1 + EPS_F);
        float k2 = kv.z / (p2 + EPS_F), k3 = kv.w / (p3 + EPS_F);
        sqt[t * 65 + c4 + 0] = q0; sqt[t * 65 + c4 + 1] = q1;
        sqt[t * 65 + c4 + 2] = q2; sqt[t * 65 + c4 + 3] = q3;
        skt[t * 65 + c4 + 0] = k0; skt[t * 65 + c4 + 1] = k1;
        skt[t * 65 + c4 + 2] = k2; skt[t * 65 + c4 + 3] = k3;
        float4 oq; oq.x = q0; oq.y = q1; oq.z = q2; oq.w = q3;
        *(float4*)&gq[t * 64 + c4] = oq;
        float4 ok; ok.x = k0 * pe0; ok.y = k1 * pe1; ok.z = k2 * pe2; ok.w = k3 * pe3;
        *(float4*)&gk[t * 64 + c4] = ok;
    }
    __syncthreads();

    // A[t][s] = sum_n q_t[t][n] * k_t[s][n], masked t>=s, natural layout
    int sxl = tid & 15;
    int t0  = (tid >> 4) * 8;
    float acc[8][8];
#pragma unroll
    for (int i = 0; i < 8; i++)
#pragma unroll
        for (int j = 0; j < 8; j++) acc[i][j] = 0.f;

    for (int n = 0; n < D_K; n++) {
        float qv[8], kv[8];
#pragma unroll
        for (int i = 0; i < 8; i++) qv[i] = sqt[(t0 + i) * 65 + n];
#pragma unroll
        for (int j = 0; j < 8; j++) kv[j] = skt[(sxl + 16 * j) * 65 + n];
#pragma unroll
        for (int i = 0; i < 8; i++)
#pragma unroll
            for (int j = 0; j < 8; j++)
                acc[i][j] = fmaf(qv[i], kv[j], acc[i][j]);
    }
    float* Ab = g_A + (size_t)(c * BATCH + b) * CHUNK * CHUNK;
#pragma unroll
    for (int i = 0; i < 8; i++) {
        int t = t0 + i;
#pragma unroll
        for (int j = 0; j < 8; j++) {
            int s = sxl + 16 * j;
            Ab[t * CHUNK + s] = (t >= s) ? acc[i][j] : 0.f;
        }
    }
}

// ---------------- kernel 3: per-chunk state contributions W_c = v^T @ kpe ----------
// out: g_Wc[c][b][n][d], block computes [64 n][128 d] for one (c,b,dtile)
__global__ void __launch_bounds__(256) contrib_kernel() {
    __shared__ float v_s[32][128];
    __shared__ float k_s[32][64];
    int d0 = blockIdx.x * 128, c = blockIdx.y, b = blockIdx.z;
    int tid = threadIdx.x;
    int tx = tid & 31;           // d group (4 each)
    int ty = tid >> 5;           // n group (8 each)

    float acc[8][4];
#pragma unroll
    for (int i = 0; i < 8; i++)
#pragma unroll
        for (int j = 0; j < 4; j++) acc[i][j] = 0.f;

    const float* kbase = g_kpe + (size_t)(c * BATCH + b) * CHUNK * D_K;

    for (int t0 = 0; t0 < CHUNK; t0 += 32) {
#pragma unroll
        for (int j = 0; j < 4; j++) {
            int l  = tid + j * 256;
            int tt = l >> 5;
            int c4 = (l & 31) * 4;
            float4 v = *(const float4*)&g_proj[(size_t)((c * CHUNK + t0 + tt) * BATCH + b) * NPROJ + d0 + c4];
            *(float4*)&v_s[tt][c4] = v;
        }
#pragma unroll
        for (int j = 0; j < 2; j++) {
            int l  = tid + j * 256;
            int tt = l >> 4;
            int c4 = (l & 15) * 4;
            float4 v = *(const float4*)&kbase[(t0 + tt) * D_K + c4];
            *(float4*)&k_s[tt][c4] = v;
        }
        __syncthreads();
#pragma unroll
        for (int t = 0; t < 32; t++) {
            float4 vv = *(const float4*)&v_s[t][tx * 4];
            float4 k0v = *(const float4*)&k_s[t][ty * 8];
            float4 k1v = *(const float4*)&k_s[t][ty * 8 + 4];
            float kn[8] = {k0v.x, k0v.y, k0v.z, k0v.w, k1v.x, k1v.y, k1v.z, k1v.w};
#pragma unroll
            for (int i = 0; i < 8; i++) {
                acc[i][0] = fmaf(kn[i], vv.x, acc[i][0]);
                acc[i][1] = fmaf(kn[i], vv.y, acc[i][1]);
                acc[i][2] = fmaf(kn[i], vv.z, acc[i][2]);
                acc[i][3] = fmaf(kn[i], vv.w, acc[i][3]);
            }
        }
        __syncthreads();
    }
#pragma unroll
    for (int i = 0; i < 8; i++) {
        float4 o; o.x = acc[i][0]; o.y = acc[i][1]; o.z = acc[i][2]; o.w = acc[i][3];
        *(float4*)&g_Wc[(size_t)((c * BATCH + b) * D_K + ty * 8 + i) * D_V + d0 + tx * 4] = o;
    }
}

// ---------------- kernel 4: elementwise state scan over chunks --------------------
// 131072 independent recurrences s_{c+1} = s_c * pend[c] + W_c ; emit S_start[c]
__global__ void __launch_bounds__(256) state_scan_kernel() {
    int g = blockIdx.x * 256 + threadIdx.x;  // g = (b*64+n)*512 + d
    int bn = g >> 9;
    float s = 0.f;
    for (int c = 0; c < NC; c++) {
        size_t idx = (size_t)c * SEG + g;
        g_Sstart[idx] = s;
        s = fmaf(s, g_pend[c * (BATCH * D_K) + bn], g_Wc[idx]);
    }
}

// ---------------- kernel 5: y = [A | q_t] @ [v ; S_start] ------------------------
__global__ void __launch_bounds__(256) ygemm_kernel(float* __restrict__ out) {
    __shared__ float As[16][132];   // [k][t]
    __shared__ float Bs[16][68];    // [k][d]

    int n0 = blockIdx.x * 64;       // d offset
    int c = blockIdx.y, b = blockIdx.z;
    int tid = threadIdx.x;
    int tx = tid & 15;
    int ty = tid >> 4;

    float acc[8][4];
#pragma unroll
    for (int i = 0; i < 8; i++)
#pragma unroll
        for (int j = 0; j < 4; j++) acc[i][j] = 0.f;

    const float* Abase = g_A  + (size_t)(c * BATCH + b) * CHUNK * CHUNK;
    const float* Qbase = g_qt + (size_t)(c * BATCH + b) * CHUNK * D_K;
    const float* Sbase = g_Sstart + (size_t)(c * BATCH + b) * D_K * D_V;

    for (int k0 = 0; k0 < CHUNK + D_K; k0 += 16) {
        // L tile: 128 t x 16 k
#pragma unroll
        for (int j = 0; j < 2; j++) {
            int l  = tid + j * 256;
            int t  = l >> 2;
            int c4 = (l & 3) * 4;
            float4 v;
            if (k0 < CHUNK) v = *(const float4*)&Abase[t * CHUNK + k0 + c4];
            else            v = *(const float4*)&Qbase[t * D_K + (k0 - CHUNK) + c4];
            As[c4 + 0][t] = v.x; As[c4 + 1][t] = v.y;
            As[c4 + 2][t] = v.z; As[c4 + 3][t] = v.w;
        }
        // R tile: 16 k x 64 d
        {
            int k  = tid >> 4;
            int c4 = (tid & 15) * 4;
            float4 v;
            if (k0 < CHUNK)
                v = *(const float4*)&g_proj[(size_t)((c * CHUNK + k0 + k) * BATCH + b) * NPROJ + n0 + c4];
            else
                v = *(const float4*)&Sbase[(size_t)(k0 + k - CHUNK) * D_V + n0 + c4];
            *(float4*)&Bs[k][c4] = v;
        }
        __syncthreads();
#pragma unroll
        for (int kk = 0; kk < 16; kk++) {
            float4 a0 = *(const float4*)&As[kk][ty * 8];
            float4 a1 = *(const float4*)&As[kk][ty * 8 + 4];
            float4 b0 = *(const float4*)&Bs[kk][tx * 4];
            float a[8] = {a0.x, a0.y, a0.z, a0.w, a1.x, a1.y, a1.z, a1.w};
            float bb[4] = {b0.x, b0.y, b0.z, b0.w};
#pragma unroll
            for (int i = 0; i < 8; i++)
#pragma unroll
                for (int j = 0; j < 4; j++)
                    acc[i][j] = fmaf(a[i], bb[j], acc[i][j]);
        }
        __syncthreads();
    }

#pragma unroll
    for (int i = 0; i < 8; i++) {
        int t = ty * 8 + i;
        float4 o; o.x = acc[i][0]; o.y = acc[i][1]; o.z = acc[i][2]; o.w = acc[i][3];
        *(float4*)&out[(size_t)((c * CHUNK + t) * BATCH + b) * D_V + n0 + tx * 4] = o;
    }
}

// ---------------- launch ----------------
extern "C" void kernel_launch(void* const* d_in, const int* in_sizes, int n_in,
                              void* d_out, int out_size) {
    const float* x  = (const float*)d_in[0];
    const float* Wv = (const float*)d_in[1];
    const float* bv = (const float*)d_in[2];
    const float* Wk = (const float*)d_in[3];
    const float* bk = (const float*)d_in[4];
    const float* Wq = (const float*)d_in[5];
    const float* bq = (const float*)d_in[6];
    const float* Wa = (const float*)d_in[7];
    const float* ba = (const float*)d_in[8];
    float* out = (float*)d_out;

    cudaFuncSetAttribute(prep_kernel, cudaFuncAttributeMaxDynamicSharedMemorySize, PREP_SMEM);

    pack_kernel<<<(NPROJ * IN_DIM + 255) / 256, 256>>>(Wv, bv, Wk, bk, Wq, bq, Wa, ba);
    gemm_kernel<<<dim3(NPROJ / 64, MROWS / 128), 256>>>(x);
    prep_kernel<<<dim3(BATCH, NC), 256, PREP_SMEM>>>();
    contrib_kernel<<<dim3(D_V / 128, NC, BATCH), 256>>>();
    state_scan_kernel<<<SEG / 256, 256>>>();
    ygemm_kernel<<<dim3(D_V / 64, NC, BATCH), 256>>>(out);
}

// round 5
// speedup vs baseline: 2.3761x; 1.5173x over previous
#include <cuda_runtime.h>
#include <cuda_bf16.h>
#include <math.h>
#include <stdint.h>

#define T_LEN   8192
#define BATCH   4
#define IN_DIM  512
#define D_V     512
#define D_K     64
#define CHUNK   128
#define NC      (T_LEN / CHUNK)          // 64
#define NPROJ   (D_V + 3 * D_K)          // 704
#define NPROJ_P 768                      // padded to 6*128
#define MROWS   (T_LEN * BATCH)          // 32768
#define EPS_F   1e-8f
#define SEG     (BATCH * D_K * D_V)      // 131072 state elements

// ---------------- static device scratch ----------------
__device__ __align__(128) float g_bias[NPROJ];
__device__ __align__(128) __nv_bfloat16 g_Wh[NPROJ_P * IN_DIM];
__device__ __align__(128) __nv_bfloat16 g_Wl[NPROJ_P * IN_DIM];
__device__ __align__(128) __nv_bfloat16 g_Xh[(size_t)MROWS * IN_DIM];
__device__ __align__(128) __nv_bfloat16 g_Xl[(size_t)MROWS * IN_DIM];
__device__ __align__(128) float g_proj[(size_t)MROWS * NPROJ];             // [t*B+b][704] : v|k|q|sig(a)
__device__ __align__(128) float g_A[(size_t)NC * BATCH * CHUNK * CHUNK];   // [c][b][t][s] masked
__device__ __align__(128) float g_qt[(size_t)NC * BATCH * CHUNK * D_K];
__device__ __align__(128) float g_kpe[(size_t)NC * BATCH * CHUNK * D_K];
__device__ __align__(128) float g_pend[NC * BATCH * D_K];
__device__ __align__(128) float g_Wc[(size_t)NC * SEG];
__device__ __align__(128) float g_Sstart[(size_t)NC * SEG];

// ---------------- warp-level bf16 MMA (sm_80+, no 'a' feature needed) ----------------
__device__ __forceinline__ void mma_bf16(float* c, const uint32_t* a, const uint32_t* b) {
    asm volatile(
        "mma.sync.aligned.m16n8k16.row.col.f32.bf16.bf16.f32 "
        "{%0,%1,%2,%3}, {%4,%5,%6,%7}, {%8,%9}, {%0,%1,%2,%3};"
        : "+f"(c[0]), "+f"(c[1]), "+f"(c[2]), "+f"(c[3])
        : "r"(a[0]), "r"(a[1]), "r"(a[2]), "r"(a[3]), "r"(b[0]), "r"(b[1]));
}

// ---------------- kernel 0: pack weights (bf16 hi/lo) + bias ----------------
__global__ void pack_kernel(const float* __restrict__ Wv, const float* __restrict__ bv,
                            const float* __restrict__ Wk, const float* __restrict__ bk,
                            const float* __restrict__ Wq, const float* __restrict__ bq,
                            const float* __restrict__ Wa, const float* __restrict__ ba) {
    int idx = blockIdx.x * 256 + threadIdx.x;
    if (idx < NPROJ_P * IN_DIM) {
        int o = idx >> 9, i = idx & 511;
        float v = 0.f;
        if (o < 512)       v = Wv[o * IN_DIM + i];
        else if (o < 576)  v = Wk[(o - 512) * IN_DIM + i];
        else if (o < 640)  v = Wq[(o - 576) * IN_DIM + i];
        else if (o < 704)  v = Wa[(o - 640) * IN_DIM + i];
        __nv_bfloat16 h = __float2bfloat16(v);
        __nv_bfloat16 l = __float2bfloat16(v - __bfloat162float(h));
        g_Wh[idx] = h;
        g_Wl[idx] = l;
    }
    if (idx < NPROJ) {
        float v;
        if (idx < 512)      v = bv[idx];
        else if (idx < 576) v = bk[idx - 512];
        else if (idx < 640) v = bq[idx - 576];
        else                v = ba[idx - 640];
        g_bias[idx] = v;
    }
}

// ---------------- kernel 1: X -> bf16 hi/lo ----------------
__global__ void __launch_bounds__(256) convx_kernel(const float* __restrict__ X) {
    size_t e0 = ((size_t)blockIdx.x * 256 + threadIdx.x) * 8;
    float4 v0 = *(const float4*)&X[e0];
    float4 v1 = *(const float4*)&X[e0 + 4];
    float f[8] = {v0.x, v0.y, v0.z, v0.w, v1.x, v1.y, v1.z, v1.w};
    __align__(16) __nv_bfloat16 hh[8], ll[8];
#pragma unroll
    for (int i = 0; i < 8; i++) {
        hh[i] = __float2bfloat16(f[i]);
        ll[i] = __float2bfloat16(f[i] - __bfloat162float(hh[i]));
    }
    *(uint4*)&g_Xh[e0] = *(uint4*)hh;
    *(uint4*)&g_Xl[e0] = *(uint4*)ll;
}

// ---------------- kernel 2: projection GEMM via HMMA bf16 (3-term) ----------------
// CTA tile M=128, N=128; 8 warps as 2(m) x 4(n), each warp 64x32.
// K=512 in 8 chunks of 64. Smem pitch 72 bf16 (144B): uint4-aligned, conflict-free frags.
#define GP 72
#define GM_SMEM (4 * 128 * GP * 2)     // Xh, Xl, Wh, Wl tiles (bf16)

__global__ void __launch_bounds__(256, 2) gemm_mma_kernel() {
    extern __shared__ __nv_bfloat16 sm_b[];
    __nv_bfloat16* sXh = sm_b;
    __nv_bfloat16* sXl = sXh + 128 * GP;
    __nv_bfloat16* sWh = sXl + 128 * GP;
    __nv_bfloat16* sWl = sWh + 128 * GP;

    int tid = threadIdx.x, wid = tid >> 5, lane = tid & 31;
    int g = lane >> 2, tig = lane & 3;
    int wm = wid >> 2;               // 0..1 -> 64 rows each
    int wn = wid & 3;                // 0..3 -> 32 cols each
    int bx = blockIdx.x;             // n tile 0..5
    int m0 = blockIdx.y * 128;
    int n0 = bx * 128;

    float acc[4][4][4];              // [mi][nj][c0..c3]
#pragma unroll
    for (int i = 0; i < 4; i++)
#pragma unroll
        for (int j = 0; j < 4; j++)
#pragma unroll
            for (int k = 0; k < 4; k++) acc[i][j][k] = 0.f;

    for (int ch = 0; ch < 8; ch++) {
        __syncthreads();
        // stage 4 tiles: 128 rows x 64 bf16 each (8 uint4 per row)
#pragma unroll
        for (int u = 0; u < 4; u++) {
            int l = tid + u * 256;           // 0..1023
            int r = l >> 3, q = l & 7;
            size_t gx = (size_t)(m0 + r) * IN_DIM + ch * 64 + q * 8;
            size_t gw = (size_t)(n0 + r) * IN_DIM + ch * 64 + q * 8;
            int so = r * GP + q * 8;
            *(uint4*)&sXh[so] = *(const uint4*)&g_Xh[gx];
            *(uint4*)&sXl[so] = *(const uint4*)&g_Xl[gx];
            *(uint4*)&sWh[so] = *(const uint4*)&g_Wh[gw];
            *(uint4*)&sWl[so] = *(const uint4*)&g_Wl[gw];
        }
        __syncthreads();

#pragma unroll
        for (int ks = 0; ks < 64; ks += 16) {
            int kc = ks + tig * 2;
            uint32_t Ah[4][4], Al[4][4], Bh[4][2], Bl[4][2];
#pragma unroll
            for (int mi = 0; mi < 4; mi++) {
                int mb = wm * 64 + mi * 16 + g;
                const __nv_bfloat16* p = &sXh[mb * GP + kc];
                const __nv_bfloat16* q = &sXl[mb * GP + kc];
                Ah[mi][0] = *(const uint32_t*)p;
                Ah[mi][1] = *(const uint32_t*)(p + 8 * GP);
                Ah[mi][2] = *(const uint32_t*)(p + 8);
                Ah[mi][3] = *(const uint32_t*)(p + 8 * GP + 8);
                Al[mi][0] = *(const uint32_t*)q;
                Al[mi][1] = *(const uint32_t*)(q + 8 * GP);
                Al[mi][2] = *(const uint32_t*)(q + 8);
                Al[mi][3] = *(const uint32_t*)(q + 8 * GP + 8);
            }
#pragma unroll
            for (int nj = 0; nj < 4; nj++) {
                int nb = wn * 32 + nj * 8 + g;
                const __nv_bfloat16* p = &sWh[nb * GP + kc];
                const __nv_bfloat16* q = &sWl[nb * GP + kc];
                Bh[nj][0] = *(const uint32_t*)p;
                Bh[nj][1] = *(const uint32_t*)(p + 8);
                Bl[nj][0] = *(const uint32_t*)q;
                Bl[nj][1] = *(const uint32_t*)(q + 8);
            }
#pragma unroll
            for (int mi = 0; mi < 4; mi++)
#pragma unroll
                for (int nj = 0; nj < 4; nj++) {
                    mma_bf16(acc[mi][nj], Ah[mi], Bh[nj]);
                    mma_bf16(acc[mi][nj], Ah[mi], Bl[nj]);
                    mma_bf16(acc[mi][nj], Al[mi], Bh[nj]);
                }
        }
    }

    // epilogue: bias (+ sigmoid for cols >= 640), store
#pragma unroll
    for (int mi = 0; mi < 4; mi++) {
        int r0 = m0 + wm * 64 + mi * 16 + g;
#pragma unroll
        for (int nj = 0; nj < 4; nj++) {
            int col = n0 + wn * 32 + nj * 8 + tig * 2;
            if (col >= NPROJ) continue;
            float b0 = g_bias[col], b1 = g_bias[col + 1];
            float v0 = acc[mi][nj][0] + b0, v1 = acc[mi][nj][1] + b1;
            float v2 = acc[mi][nj][2] + b0, v3 = acc[mi][nj][3] + b1;
            if (col >= 640) {
                v0 = 1.f / (1.f + expf(-v0));
                v1 = 1.f / (1.f + expf(-v1));
                v2 = 1.f / (1.f + expf(-v2));
                v3 = 1.f / (1.f + expf(-v3));
            }
            float2 lo; lo.x = v0; lo.y = v1;
            float2 hi; hi.x = v2; hi.y = v3;
            *(float2*)&g_proj[(size_t)r0 * NPROJ + col] = lo;
            *(float2*)&g_proj[(size_t)(r0 + 8) * NPROJ + col] = hi;
        }
    }
}

// ---------------- kernel 3: per-chunk prep (p, q_t, kpe, A[t][s]) ----------------
#define PREP_SMEM (3 * 128 * 65 * 4)
__global__ void __launch_bounds__(256) prep_kernel() {
    extern __shared__ float sm[];
    float* sp  = sm;                 // [128][65] cumulative decay p
    float* sqt = sm + 128 * 65;      // [128][65] q_t
    float* skt = sm + 2 * 128 * 65;  // [128][65] k_t (also alpha temp)

    int b = blockIdx.x, c = blockIdx.y;
    int tid = threadIdx.x;

#pragma unroll
    for (int j = 0; j < 8; j++) {
        int l  = tid + j * 256;
        int t  = l >> 4;
        int c4 = (l & 15) * 4;
        const float* rowp = g_proj + (size_t)((c * CHUNK + t) * BATCH + b) * NPROJ;
        float4 av = *(const float4*)&rowp[640 + c4];
        skt[t * 65 + c4 + 0] = av.x; skt[t * 65 + c4 + 1] = av.y;
        skt[t * 65 + c4 + 2] = av.z; skt[t * 65 + c4 + 3] = av.w;
    }
    __syncthreads();

    if (tid < D_K) {
        float p = 1.f;
        for (int t = 0; t < CHUNK; t++) {
            p *= fmaxf(skt[t * 65 + tid], EPS_F);
            sp[t * 65 + tid] = p;
        }
        g_pend[(c * BATCH + b) * D_K + tid] = p;
    }
    __syncthreads();

    float* gq = g_qt  + (size_t)(c * BATCH + b) * CHUNK * D_K;
    float* gk = g_kpe + (size_t)(c * BATCH + b) * CHUNK * D_K;
#pragma unroll
    for (int j = 0; j < 8; j++) {
        int l  = tid + j * 256;
        int t  = l >> 4;
        int c4 = (l & 15) * 4;
        const float* rowp = g_proj + (size_t)((c * CHUNK + t) * BATCH + b) * NPROJ;
        float4 qv = *(const float4*)&rowp[576 + c4];
        float4 kv = *(const float4*)&rowp[512 + c4];
        float p0 = sp[t * 65 + c4 + 0], p1 = sp[t * 65 + c4 + 1];
        float p2 = sp[t * 65 + c4 + 2], p3 = sp[t * 65 + c4 + 3];
        float pe0 = sp[127 * 65 + c4 + 0], pe1 = sp[127 * 65 + c4 + 1];
        float pe2 = sp[127 * 65 + c4 + 2], pe3 = sp[127 * 65 + c4 + 3];
        float q0 = qv.x * p0, q1 = qv.y * p1, q2 = qv.z * p2, q3 = qv.w * p3;
        float k0 = kv.x / (p0 + EPS_F), k1 = kv.y / (p1 + EPS_F);
        float k2 = kv.z / (p2 + EPS_F), k3 = kv.w / (p3 + EPS_F);
        sqt[t * 65 + c4 + 0] = q0; sqt[t * 65 + c4 + 1] = q1;
        sqt[t * 65 + c4 + 2] = q2; sqt[t * 65 + c4 + 3] = q3;
        skt[t * 65 + c4 + 0] = k0; skt[t * 65 + c4 + 1] = k1;
        skt[t * 65 + c4 + 2] = k2; skt[t * 65 + c4 + 3] = k3;
        float4 oq; oq.x = q0; oq.y = q1; oq.z = q2; oq.w = q3;
        *(float4*)&gq[t * 64 + c4] = oq;
        float4 ok; ok.x = k0 * pe0; ok.y = k1 * pe1; ok.z = k2 * pe2; ok.w = k3 * pe3;
        *(float4*)&gk[t * 64 + c4] = ok;
    }
    __syncthreads();

    // A[t][s] = sum_n q_t[t][n] * k_t[s][n], masked t>=s, natural layout
    int sxl = tid & 15;
    int t0  = (tid >> 4) * 8;
    float acc[8][8];
#pragma unroll
    for (int i = 0; i < 8; i++)
#pragma unroll
        for (int j = 0; j < 8; j++) acc[i][j] = 0.f;

    for (int n = 0; n < D_K; n++) {
        float qv[8], kv[8];
#pragma unroll
        for (int i = 0; i < 8; i++) qv[i] = sqt[(t0 + i) * 65 + n];
#pragma unroll
        for (int j = 0; j < 8; j++) kv[j] = skt[(sxl + 16 * j) * 65 + n];
#pragma unroll
        for (int i = 0; i < 8; i++)
#pragma unroll
            for (int j = 0; j < 8; j++)
                acc[i][j] = fmaf(qv[i], kv[j], acc[i][j]);
    }
    float* Ab = g_A + (size_t)(c * BATCH + b) * CHUNK * CHUNK;
#pragma unroll
    for (int i = 0; i < 8; i++) {
        int t = t0 + i;
#pragma unroll
        for (int j = 0; j < 8; j++) {
            int s = sxl + 16 * j;
            Ab[t * CHUNK + s] = (t >= s) ? acc[i][j] : 0.f;
        }
    }
}

// ---------------- kernel 4: per-chunk state contributions W_c = v^T @ kpe ----------
__global__ void __launch_bounds__(256) contrib_kernel() {
    __shared__ float v_s[32][128];
    __shared__ float k_s[32][64];
    int d0 = blockIdx.x * 128, c = blockIdx.y, b = blockIdx.z;
    int tid = threadIdx.x;
    int tx = tid & 31;           // d group (4 each)
    int ty = tid >> 5;           // n group (8 each)

    float acc[8][4];
#pragma unroll
    for (int i = 0; i < 8; i++)
#pragma unroll
        for (int j = 0; j < 4; j++) acc[i][j] = 0.f;

    const float* kbase = g_kpe + (size_t)(c * BATCH + b) * CHUNK * D_K;

    for (int t0 = 0; t0 < CHUNK; t0 += 32) {
#pragma unroll
        for (int j = 0; j < 4; j++) {
            int l  = tid + j * 256;
            int tt = l >> 5;
            int c4 = (l & 31) * 4;
            float4 v = *(const float4*)&g_proj[(size_t)((c * CHUNK + t0 + tt) * BATCH + b) * NPROJ + d0 + c4];
            *(float4*)&v_s[tt][c4] = v;
        }
#pragma unroll
        for (int j = 0; j < 2; j++) {
            int l  = tid + j * 256;
            int tt = l >> 4;
            int c4 = (l & 15) * 4;
            float4 v = *(const float4*)&kbase[(t0 + tt) * D_K + c4];
            *(float4*)&k_s[tt][c4] = v;
        }
        __syncthreads();
#pragma unroll
        for (int t = 0; t < 32; t++) {
            float4 vv = *(const float4*)&v_s[t][tx * 4];
            float4 k0v = *(const float4*)&k_s[t][ty * 8];
            float4 k1v = *(const float4*)&k_s[t][ty * 8 + 4];
            float kn[8] = {k0v.x, k0v.y, k0v.z, k0v.w, k1v.x, k1v.y, k1v.z, k1v.w};
#pragma unroll
            for (int i = 0; i < 8; i++) {
                acc[i][0] = fmaf(kn[i], vv.x, acc[i][0]);
                acc[i][1] = fmaf(kn[i], vv.y, acc[i][1]);
                acc[i][2] = fmaf(kn[i], vv.z, acc[i][2]);
                acc[i][3] = fmaf(kn[i], vv.w, acc[i][3]);
            }
        }
        __syncthreads();
    }
#pragma unroll
    for (int i = 0; i < 8; i++) {
        float4 o; o.x = acc[i][0]; o.y = acc[i][1]; o.z = acc[i][2]; o.w = acc[i][3];
        *(float4*)&g_Wc[(size_t)((c * BATCH + b) * D_K + ty * 8 + i) * D_V + d0 + tx * 4] = o;
    }
}

// ---------------- kernel 5: elementwise state scan over chunks --------------------
__global__ void __launch_bounds__(256) state_scan_kernel() {
    int g = blockIdx.x * 256 + threadIdx.x;  // g = (b*64+n)*512 + d
    int bn = g >> 9;
    float s = 0.f;
    for (int c = 0; c < NC; c++) {
        size_t idx = (size_t)c * SEG + g;
        g_Sstart[idx] = s;
        s = fmaf(s, g_pend[c * (BATCH * D_K) + bn], g_Wc[idx]);
    }
}

// ---------------- kernel 6: y = [A | q_t] @ [v ; S_start] ------------------------
__global__ void __launch_bounds__(256) ygemm_kernel(float* __restrict__ out) {
    __shared__ float As[16][132];   // [k][t]
    __shared__ float Bs[16][68];    // [k][d]

    int n0 = blockIdx.x * 64;       // d offset
    int c = blockIdx.y, b = blockIdx.z;
    int tid = threadIdx.x;
    int tx = tid & 15;
    int ty = tid >> 4;

    float acc[8][4];
#pragma unroll
    for (int i = 0; i < 8; i++)
#pragma unroll
        for (int j = 0; j < 4; j++) acc[i][j] = 0.f;

    const float* Abase = g_A  + (size_t)(c * BATCH + b) * CHUNK * CHUNK;
    const float* Qbase = g_qt + (size_t)(c * BATCH + b) * CHUNK * D_K;
    const float* Sbase = g_Sstart + (size_t)(c * BATCH + b) * D_K * D_V;

    for (int k0 = 0; k0 < CHUNK + D_K; k0 += 16) {
#pragma unroll
        for (int j = 0; j < 2; j++) {
            int l  = tid + j * 256;
            int t  = l >> 2;
            int c4 = (l & 3) * 4;
            float4 v;
            if (k0 < CHUNK) v = *(const float4*)&Abase[t * CHUNK + k0 + c4];
            else            v = *(const float4*)&Qbase[t * D_K + (k0 - CHUNK) + c4];
            As[c4 + 0][t] = v.x; As[c4 + 1][t] = v.y;
            As[c4 + 2][t] = v.z; As[c4 + 3][t] = v.w;
        }
        {
            int k  = tid >> 4;
            int c4 = (tid & 15) * 4;
            float4 v;
            if (k0 < CHUNK)
                v = *(const float4*)&g_proj[(size_t)((c * CHUNK + k0 + k) * BATCH + b) * NPROJ + n0 + c4];
            else
                v = *(const float4*)&Sbase[(size_t)(k0 + k - CHUNK) * D_V + n0 + c4];
            *(float4*)&Bs[k][c4] = v;
        }
        __syncthreads();
#pragma unroll
        for (int kk = 0; kk < 16; kk++) {
            float4 a0 = *(const float4*)&As[kk][ty * 8];
            float4 a1 = *(const float4*)&As[kk][ty * 8 + 4];
            float4 b0 = *(const float4*)&Bs[kk][tx * 4];
            float a[8] = {a0.x, a0.y, a0.z, a0.w, a1.x, a1.y, a1.z, a1.w};
            float bb[4] = {b0.x, b0.y, b0.z, b0.w};
#pragma unroll
            for (int i = 0; i < 8; i++)
#pragma unroll
                for (int j = 0; j < 4; j++)
                    acc[i][j] = fmaf(a[i], bb[j], acc[i][j]);
        }
        __syncthreads();
    }

#pragma unroll
    for (int i = 0; i < 8; i++) {
        int t = ty * 8 + i;
        float4 o; o.x = acc[i][0]; o.y = acc[i][1]; o.z = acc[i][2]; o.w = acc[i][3];
        *(float4*)&out[(size_t)((c * CHUNK + t) * BATCH + b) * D_V + n0 + tx * 4] = o;
    }
}

// ---------------- launch ----------------
extern "C" void kernel_launch(void* const* d_in, const int* in_sizes, int n_in,
                              void* d_out, int out_size) {
    const float* x  = (const float*)d_in[0];
    const float* Wv = (const float*)d_in[1];
    const float* bv = (const float*)d_in[2];
    const float* Wk = (const float*)d_in[3];
    const float* bk = (const float*)d_in[4];
    const float* Wq = (const float*)d_in[5];
    const float* bq = (const float*)d_in[6];
    const float* Wa = (const float*)d_in[7];
    const float* ba = (const float*)d_in[8];
    float* out = (float*)d_out;

    cudaFuncSetAttribute(prep_kernel, cudaFuncAttributeMaxDynamicSharedMemorySize, PREP_SMEM);
    cudaFuncSetAttribute(gemm_mma_kernel, cudaFuncAttributeMaxDynamicSharedMemorySize, GM_SMEM);

    pack_kernel<<<(NPROJ_P * IN_DIM + 255) / 256, 256>>>(Wv, bv, Wk, bk, Wq, bq, Wa, ba);
    convx_kernel<<<(int)(((size_t)MROWS * IN_DIM / 8) / 256), 256>>>(x);
    gemm_mma_kernel<<<dim3(NPROJ_P / 128, MROWS / 128), 256, GM_SMEM>>>();
    prep_kernel<<<dim3(BATCH, NC), 256, PREP_SMEM>>>();
    contrib_kernel<<<dim3(D_V / 128, NC, BATCH), 256>>>();
    state_scan_kernel<<<SEG / 256, 256>>>();
    ygemm_kernel<<<dim3(D_V / 64, NC, BATCH), 256>>>(out);
}

// round 6
// speedup vs baseline: 2.5013x; 1.0527x over previous
#include <cuda_runtime.h>
#include <cuda_bf16.h>
#include <math.h>
#include <stdint.h>

#define T_LEN   8192
#define BATCH   4
#define IN_DIM  512
#define D_V     512
#define D_K     64
#define CHUNK   128
#define NC      (T_LEN / CHUNK)          // 64
#define NPROJ   (D_V + 3 * D_K)          // 704
#define NPROJ_P 768                      // padded to 6*128
#define MROWS   (T_LEN * BATCH)          // 32768
#define EPS_F   1e-8f
#define SEG     (BATCH * D_K * D_V)      // 131072 state elements

// ---------------- static device scratch ----------------
__device__ __align__(128) float g_bias[NPROJ];
__device__ __align__(128) __nv_bfloat16 g_Wh[NPROJ_P * IN_DIM];
__device__ __align__(128) __nv_bfloat16 g_Wl[NPROJ_P * IN_DIM];
__device__ __align__(128) __nv_bfloat16 g_Xh[(size_t)MROWS * IN_DIM];
__device__ __align__(128) __nv_bfloat16 g_Xl[(size_t)MROWS * IN_DIM];
__device__ __align__(128) float g_proj[(size_t)MROWS * NPROJ];             // [t*B+b][704] : v|k|q|sig(a)
__device__ __align__(128) float g_A[(size_t)NC * BATCH * CHUNK * CHUNK];   // [c][b][t][s] masked
__device__ __align__(128) float g_qt[(size_t)NC * BATCH * CHUNK * D_K];
__device__ __align__(128) float g_kpe[(size_t)NC * BATCH * CHUNK * D_K];
__device__ __align__(128) float g_pend[NC * BATCH * D_K];
__device__ __align__(128) float g_Wc[(size_t)NC * SEG];
__device__ __align__(128) float g_Sstart[(size_t)NC * SEG];

// ---------------- helpers ----------------
__device__ __forceinline__ uint32_t smem_u32(const void* p) {
    uint32_t a;
    asm("{ .reg .u64 t; cvta.to.shared.u64 t, %1; cvt.u32.u64 %0, t; }" : "=r"(a) : "l"(p));
    return a;
}
__device__ __forceinline__ void cp16(uint32_t dst, const void* src) {
    asm volatile("cp.async.cg.shared.global [%0], [%1], 16;" :: "r"(dst), "l"(src));
}
#define CP_COMMIT() asm volatile("cp.async.commit_group;")
#define CP_WAIT(n)  asm volatile("cp.async.wait_group %0;" :: "n"(n))

__device__ __forceinline__ void mma_bf16(float* c, const uint32_t* a, const uint32_t* b) {
    asm volatile(
        "mma.sync.aligned.m16n8k16.row.col.f32.bf16.bf16.f32 "
        "{%0,%1,%2,%3}, {%4,%5,%6,%7}, {%8,%9}, {%0,%1,%2,%3};"
        : "+f"(c[0]), "+f"(c[1]), "+f"(c[2]), "+f"(c[3])
        : "r"(a[0]), "r"(a[1]), "r"(a[2]), "r"(a[3]), "r"(b[0]), "r"(b[1]));
}
__device__ __forceinline__ uint32_t pack_bf16(float a, float b) {
    __nv_bfloat162 h = __floats2bfloat162_rn(a, b);
    return *(uint32_t*)&h;
}

// ---------------- kernel 0: pack weights (bf16 hi/lo) + bias ----------------
__global__ void pack_kernel(const float* __restrict__ Wv, const float* __restrict__ bv,
                            const float* __restrict__ Wk, const float* __restrict__ bk,
                            const float* __restrict__ Wq, const float* __restrict__ bq,
                            const float* __restrict__ Wa, const float* __restrict__ ba) {
    int idx = blockIdx.x * 256 + threadIdx.x;
    if (idx < NPROJ_P * IN_DIM) {
        int o = idx >> 9, i = idx & 511;
        float v = 0.f;
        if (o < 512)       v = Wv[o * IN_DIM + i];
        else if (o < 576)  v = Wk[(o - 512) * IN_DIM + i];
        else if (o < 640)  v = Wq[(o - 576) * IN_DIM + i];
        else if (o < 704)  v = Wa[(o - 640) * IN_DIM + i];
        __nv_bfloat16 h = __float2bfloat16(v);
        __nv_bfloat16 l = __float2bfloat16(v - __bfloat162float(h));
        g_Wh[idx] = h;
        g_Wl[idx] = l;
    }
    if (idx < NPROJ) {
        float v;
        if (idx < 512)      v = bv[idx];
        else if (idx < 576) v = bk[idx - 512];
        else if (idx < 640) v = bq[idx - 576];
        else                v = ba[idx - 640];
        g_bias[idx] = v;
    }
}

// ---------------- kernel 1: X -> bf16 hi/lo ----------------
__global__ void __launch_bounds__(256) convx_kernel(const float* __restrict__ X) {
    size_t e0 = ((size_t)blockIdx.x * 256 + threadIdx.x) * 8;
    float4 v0 = *(const float4*)&X[e0];
    float4 v1 = *(const float4*)&X[e0 + 4];
    float f[8] = {v0.x, v0.y, v0.z, v0.w, v1.x, v1.y, v1.z, v1.w};
    __align__(16) __nv_bfloat16 hh[8], ll[8];
#pragma unroll
    for (int i = 0; i < 8; i++) {
        hh[i] = __float2bfloat16(f[i]);
        ll[i] = __float2bfloat16(f[i] - __bfloat162float(hh[i]));
    }
    *(uint4*)&g_Xh[e0] = *(uint4*)hh;
    *(uint4*)&g_Xl[e0] = *(uint4*)ll;
}

// ---------------- kernel 2: projection GEMM via HMMA bf16, cp.async double-buffered --
#define GP 72
#define GSTAGE (4 * 128 * GP)                 // bf16 elems per stage
#define GM_SMEM (2 * GSTAGE * 2)              // bytes

__global__ void __launch_bounds__(256) gemm_mma_kernel() {
    extern __shared__ __nv_bfloat16 sm_b[];
    uint32_t sb = smem_u32(sm_b);

    int tid = threadIdx.x, wid = tid >> 5, lane = tid & 31;
    int g = lane >> 2, tig = lane & 3;
    int wm = wid >> 2;               // 0..1 -> 64 rows each
    int wn = wid & 3;                // 0..3 -> 32 cols each
    int bx = blockIdx.x;             // n tile 0..5
    int m0 = blockIdx.y * 128;
    int n0 = bx * 128;

    // per-thread source pointers for staging (16 x 16B per chunk)
    int r = tid >> 1, q = (tid & 1) * 4;     // 256 thr -> 128 rows x 2 half-rows? no:
    // staging map: l in [0,1024): r=l>>3 (row), q=l&7 (uint4 within 64-col chunk)
    float acc[4][4][4];
#pragma unroll
    for (int i = 0; i < 4; i++)
#pragma unroll
        for (int j = 0; j < 4; j++)
#pragma unroll
            for (int k = 0; k < 4; k++) acc[i][j][k] = 0.f;

    // stage copy lambda-ish macro
#define GCOPY(ch, buf) do {                                                              \
    uint32_t base = sb + (uint32_t)(buf) * (GSTAGE * 2);                                 \
    _Pragma("unroll")                                                                    \
    for (int u = 0; u < 4; u++) {                                                        \
        int l = tid + u * 256;                                                           \
        int rr = l >> 3, qq = l & 7;                                                     \
        size_t gx = (size_t)(m0 + rr) * IN_DIM + (ch) * 64 + qq * 8;                     \
        size_t gw = (size_t)(n0 + rr) * IN_DIM + (ch) * 64 + qq * 8;                     \
        uint32_t so = (uint32_t)(rr * GP + qq * 8) * 2;                                  \
        cp16(base + so,                     &g_Xh[gx]);                                  \
        cp16(base + 128 * GP * 2 + so,      &g_Xl[gx]);                                  \
        cp16(base + 2 * 128 * GP * 2 + so,  &g_Wh[gw]);                                  \
        cp16(base + 3 * 128 * GP * 2 + so,  &g_Wl[gw]);                                  \
    }                                                                                    \
} while (0)

    GCOPY(0, 0);
    CP_COMMIT();

    for (int ch = 0; ch < 8; ch++) {
        if (ch + 1 < 8) { GCOPY(ch + 1, (ch + 1) & 1); CP_COMMIT(); }
        if (ch + 1 < 8) CP_WAIT(1); else CP_WAIT(0);
        __syncthreads();

        const __nv_bfloat16* sXh = sm_b + (size_t)(ch & 1) * GSTAGE;
        const __nv_bfloat16* sXl = sXh + 128 * GP;
        const __nv_bfloat16* sWh = sXl + 128 * GP;
        const __nv_bfloat16* sWl = sWh + 128 * GP;

#pragma unroll
        for (int ks = 0; ks < 64; ks += 16) {
            int kc = ks + tig * 2;
            uint32_t Ah[4][4], Al[4][4], Bh[4][2], Bl[4][2];
#pragma unroll
            for (int mi = 0; mi < 4; mi++) {
                int mb = wm * 64 + mi * 16 + g;
                const __nv_bfloat16* p = &sXh[mb * GP + kc];
                const __nv_bfloat16* qq = &sXl[mb * GP + kc];
                Ah[mi][0] = *(const uint32_t*)p;
                Ah[mi][1] = *(const uint32_t*)(p + 8 * GP);
                Ah[mi][2] = *(const uint32_t*)(p + 8);
                Ah[mi][3] = *(const uint32_t*)(p + 8 * GP + 8);
                Al[mi][0] = *(const uint32_t*)qq;
                Al[mi][1] = *(const uint32_t*)(qq + 8 * GP);
                Al[mi][2] = *(const uint32_t*)(qq + 8);
                Al[mi][3] = *(const uint32_t*)(qq + 8 * GP + 8);
            }
#pragma unroll
            for (int nj = 0; nj < 4; nj++) {
                int nb = wn * 32 + nj * 8 + g;
                const __nv_bfloat16* p = &sWh[nb * GP + kc];
                const __nv_bfloat16* qq = &sWl[nb * GP + kc];
                Bh[nj][0] = *(const uint32_t*)p;
                Bh[nj][1] = *(const uint32_t*)(p + 8);
                Bl[nj][0] = *(const uint32_t*)qq;
                Bl[nj][1] = *(const uint32_t*)(qq + 8);
            }
#pragma unroll
            for (int mi = 0; mi < 4; mi++)
#pragma unroll
                for (int nj = 0; nj < 4; nj++) {
                    mma_bf16(acc[mi][nj], Ah[mi], Bh[nj]);
                    mma_bf16(acc[mi][nj], Ah[mi], Bl[nj]);
                    mma_bf16(acc[mi][nj], Al[mi], Bh[nj]);
                }
        }
        __syncthreads();
    }

    // epilogue: bias (+ sigmoid for cols >= 640), store
#pragma unroll
    for (int mi = 0; mi < 4; mi++) {
        int r0 = m0 + wm * 64 + mi * 16 + g;
#pragma unroll
        for (int nj = 0; nj < 4; nj++) {
            int col = n0 + wn * 32 + nj * 8 + tig * 2;
            if (col >= NPROJ) continue;
            float b0 = g_bias[col], b1 = g_bias[col + 1];
            float v0 = acc[mi][nj][0] + b0, v1 = acc[mi][nj][1] + b1;
            float v2 = acc[mi][nj][2] + b0, v3 = acc[mi][nj][3] + b1;
            if (col >= 640) {
                v0 = 1.f / (1.f + expf(-v0));
                v1 = 1.f / (1.f + expf(-v1));
                v2 = 1.f / (1.f + expf(-v2));
                v3 = 1.f / (1.f + expf(-v3));
            }
            float2 lo; lo.x = v0; lo.y = v1;
            float2 hi; hi.x = v2; hi.y = v3;
            *(float2*)&g_proj[(size_t)r0 * NPROJ + col] = lo;
            *(float2*)&g_proj[(size_t)(r0 + 8) * NPROJ + col] = hi;
        }
    }
#undef GCOPY
}

// ---------------- kernel 3: per-chunk prep (p, q_t, kpe, A[t][s]) ----------------
#define PREP_SMEM (3 * 128 * 65 * 4)
__global__ void __launch_bounds__(256) prep_kernel() {
    extern __shared__ float sm[];
    float* sp  = sm;                 // [128][65] cumulative decay p
    float* sqt = sm + 128 * 65;      // [128][65] q_t
    float* skt = sm + 2 * 128 * 65;  // [128][65] k_t (also alpha temp)

    int b = blockIdx.x, c = blockIdx.y;
    int tid = threadIdx.x;

#pragma unroll
    for (int j = 0; j < 8; j++) {
        int l  = tid + j * 256;
        int t  = l >> 4;
        int c4 = (l & 15) * 4;
        const float* rowp = g_proj + (size_t)((c * CHUNK + t) * BATCH + b) * NPROJ;
        float4 av = *(const float4*)&rowp[640 + c4];
        skt[t * 65 + c4 + 0] = av.x; skt[t * 65 + c4 + 1] = av.y;
        skt[t * 65 + c4 + 2] = av.z; skt[t * 65 + c4 + 3] = av.w;
    }
    __syncthreads();

    if (tid < D_K) {
        float p = 1.f;
        for (int t = 0; t < CHUNK; t++) {
            p *= fmaxf(skt[t * 65 + tid], EPS_F);
            sp[t * 65 + tid] = p;
        }
        g_pend[(c * BATCH + b) * D_K + tid] = p;
    }
    __syncthreads();

    float* gq = g_qt  + (size_t)(c * BATCH + b) * CHUNK * D_K;
    float* gk = g_kpe + (size_t)(c * BATCH + b) * CHUNK * D_K;
#pragma unroll
    for (int j = 0; j < 8; j++) {
        int l  = tid + j * 256;
        int t  = l >> 4;
        int c4 = (l & 15) * 4;
        const float* rowp = g_proj + (size_t)((c * CHUNK + t) * BATCH + b) * NPROJ;
        float4 qv = *(const float4*)&rowp[576 + c4];
        float4 kv = *(const float4*)&rowp[512 + c4];
        float p0 = sp[t * 65 + c4 + 0], p1 = sp[t * 65 + c4 + 1];
        float p2 = sp[t * 65 + c4 + 2], p3 = sp[t * 65 + c4 + 3];
        float pe0 = sp[127 * 65 + c4 + 0], pe1 = sp[127 * 65 + c4 + 1];
        float pe2 = sp[127 * 65 + c4 + 2], pe3 = sp[127 * 65 + c4 + 3];
        float q0 = qv.x * p0, q1 = qv.y * p1, q2 = qv.z * p2, q3 = qv.w * p3;
        float k0 = kv.x / (p0 + EPS_F), k1 = kv.y / (p1 + EPS_F);
        float k2 = kv.z / (p2 + EPS_F), k3 = kv.w / (p3 + EPS_F);
        sqt[t * 65 + c4 + 0] = q0; sqt[t * 65 + c4 + 1] = q1;
        sqt[t * 65 + c4 + 2] = q2; sqt[t * 65 + c4 + 3] = q3;
        skt[t * 65 + c4 + 0] = k0; skt[t * 65 + c4 + 1] = k1;
        skt[t * 65 + c4 + 2] = k2; skt[t * 65 + c4 + 3] = k3;
        float4 oq; oq.x = q0; oq.y = q1; oq.z = q2; oq.w = q3;
        *(float4*)&gq[t * 64 + c4] = oq;
        float4 ok; ok.x = k0 * pe0; ok.y = k1 * pe1; ok.z = k2 * pe2; ok.w = k3 * pe3;
        *(float4*)&gk[t * 64 + c4] = ok;
    }
    __syncthreads();

    // A[t][s] = sum_n q_t[t][n] * k_t[s][n], masked t>=s, natural layout
    int sxl = tid & 15;
    int t0  = (tid >> 4) * 8;
    float acc[8][8];
#pragma unroll
    for (int i = 0; i < 8; i++)
#pragma unroll
        for (int j = 0; j < 8; j++) acc[i][j] = 0.f;

    for (int n = 0; n < D_K; n++) {
        float qv[8], kv[8];
#pragma unroll
        for (int i = 0; i < 8; i++) qv[i] = sqt[(t0 + i) * 65 + n];
#pragma unroll
        for (int j = 0; j < 8; j++) kv[j] = skt[(sxl + 16 * j) * 65 + n];
#pragma unroll
        for (int i = 0; i < 8; i++)
#pragma unroll
            for (int j = 0; j < 8; j++)
                acc[i][j] = fmaf(qv[i], kv[j], acc[i][j]);
    }
    float* Ab = g_A + (size_t)(c * BATCH + b) * CHUNK * CHUNK;
#pragma unroll
    for (int i = 0; i < 8; i++) {
        int t = t0 + i;
#pragma unroll
        for (int j = 0; j < 8; j++) {
            int s = sxl + 16 * j;
            Ab[t * CHUNK + s] = (t >= s) ? acc[i][j] : 0.f;
        }
    }
}

// ---------------- kernel 4: per-chunk state contributions W_c = v^T @ kpe ----------
__global__ void __launch_bounds__(256) contrib_kernel() {
    __shared__ float v_s[32][128];
    __shared__ float k_s[32][64];
    int d0 = blockIdx.x * 128, c = blockIdx.y, b = blockIdx.z;
    int tid = threadIdx.x;
    int tx = tid & 31;           // d group (4 each)
    int ty = tid >> 5;           // n group (8 each)

    float acc[8][4];
#pragma unroll
    for (int i = 0; i < 8; i++)
#pragma unroll
        for (int j = 0; j < 4; j++) acc[i][j] = 0.f;

    const float* kbase = g_kpe + (size_t)(c * BATCH + b) * CHUNK * D_K;

    for (int t0 = 0; t0 < CHUNK; t0 += 32) {
#pragma unroll
        for (int j = 0; j < 4; j++) {
            int l  = tid + j * 256;
            int tt = l >> 5;
            int c4 = (l & 31) * 4;
            float4 v = *(const float4*)&g_proj[(size_t)((c * CHUNK + t0 + tt) * BATCH + b) * NPROJ + d0 + c4];
            *(float4*)&v_s[tt][c4] = v;
        }
#pragma unroll
        for (int j = 0; j < 2; j++) {
            int l  = tid + j * 256;
            int tt = l >> 4;
            int c4 = (l & 15) * 4;
            float4 v = *(const float4*)&kbase[(t0 + tt) * D_K + c4];
            *(float4*)&k_s[tt][c4] = v;
        }
        __syncthreads();
#pragma unroll
        for (int t = 0; t < 32; t++) {
            float4 vv = *(const float4*)&v_s[t][tx * 4];
            float4 k0v = *(const float4*)&k_s[t][ty * 8];
            float4 k1v = *(const float4*)&k_s[t][ty * 8 + 4];
            float kn[8] = {k0v.x, k0v.y, k0v.z, k0v.w, k1v.x, k1v.y, k1v.z, k1v.w};
#pragma unroll
            for (int i = 0; i < 8; i++) {
                acc[i][0] = fmaf(kn[i], vv.x, acc[i][0]);
                acc[i][1] = fmaf(kn[i], vv.y, acc[i][1]);
                acc[i][2] = fmaf(kn[i], vv.z, acc[i][2]);
                acc[i][3] = fmaf(kn[i], vv.w, acc[i][3]);
            }
        }
        __syncthreads();
    }
#pragma unroll
    for (int i = 0; i < 8; i++) {
        float4 o; o.x = acc[i][0]; o.y = acc[i][1]; o.z = acc[i][2]; o.w = acc[i][3];
        *(float4*)&g_Wc[(size_t)((c * BATCH + b) * D_K + ty * 8 + i) * D_V + d0 + tx * 4] = o;
    }
}

// ---------------- kernel 5: elementwise state scan over chunks --------------------
__global__ void __launch_bounds__(256) state_scan_kernel() {
    int g = blockIdx.x * 256 + threadIdx.x;  // g = (b*64+n)*512 + d
    int bn = g >> 9;
    float s = 0.f;
    for (int c = 0; c < NC; c++) {
        size_t idx = (size_t)c * SEG + g;
        g_Sstart[idx] = s;
        s = fmaf(s, g_pend[c * (BATCH * D_K) + bn], g_Wc[idx]);
    }
}

// ---------------- kernel 6: Y = [A | q_t] @ [V ; S] via HMMA bf16 3-term ----------
// C[t=128][d=64] per (c,b,dtile). K = 192 in 3 chunks of 64.
// A-operand row-major (A then q_t). B-operand [d][k] K-major: transposed staging of
// V (from g_proj) and S_start, fp32 -> bf16 hi/lo on the fly.
#define YP 68
#define YG_SMEM ((2 * 128 * YP + 2 * 64 * YP) * 2)

__global__ void __launch_bounds__(128) ygemm_mma_kernel(float* __restrict__ out) {
    extern __shared__ __nv_bfloat16 ysm[];
    __nv_bfloat16* sAh = ysm;                    // [128][YP]
    __nv_bfloat16* sAl = sAh + 128 * YP;
    __nv_bfloat16* sBh = sAl + 128 * YP;         // [64][YP]
    __nv_bfloat16* sBl = sBh + 64 * YP;

    int d0 = blockIdx.x * 64;
    int c = blockIdx.y, b = blockIdx.z;
    int tid = threadIdx.x, w = tid >> 5, lane = tid & 31;
    int g = lane >> 2, tig = lane & 3;

    const float* Abase = g_A  + (size_t)(c * BATCH + b) * CHUNK * CHUNK;
    const float* Qbase = g_qt + (size_t)(c * BATCH + b) * CHUNK * D_K;
    const float* Sbase = g_Sstart + (size_t)(c * BATCH + b) * D_K * D_V;

    float acc[2][8][4];
#pragma unroll
    for (int i = 0; i < 2; i++)
#pragma unroll
        for (int j = 0; j < 8; j++)
#pragma unroll
            for (int k = 0; k < 4; k++) acc[i][j][k] = 0.f;

    for (int ch = 0; ch < 3; ch++) {
        __syncthreads();
        // --- stage A-op tile: 128 rows x 64 k (fp32 -> hi/lo), row-major ---
#pragma unroll
        for (int u = 0; u < 16; u++) {
            int l = tid + u * 128;           // 0..2047 float4 ids
            int rr = l >> 4, qq = l & 15;    // row, float4 col (k = qq*4)
            float4 v;
            if (ch < 2) v = *(const float4*)&Abase[rr * CHUNK + ch * 64 + qq * 4];
            else        v = *(const float4*)&Qbase[rr * D_K + qq * 4];
            int so = rr * YP + qq * 4;
            *(uint32_t*)&sAh[so]     = pack_bf16(__bfloat162float(__float2bfloat16(v.x)) * 0.f + 0.f, 0.f); // placeholder avoided below
            // (real packing below)
            __nv_bfloat16 h0 = __float2bfloat16(v.x), h1 = __float2bfloat16(v.y);
            __nv_bfloat16 h2 = __float2bfloat16(v.z), h3 = __float2bfloat16(v.w);
            float l0 = v.x - __bfloat162float(h0), l1 = v.y - __bfloat162float(h1);
            float l2 = v.z - __bfloat162float(h2), l3 = v.w - __bfloat162float(h3);
            __nv_bfloat162 hp0 = __floats2bfloat162_rn(v.x, v.y);   // rn pack of hi parts
            // NOTE: hi parts must be truncation-consistent: use h0..h3 directly
            uint32_t hA = ((uint32_t)*(uint16_t*)&h1 << 16) | *(uint16_t*)&h0;
            uint32_t hB = ((uint32_t)*(uint16_t*)&h3 << 16) | *(uint16_t*)&h2;
            *(uint32_t*)&sAh[so]     = hA;
            *(uint32_t*)&sAh[so + 2] = hB;
            *(uint32_t*)&sAl[so]     = pack_bf16(l0, l1);
            *(uint32_t*)&sAl[so + 2] = pack_bf16(l2, l3);
            (void)hp0;
        }
        // --- stage B-op tile transposed: 64 d-rows x 64 k ---
#pragma unroll
        for (int u = 0; u < 8; u++) {
            int l = tid + u * 128;           // 0..1023 float4 ids
            int ss = l >> 4, qq = l & 15;    // source row (s or n), d-quad
            float4 v;
            if (ch == 0)
                v = *(const float4*)&g_proj[(size_t)((c * CHUNK + ss) * BATCH + b) * NPROJ + d0 + qq * 4];
            else if (ch == 1)
                v = *(const float4*)&g_proj[(size_t)((c * CHUNK + 64 + ss) * BATCH + b) * NPROJ + d0 + qq * 4];
            else
                v = *(const float4*)&Sbase[(size_t)ss * D_V + d0 + qq * 4];
            float vals[4] = {v.x, v.y, v.z, v.w};
#pragma unroll
            for (int j = 0; j < 4; j++) {
                int dd = qq * 4 + j;
                __nv_bfloat16 h = __float2bfloat16(vals[j]);
                sBh[dd * YP + ss] = h;
                sBl[dd * YP + ss] = __float2bfloat16(vals[j] - __bfloat162float(h));
            }
        }
        __syncthreads();

        // --- compute: warp w covers m rows w*32..+31 (2 frags), all 64 d (8 frags) ---
#pragma unroll
        for (int ks = 0; ks < 64; ks += 16) {
            int kc = ks + tig * 2;
            uint32_t Ah[2][4], Al[2][4], Bh[8][2], Bl[8][2];
#pragma unroll
            for (int mi = 0; mi < 2; mi++) {
                int mb = w * 32 + mi * 16 + g;
                const __nv_bfloat16* p = &sAh[mb * YP + kc];
                const __nv_bfloat16* qq = &sAl[mb * YP + kc];
                Ah[mi][0] = *(const uint32_t*)p;
                Ah[mi][1] = *(const uint32_t*)(p + 8 * YP);
                Ah[mi][2] = *(const uint32_t*)(p + 8);
                Ah[mi][3] = *(const uint32_t*)(p + 8 * YP + 8);
                Al[mi][0] = *(const uint32_t*)qq;
                Al[mi][1] = *(const uint32_t*)(qq + 8 * YP);
                Al[mi][2] = *(const uint32_t*)(qq + 8);
                Al[mi][3] = *(const uint32_t*)(qq + 8 * YP + 8);
            }
#pragma unroll
            for (int nj = 0; nj < 8; nj++) {
                int nb = nj * 8 + g;
                const __nv_bfloat16* p = &sBh[nb * YP + kc];
                const __nv_bfloat16* qq = &sBl[nb * YP + kc];
                Bh[nj][0] = *(const uint32_t*)p;
                Bh[nj][1] = *(const uint32_t*)(p + 8);
                Bl[nj][0] = *(const uint32_t*)qq;
                Bl[nj][1] = *(const uint32_t*)(qq + 8);
            }
#pragma unroll
            for (int mi = 0; mi < 2; mi++)
#pragma unroll
                for (int nj = 0; nj < 8; nj++) {
                    mma_bf16(acc[mi][nj], Ah[mi], Bh[nj]);
                    mma_bf16(acc[mi][nj], Ah[mi], Bl[nj]);
                    mma_bf16(acc[mi][nj], Al[mi], Bh[nj]);
                }
        }
    }

    // --- epilogue: write Y ---
#pragma unroll
    for (int mi = 0; mi < 2; mi++) {
        int t = w * 32 + mi * 16 + g;
#pragma unroll
        for (int nj = 0; nj < 8; nj++) {
            int col = d0 + nj * 8 + tig * 2;
            float2 lo; lo.x = acc[mi][nj][0]; lo.y = acc[mi][nj][1];
            float2 hi; hi.x = acc[mi][nj][2]; hi.y = acc[mi][nj][3];
            *(float2*)&out[(size_t)((c * CHUNK + t) * BATCH + b) * D_V + col] = lo;
            *(float2*)&out[(size_t)((c * CHUNK + t + 8) * BATCH + b) * D_V + col] = hi;
        }
    }
}

// ---------------- launch ----------------
extern "C" void kernel_launch(void* const* d_in, const int* in_sizes, int n_in,
                              void* d_out, int out_size) {
    const float* x  = (const float*)d_in[0];
    const float* Wv = (const float*)d_in[1];
    const float* bv = (const float*)d_in[2];
    const float* Wk = (const float*)d_in[3];
    const float* bk = (const float*)d_in[4];
    const float* Wq = (const float*)d_in[5];
    const float* bq = (const float*)d_in[6];
    const float* Wa = (const float*)d_in[7];
    const float* ba = (const float*)d_in[8];
    float* out = (float*)d_out;

    cudaFuncSetAttribute(prep_kernel, cudaFuncAttributeMaxDynamicSharedMemorySize, PREP_SMEM);
    cudaFuncSetAttribute(gemm_mma_kernel, cudaFuncAttributeMaxDynamicSharedMemorySize, GM_SMEM);
    cudaFuncSetAttribute(ygemm_mma_kernel, cudaFuncAttributeMaxDynamicSharedMemorySize, YG_SMEM);

    pack_kernel<<<(NPROJ_P * IN_DIM + 255) / 256, 256>>>(Wv, bv, Wk, bk, Wq, bq, Wa, ba);
    convx_kernel<<<(int)(((size_t)MROWS * IN_DIM / 8) / 256), 256>>>(x);
    gemm_mma_kernel<<<dim3(NPROJ_P / 128, MROWS / 128), 256, GM_SMEM>>>();
    prep_kernel<<<dim3(BATCH, NC), 256, PREP_SMEM>>>();
    contrib_kernel<<<dim3(D_V / 128, NC, BATCH), 256>>>();
    state_scan_kernel<<<SEG / 256, 256>>>();
    ygemm_mma_kernel<<<dim3(D_V / 64, NC, BATCH), 128, YG_SMEM>>>(out);
}

// round 7
// speedup vs baseline: 2.6434x; 1.0568x over previous
#include <cuda_runtime.h>
#include <cuda_bf16.h>
#include <math.h>
#include <stdint.h>

#define T_LEN   8192
#define BATCH   4
#define IN_DIM  512
#define D_V     512
#define D_K     64
#define CHUNK   128
#define NC      (T_LEN / CHUNK)          // 64
#define NPROJ   (D_V + 3 * D_K)          // 704
#define NPROJ_P 768                      // padded to 6*128
#define MROWS   (T_LEN * BATCH)          // 32768
#define EPS_F   1e-8f
#define SEG     (BATCH * D_K * D_V)      // 131072 state elements
#define AQW     192                      // A(128) | qt(64) fused row width

// ---------------- static device scratch ----------------
__device__ __align__(128) float g_bias[NPROJ];
__device__ __align__(128) __nv_bfloat16 g_Wh[NPROJ_P * IN_DIM];
__device__ __align__(128) __nv_bfloat16 g_Wl[NPROJ_P * IN_DIM];
__device__ __align__(128) __nv_bfloat16 g_Xh[(size_t)MROWS * IN_DIM];
__device__ __align__(128) __nv_bfloat16 g_Xl[(size_t)MROWS * IN_DIM];
__device__ __align__(128) float g_proj[(size_t)MROWS * NPROJ];             // [t*B+b][704] : v|k|q|sig(a)
__device__ __align__(128) __nv_bfloat16 g_AQh[(size_t)NC * BATCH * CHUNK * AQW]; // [c][b][t][A|qt] hi
__device__ __align__(128) __nv_bfloat16 g_AQl[(size_t)NC * BATCH * CHUNK * AQW]; // lo
__device__ __align__(128) float g_kpe[(size_t)NC * BATCH * CHUNK * D_K];
__device__ __align__(128) float g_pend[NC * BATCH * D_K];
__device__ __align__(128) float g_Wc[(size_t)NC * SEG];
__device__ __align__(128) __nv_bfloat16 g_Sh[(size_t)NC * SEG];            // S_start hi [c][b][n][d]
__device__ __align__(128) __nv_bfloat16 g_Sl[(size_t)NC * SEG];            // lo

// ---------------- helpers ----------------
__device__ __forceinline__ uint32_t smem_u32(const void* p) {
    uint32_t a;
    asm("{ .reg .u64 t; cvta.to.shared.u64 t, %1; cvt.u32.u64 %0, t; }" : "=r"(a) : "l"(p));
    return a;
}
__device__ __forceinline__ void cp16(uint32_t dst, const void* src) {
    asm volatile("cp.async.cg.shared.global [%0], [%1], 16;" :: "r"(dst), "l"(src));
}
#define CP_COMMIT() asm volatile("cp.async.commit_group;")
#define CP_WAIT(n)  asm volatile("cp.async.wait_group %0;" :: "n"(n))

__device__ __forceinline__ void mma_bf16(float* c, const uint32_t* a, const uint32_t* b) {
    asm volatile(
        "mma.sync.aligned.m16n8k16.row.col.f32.bf16.bf16.f32 "
        "{%0,%1,%2,%3}, {%4,%5,%6,%7}, {%8,%9}, {%0,%1,%2,%3};"
        : "+f"(c[0]), "+f"(c[1]), "+f"(c[2]), "+f"(c[3])
        : "r"(a[0]), "r"(a[1]), "r"(a[2]), "r"(a[3]), "r"(b[0]), "r"(b[1]));
}
__device__ __forceinline__ void ldm_x4_trans(uint32_t& r0, uint32_t& r1, uint32_t& r2, uint32_t& r3,
                                             uint32_t addr) {
    asm volatile("ldmatrix.sync.aligned.m8n8.x4.trans.shared.b16 {%0,%1,%2,%3}, [%4];"
                 : "=r"(r0), "=r"(r1), "=r"(r2), "=r"(r3) : "r"(addr));
}
__device__ __forceinline__ uint32_t pack2h(__nv_bfloat16 a, __nv_bfloat16 b) {
    return ((uint32_t)*(uint16_t*)&b << 16) | *(uint16_t*)&a;
}
__device__ __forceinline__ void split_bf16(float v, __nv_bfloat16& h, __nv_bfloat16& l) {
    h = __float2bfloat16(v);
    l = __float2bfloat16(v - __bfloat162float(h));
}

// ---------------- kernel 0: pack weights (bf16 hi/lo) + bias ----------------
__global__ void pack_kernel(const float* __restrict__ Wv, const float* __restrict__ bv,
                            const float* __restrict__ Wk, const float* __restrict__ bk,
                            const float* __restrict__ Wq, const float* __restrict__ bq,
                            const float* __restrict__ Wa, const float* __restrict__ ba) {
    int idx = blockIdx.x * 256 + threadIdx.x;
    if (idx < NPROJ_P * IN_DIM) {
        int o = idx >> 9, i = idx & 511;
        float v = 0.f;
        if (o < 512)       v = Wv[o * IN_DIM + i];
        else if (o < 576)  v = Wk[(o - 512) * IN_DIM + i];
        else if (o < 640)  v = Wq[(o - 576) * IN_DIM + i];
        else if (o < 704)  v = Wa[(o - 640) * IN_DIM + i];
        __nv_bfloat16 h, l; split_bf16(v, h, l);
        g_Wh[idx] = h;
        g_Wl[idx] = l;
    }
    if (idx < NPROJ) {
        float v;
        if (idx < 512)      v = bv[idx];
        else if (idx < 576) v = bk[idx - 512];
        else if (idx < 640) v = bq[idx - 576];
        else                v = ba[idx - 640];
        g_bias[idx] = v;
    }
}

// ---------------- kernel 1: X -> bf16 hi/lo ----------------
__global__ void __launch_bounds__(256) convx_kernel(const float* __restrict__ X) {
    size_t e0 = ((size_t)blockIdx.x * 256 + threadIdx.x) * 8;
    float4 v0 = *(const float4*)&X[e0];
    float4 v1 = *(const float4*)&X[e0 + 4];
    float f[8] = {v0.x, v0.y, v0.z, v0.w, v1.x, v1.y, v1.z, v1.w};
    __align__(16) __nv_bfloat16 hh[8], ll[8];
#pragma unroll
    for (int i = 0; i < 8; i++) split_bf16(f[i], hh[i], ll[i]);
    *(uint4*)&g_Xh[e0] = *(uint4*)hh;
    *(uint4*)&g_Xl[e0] = *(uint4*)ll;
}

// ---------------- kernel 2: projection GEMM via HMMA bf16, cp.async 2-stage --------
#define GP 72
#define GSTAGE (4 * 128 * GP)                 // bf16 elems per stage
#define GM_SMEM (2 * GSTAGE * 2)              // bytes

__global__ void __launch_bounds__(256) gemm_mma_kernel() {
    extern __shared__ __nv_bfloat16 sm_b[];
    uint32_t sb = smem_u32(sm_b);

    int tid = threadIdx.x, wid = tid >> 5, lane = tid & 31;
    int g = lane >> 2, tig = lane & 3;
    int wm = wid >> 2;               // 0..1 -> 64 rows each
    int wn = wid & 3;                // 0..3 -> 32 cols each
    int bx = blockIdx.x;             // n tile 0..5
    int m0 = blockIdx.y * 128;
    int n0 = bx * 128;
    bool active = (n0 + wn * 32 < NPROJ);   // alpha tile: warps 2,3 idle

    float acc[4][4][4];
#pragma unroll
    for (int i = 0; i < 4; i++)
#pragma unroll
        for (int j = 0; j < 4; j++)
#pragma unroll
            for (int k = 0; k < 4; k++) acc[i][j][k] = 0.f;

#define GCOPY(ch, buf) do {                                                              \
    uint32_t base = sb + (uint32_t)(buf) * (GSTAGE * 2);                                 \
    _Pragma("unroll")                                                                    \
    for (int u = 0; u < 4; u++) {                                                        \
        int l = tid + u * 256;                                                           \
        int rr = l >> 3, qq = l & 7;                                                     \
        size_t gx = (size_t)(m0 + rr) * IN_DIM + (ch) * 64 + qq * 8;                     \
        size_t gw = (size_t)(n0 + rr) * IN_DIM + (ch) * 64 + qq * 8;                     \
        uint32_t so = (uint32_t)(rr * GP + qq * 8) * 2;                                  \
        cp16(base + so,                     &g_Xh[gx]);                                  \
        cp16(base + 128 * GP * 2 + so,      &g_Xl[gx]);                                  \
        cp16(base + 2 * 128 * GP * 2 + so,  &g_Wh[gw]);                                  \
        cp16(base + 3 * 128 * GP * 2 + so,  &g_Wl[gw]);                                  \
    }                                                                                    \
} while (0)

    GCOPY(0, 0);
    CP_COMMIT();

    for (int ch = 0; ch < 8; ch++) {
        if (ch + 1 < 8) { GCOPY(ch + 1, (ch + 1) & 1); CP_COMMIT(); }
        if (ch + 1 < 8) CP_WAIT(1); else CP_WAIT(0);
        __syncthreads();

        const __nv_bfloat16* sXh = sm_b + (size_t)(ch & 1) * GSTAGE;
        const __nv_bfloat16* sXl = sXh + 128 * GP;
        const __nv_bfloat16* sWh = sXl + 128 * GP;
        const __nv_bfloat16* sWl = sWh + 128 * GP;

        if (active) {
#pragma unroll
            for (int ks = 0; ks < 64; ks += 16) {
                int kc = ks + tig * 2;
                uint32_t Ah[4][4], Al[4][4], Bh[4][2], Bl[4][2];
#pragma unroll
                for (int mi = 0; mi < 4; mi++) {
                    int mb = wm * 64 + mi * 16 + g;
                    const __nv_bfloat16* p = &sXh[mb * GP + kc];
                    const __nv_bfloat16* qq = &sXl[mb * GP + kc];
                    Ah[mi][0] = *(const uint32_t*)p;
                    Ah[mi][1] = *(const uint32_t*)(p + 8 * GP);
                    Ah[mi][2] = *(const uint32_t*)(p + 8);
                    Ah[mi][3] = *(const uint32_t*)(p + 8 * GP + 8);
                    Al[mi][0] = *(const uint32_t*)qq;
                    Al[mi][1] = *(const uint32_t*)(qq + 8 * GP);
                    Al[mi][2] = *(const uint32_t*)(qq + 8);
                    Al[mi][3] = *(const uint32_t*)(qq + 8 * GP + 8);
                }
#pragma unroll
                for (int nj = 0; nj < 4; nj++) {
                    int nb = wn * 32 + nj * 8 + g;
                    const __nv_bfloat16* p = &sWh[nb * GP + kc];
                    const __nv_bfloat16* qq = &sWl[nb * GP + kc];
                    Bh[nj][0] = *(const uint32_t*)p;
                    Bh[nj][1] = *(const uint32_t*)(p + 8);
                    Bl[nj][0] = *(const uint32_t*)qq;
                    Bl[nj][1] = *(const uint32_t*)(qq + 8);
                }
#pragma unroll
                for (int mi = 0; mi < 4; mi++)
#pragma unroll
                    for (int nj = 0; nj < 4; nj++) {
                        mma_bf16(acc[mi][nj], Ah[mi], Bh[nj]);
                        mma_bf16(acc[mi][nj], Ah[mi], Bl[nj]);
                        mma_bf16(acc[mi][nj], Al[mi], Bh[nj]);
                    }
            }
        }
        __syncthreads();
    }

#pragma unroll
    for (int mi = 0; mi < 4; mi++) {
        int r0 = m0 + wm * 64 + mi * 16 + g;
#pragma unroll
        for (int nj = 0; nj < 4; nj++) {
            int col = n0 + wn * 32 + nj * 8 + tig * 2;
            if (col >= NPROJ) continue;
            float b0 = g_bias[col], b1 = g_bias[col + 1];
            float v0 = acc[mi][nj][0] + b0, v1 = acc[mi][nj][1] + b1;
            float v2 = acc[mi][nj][2] + b0, v3 = acc[mi][nj][3] + b1;
            if (col >= 640) {
                v0 = 1.f / (1.f + expf(-v0));
                v1 = 1.f / (1.f + expf(-v1));
                v2 = 1.f / (1.f + expf(-v2));
                v3 = 1.f / (1.f + expf(-v3));
            }
            float2 lo; lo.x = v0; lo.y = v1;
            float2 hi; hi.x = v2; hi.y = v3;
            *(float2*)&g_proj[(size_t)r0 * NPROJ + col] = lo;
            *(float2*)&g_proj[(size_t)(r0 + 8) * NPROJ + col] = hi;
        }
    }
#undef GCOPY
}

// ---------------- kernel 3: per-chunk prep -> p, kpe(fp32), AQ(bf16 hi/lo) -------
#define PREP_SMEM (3 * 128 * 65 * 4)
__global__ void __launch_bounds__(256) prep_kernel() {
    extern __shared__ float sm[];
    float* sp  = sm;                 // [128][65] cumulative decay p
    float* sqt = sm + 128 * 65;      // [128][65] q_t
    float* skt = sm + 2 * 128 * 65;  // [128][65] k_t (also alpha temp)

    int b = blockIdx.x, c = blockIdx.y;
    int tid = threadIdx.x;
    size_t aqbase = (size_t)(c * BATCH + b) * CHUNK * AQW;

#pragma unroll
    for (int j = 0; j < 8; j++) {
        int l  = tid + j * 256;
        int t  = l >> 4;
        int c4 = (l & 15) * 4;
        const float* rowp = g_proj + (size_t)((c * CHUNK + t) * BATCH + b) * NPROJ;
        float4 av = *(const float4*)&rowp[640 + c4];
        skt[t * 65 + c4 + 0] = av.x; skt[t * 65 + c4 + 1] = av.y;
        skt[t * 65 + c4 + 2] = av.z; skt[t * 65 + c4 + 3] = av.w;
    }
    __syncthreads();

    if (tid < D_K) {
        float p = 1.f;
        for (int t = 0; t < CHUNK; t++) {
            p *= fmaxf(skt[t * 65 + tid], EPS_F);
            sp[t * 65 + tid] = p;
        }
        g_pend[(c * BATCH + b) * D_K + tid] = p;
    }
    __syncthreads();

    float* gk = g_kpe + (size_t)(c * BATCH + b) * CHUNK * D_K;
#pragma unroll
    for (int j = 0; j < 8; j++) {
        int l  = tid + j * 256;
        int t  = l >> 4;
        int c4 = (l & 15) * 4;
        const float* rowp = g_proj + (size_t)((c * CHUNK + t) * BATCH + b) * NPROJ;
        float4 qv = *(const float4*)&rowp[576 + c4];
        float4 kv = *(const float4*)&rowp[512 + c4];
        float p0 = sp[t * 65 + c4 + 0], p1 = sp[t * 65 + c4 + 1];
        float p2 = sp[t * 65 + c4 + 2], p3 = sp[t * 65 + c4 + 3];
        float pe0 = sp[127 * 65 + c4 + 0], pe1 = sp[127 * 65 + c4 + 1];
        float pe2 = sp[127 * 65 + c4 + 2], pe3 = sp[127 * 65 + c4 + 3];
        float q0 = qv.x * p0, q1 = qv.y * p1, q2 = qv.z * p2, q3 = qv.w * p3;
        float k0 = kv.x / (p0 + EPS_F), k1 = kv.y / (p1 + EPS_F);
        float k2 = kv.z / (p2 + EPS_F), k3 = kv.w / (p3 + EPS_F);
        sqt[t * 65 + c4 + 0] = q0; sqt[t * 65 + c4 + 1] = q1;
        sqt[t * 65 + c4 + 2] = q2; sqt[t * 65 + c4 + 3] = q3;
        skt[t * 65 + c4 + 0] = k0; skt[t * 65 + c4 + 1] = k1;
        skt[t * 65 + c4 + 2] = k2; skt[t * 65 + c4 + 3] = k3;
        // qt -> bf16 hi/lo into fused AQ rows (cols 128..191)
        __nv_bfloat16 h0, h1, h2, h3, l0, l1, l2, l3;
        split_bf16(q0, h0, l0); split_bf16(q1, h1, l1);
        split_bf16(q2, h2, l2); split_bf16(q3, h3, l3);
        uint32_t* ph = (uint32_t*)&g_AQh[aqbase + t * AQW + 128 + c4];
        uint32_t* pl = (uint32_t*)&g_AQl[aqbase + t * AQW + 128 + c4];
        ph[0] = pack2h(h0, h1); ph[1] = pack2h(h2, h3);
        pl[0] = pack2h(l0, l1); pl[1] = pack2h(l2, l3);
        // kpe fp32 (contrib consumes)
        float4 ok; ok.x = k0 * pe0; ok.y = k1 * pe1; ok.z = k2 * pe2; ok.w = k3 * pe3;
        *(float4*)&gk[t * 64 + c4] = ok;
    }
    __syncthreads();

    // A[t][s] = sum_n q_t[t][n] * k_t[s][n], masked t>=s -> bf16 hi/lo
    int sxl = tid & 15;
    int t0  = (tid >> 4) * 8;
    float acc[8][8];
#pragma unroll
    for (int i = 0; i < 8; i++)
#pragma unroll
        for (int j = 0; j < 8; j++) acc[i][j] = 0.f;

    for (int n = 0; n < D_K; n++) {
        float qv[8], kv[8];
#pragma unroll
        for (int i = 0; i < 8; i++) qv[i] = sqt[(t0 + i) * 65 + n];
#pragma unroll
        for (int j = 0; j < 8; j++) kv[j] = skt[(sxl + 16 * j) * 65 + n];
#pragma unroll
        for (int i = 0; i < 8; i++)
#pragma unroll
            for (int j = 0; j < 8; j++)
                acc[i][j] = fmaf(qv[i], kv[j], acc[i][j]);
    }
#pragma unroll
    for (int i = 0; i < 8; i++) {
        int t = t0 + i;
#pragma unroll
        for (int j = 0; j < 8; j++) {
            int s = sxl + 16 * j;
            float val = (t >= s) ? acc[i][j] : 0.f;
            __nv_bfloat16 h, l; split_bf16(val, h, l);
            g_AQh[aqbase + t * AQW + s] = h;
            g_AQl[aqbase + t * AQW + s] = l;
        }
    }
}

// ---------------- kernel 4: per-chunk state contributions W_c = v^T @ kpe ----------
__global__ void __launch_bounds__(256) contrib_kernel() {
    __shared__ float v_s[32][128];
    __shared__ float k_s[32][64];
    int d0 = blockIdx.x * 128, c = blockIdx.y, b = blockIdx.z;
    int tid = threadIdx.x;
    int tx = tid & 31;           // d group (4 each)
    int ty = tid >> 5;           // n group (8 each)

    float acc[8][4];
#pragma unroll
    for (int i = 0; i < 8; i++)
#pragma unroll
        for (int j = 0; j < 4; j++) acc[i][j] = 0.f;

    const float* kbase = g_kpe + (size_t)(c * BATCH + b) * CHUNK * D_K;

    for (int t0 = 0; t0 < CHUNK; t0 += 32) {
#pragma unroll
        for (int j = 0; j < 4; j++) {
            int l  = tid + j * 256;
            int tt = l >> 5;
            int c4 = (l & 31) * 4;
            float4 v = *(const float4*)&g_proj[(size_t)((c * CHUNK + t0 + tt) * BATCH + b) * NPROJ + d0 + c4];
            *(float4*)&v_s[tt][c4] = v;
        }
#pragma unroll
        for (int j = 0; j < 2; j++) {
            int l  = tid + j * 256;
            int tt = l >> 4;
            int c4 = (l & 15) * 4;
            float4 v = *(const float4*)&kbase[(t0 + tt) * D_K + c4];
            *(float4*)&k_s[tt][c4] = v;
        }
        __syncthreads();
#pragma unroll
        for (int t = 0; t < 32; t++) {
            float4 vv = *(const float4*)&v_s[t][tx * 4];
            float4 k0v = *(const float4*)&k_s[t][ty * 8];
            float4 k1v = *(const float4*)&k_s[t][ty * 8 + 4];
            float kn[8] = {k0v.x, k0v.y, k0v.z, k0v.w, k1v.x, k1v.y, k1v.z, k1v.w};
#pragma unroll
            for (int i = 0; i < 8; i++) {
                acc[i][0] = fmaf(kn[i], vv.x, acc[i][0]);
                acc[i][1] = fmaf(kn[i], vv.y, acc[i][1]);
                acc[i][2] = fmaf(kn[i], vv.z, acc[i][2]);
                acc[i][3] = fmaf(kn[i], vv.w, acc[i][3]);
            }
        }
        __syncthreads();
    }
#pragma unroll
    for (int i = 0; i < 8; i++) {
        float4 o; o.x = acc[i][0]; o.y = acc[i][1]; o.z = acc[i][2]; o.w = acc[i][3];
        *(float4*)&g_Wc[(size_t)((c * BATCH + b) * D_K + ty * 8 + i) * D_V + d0 + tx * 4] = o;
    }
}

// ---------------- kernel 5: elementwise state scan; emit S_start bf16 hi/lo -------
__global__ void __launch_bounds__(256) state_scan_kernel() {
    int g = blockIdx.x * 256 + threadIdx.x;  // g = (b*64+n)*512 + d
    int bn = g >> 9;
    float s = 0.f;
    for (int c = 0; c < NC; c++) {
        size_t idx = (size_t)c * SEG + g;
        __nv_bfloat16 h, l; split_bf16(s, h, l);
        g_Sh[idx] = h;
        g_Sl[idx] = l;
        s = fmaf(s, g_pend[c * (BATCH * D_K) + bn], g_Wc[idx]);
    }
}

// ---------------- kernel 6: Y = [A | q_t] @ [V ; S] via HMMA, ldmatrix.trans B ----
#define YP 72
#define YG_SMEM ((2 * 128 * YP + 2 * 64 * YP) * 2)

__global__ void __launch_bounds__(128) ygemm_mma_kernel(float* __restrict__ out) {
    extern __shared__ __nv_bfloat16 ysm[];
    __nv_bfloat16* sAh = ysm;                    // [128][YP]
    __nv_bfloat16* sAl = sAh + 128 * YP;
    __nv_bfloat16* sBh = sAl + 128 * YP;         // [64 k][YP d]
    __nv_bfloat16* sBl = sBh + 64 * YP;
    uint32_t uAh = smem_u32(sAh), uAl = smem_u32(sAl);
    uint32_t uBh = smem_u32(sBh), uBl = smem_u32(sBl);

    int d0 = blockIdx.x * 64;
    int c = blockIdx.y, b = blockIdx.z;
    int tid = threadIdx.x, w = tid >> 5, lane = tid & 31;
    int g = lane >> 2, tig = lane & 3;
    // ldmatrix lane address components
    int lq = lane & 7, lseg = lane >> 3;         // row-in-matrix, matrix id

    size_t aqbase = (size_t)(c * BATCH + b) * CHUNK * AQW;
    size_t sbase  = (size_t)(c * BATCH + b) * D_K * D_V;

    float acc[2][8][4];
#pragma unroll
    for (int i = 0; i < 2; i++)
#pragma unroll
        for (int j = 0; j < 8; j++)
#pragma unroll
            for (int k = 0; k < 4; k++) acc[i][j][k] = 0.f;

    for (int ch = 0; ch < 3; ch++) {
        __syncthreads();
        // --- A staging: cp.async 128 rows x 64 bf16 (hi+lo) ---
#pragma unroll
        for (int u = 0; u < 8; u++) {
            int l = tid + u * 128;               // 0..1023
            int rr = l >> 3, qq = l & 7;
            size_t src = aqbase + rr * AQW + ch * 64 + qq * 8;
            uint32_t so = (uint32_t)(rr * YP + qq * 8) * 2;
            cp16(uAh + so, &g_AQh[src]);
            cp16(uAl + so, &g_AQl[src]);
        }
        // --- B staging ---
        if (ch < 2) {
            // V rows s=ch*64..+63: fp32 -> bf16 hi/lo, row-major [s][d]
#pragma unroll
            for (int u = 0; u < 8; u++) {
                int l = tid + u * 128;           // 0..1023 float4 ids
                int ss = l >> 4, qq = l & 15;
                float4 v = *(const float4*)&g_proj[(size_t)((c * CHUNK + ch * 64 + ss) * BATCH + b) * NPROJ + d0 + qq * 4];
                __nv_bfloat16 h0, h1, h2, h3, l0, l1, l2, l3;
                split_bf16(v.x, h0, l0); split_bf16(v.y, h1, l1);
                split_bf16(v.z, h2, l2); split_bf16(v.w, h3, l3);
                uint32_t* ph = (uint32_t*)&sBh[ss * YP + qq * 4];
                uint32_t* pl = (uint32_t*)&sBl[ss * YP + qq * 4];
                ph[0] = pack2h(h0, h1); ph[1] = pack2h(h2, h3);
                pl[0] = pack2h(l0, l1); pl[1] = pack2h(l2, l3);
            }
        } else {
            // S rows n=0..63: direct cp.async of bf16 hi/lo
#pragma unroll
            for (int u = 0; u < 4; u++) {
                int l = tid + u * 128;           // 0..511
                int rr = l >> 3, qq = l & 7;
                size_t src = sbase + (size_t)rr * D_V + d0 + qq * 8;
                uint32_t so = (uint32_t)(rr * YP + qq * 8) * 2;
                cp16(uBh + so, &g_Sh[src]);
                cp16(uBl + so, &g_Sl[src]);
            }
        }
        CP_COMMIT();
        CP_WAIT(0);
        __syncthreads();

        // --- compute ---
#pragma unroll
        for (int ks = 0; ks < 64; ks += 16) {
            int kc = ks + tig * 2;
            uint32_t Ah[2][4], Al[2][4], Bh[8][2], Bl[8][2];
#pragma unroll
            for (int mi = 0; mi < 2; mi++) {
                int mb = w * 32 + mi * 16 + g;
                const __nv_bfloat16* p = &sAh[mb * YP + kc];
                const __nv_bfloat16* qq = &sAl[mb * YP + kc];
                Ah[mi][0] = *(const uint32_t*)p;
                Ah[mi][1] = *(const uint32_t*)(p + 8 * YP);
                Ah[mi][2] = *(const uint32_t*)(p + 8);
                Ah[mi][3] = *(const uint32_t*)(p + 8 * YP + 8);
                Al[mi][0] = *(const uint32_t*)qq;
                Al[mi][1] = *(const uint32_t*)(qq + 8 * YP);
                Al[mi][2] = *(const uint32_t*)(qq + 8);
                Al[mi][3] = *(const uint32_t*)(qq + 8 * YP + 8);
            }
            // B frags via ldmatrix.x4.trans: matrices (k rows, d cols):
            // seg0: (ks+lq, nb) ; seg1: (ks+8+lq, nb) ; seg2: (ks+lq, nb+8) ; seg3: (ks+8+lq, nb+8)
            uint32_t row = ks + (lseg & 1) * 8 + lq;
#pragma unroll
            for (int nbs = 0; nbs < 4; nbs++) {
                uint32_t col = nbs * 16 + (lseg >> 1) * 8;
                uint32_t off = (row * YP + col) * 2;
                ldm_x4_trans(Bh[nbs * 2][0], Bh[nbs * 2][1], Bh[nbs * 2 + 1][0], Bh[nbs * 2 + 1][1], uBh + off);
                ldm_x4_trans(Bl[nbs * 2][0], Bl[nbs * 2][1], Bl[nbs * 2 + 1][0], Bl[nbs * 2 + 1][1], uBl + off);
            }
#pragma unroll
            for (int mi = 0; mi < 2; mi++)
#pragma unroll
                for (int nj = 0; nj < 8; nj++) {
                    mma_bf16(acc[mi][nj], Ah[mi], Bh[nj]);
                    mma_bf16(acc[mi][nj], Ah[mi], Bl[nj]);
                    mma_bf16(acc[mi][nj], Al[mi], Bh[nj]);
                }
        }
    }

    // --- epilogue: write Y ---
#pragma unroll
    for (int mi = 0; mi < 2; mi++) {
        int t = w * 32 + mi * 16 + g;
#pragma unroll
        for (int nj = 0; nj < 8; nj++) {
            int col = d0 + nj * 8 + tig * 2;
            float2 lo; lo.x = acc[mi][nj][0]; lo.y = acc[mi][nj][1];
            float2 hi; hi.x = acc[mi][nj][2]; hi.y = acc[mi][nj][3];
            *(float2*)&out[(size_t)((c * CHUNK + t) * BATCH + b) * D_V + col] = lo;
            *(float2*)&out[(size_t)((c * CHUNK + t + 8) * BATCH + b) * D_V + col] = hi;
        }
    }
}

// ---------------- launch ----------------
extern "C" void kernel_launch(void* const* d_in, const int* in_sizes, int n_in,
                              void* d_out, int out_size) {
    const float* x  = (const float*)d_in[0];
    const float* Wv = (const float*)d_in[1];
    const float* bv = (const float*)d_in[2];
    const float* Wk = (const float*)d_in[3];
    const float* bk = (const float*)d_in[4];
    const float* Wq = (const float*)d_in[5];
    const float* bq = (const float*)d_in[6];
    const float* Wa = (const float*)d_in[7];
    const float* ba = (const float*)d_in[8];
    float* out = (float*)d_out;

    cudaFuncSetAttribute(prep_kernel, cudaFuncAttributeMaxDynamicSharedMemorySize, PREP_SMEM);
    cudaFuncSetAttribute(gemm_mma_kernel, cudaFuncAttributeMaxDynamicSharedMemorySize, GM_SMEM);
    cudaFuncSetAttribute(ygemm_mma_kernel, cudaFuncAttributeMaxDynamicSharedMemorySize, YG_SMEM);

    pack_kernel<<<(NPROJ_P * IN_DIM + 255) / 256, 256>>>(Wv, bv, Wk, bk, Wq, bq, Wa, ba);
    convx_kernel<<<(int)(((size_t)MROWS * IN_DIM / 8) / 256), 256>>>(x);
    gemm_mma_kernel<<<dim3(NPROJ_P / 128, MROWS / 128), 256, GM_SMEM>>>();
    prep_kernel<<<dim3(BATCH, NC), 256, PREP_SMEM>>>();
    contrib_kernel<<<dim3(D_V / 128, NC, BATCH), 256>>>();
    state_scan_kernel<<<SEG / 256, 256>>>();
    ygemm_mma_kernel<<<dim3(D_V / 64, NC, BATCH), 128, YG_SMEM>>>(out);
}

// round 8
// speedup vs baseline: 2.7050x; 1.0233x over previous
#include <cuda_runtime.h>
#include <cuda_bf16.h>
#include <math.h>
#include <stdint.h>

#define T_LEN   8192
#define BATCH   4
#define IN_DIM  512
#define D_V     512
#define D_K     64
#define CHUNK   128
#define NC      (T_LEN / CHUNK)          // 64
#define NPROJ   (D_V + 3 * D_K)          // 704
#define NPROJ_P 768                      // padded to 6*128
#define MROWS   (T_LEN * BATCH)          // 32768
#define EPS_F   1e-8f
#define SEG     (BATCH * D_K * D_V)      // 131072 state elements
#define AQW     192                      // A(128) | qt(64) fused row width

// ---------------- static device scratch ----------------
__device__ __align__(128) float g_bias[NPROJ];
__device__ __align__(128) __nv_bfloat16 g_Wh[NPROJ_P * IN_DIM];
__device__ __align__(128) __nv_bfloat16 g_Wl[NPROJ_P * IN_DIM];
__device__ __align__(128) __nv_bfloat16 g_Xh[(size_t)MROWS * IN_DIM];
__device__ __align__(128) __nv_bfloat16 g_Xl[(size_t)MROWS * IN_DIM];
__device__ __align__(128) float g_proj[(size_t)MROWS * NPROJ];             // [t*B+b][704] : v|k|q|sig(a)
__device__ __align__(128) __nv_bfloat16 g_AQh[(size_t)NC * BATCH * CHUNK * AQW]; // [c][b][t][A|qt] hi
__device__ __align__(128) __nv_bfloat16 g_AQl[(size_t)NC * BATCH * CHUNK * AQW]; // lo
__device__ __align__(128) float g_kpe[(size_t)NC * BATCH * CHUNK * D_K];
__device__ __align__(128) float g_pend[NC * BATCH * D_K];
__device__ __align__(128) float g_Wc[(size_t)NC * SEG];
__device__ __align__(128) __nv_bfloat16 g_Sh[(size_t)NC * SEG];            // S_start hi [c][b][n][d]
__device__ __align__(128) __nv_bfloat16 g_Sl[(size_t)NC * SEG];            // lo

// ---------------- helpers ----------------
__device__ __forceinline__ uint32_t smem_u32(const void* p) {
    uint32_t a;
    asm("{ .reg .u64 t; cvta.to.shared.u64 t, %1; cvt.u32.u64 %0, t; }" : "=r"(a) : "l"(p));
    return a;
}
__device__ __forceinline__ void cp16(uint32_t dst, const void* src) {
    asm volatile("cp.async.cg.shared.global [%0], [%1], 16;" :: "r"(dst), "l"(src));
}
#define CP_COMMIT() asm volatile("cp.async.commit_group;")
#define CP_WAIT(n)  asm volatile("cp.async.wait_group %0;" :: "n"(n))

__device__ __forceinline__ void mma_bf16(float* c, const uint32_t* a, const uint32_t* b) {
    asm volatile(
        "mma.sync.aligned.m16n8k16.row.col.f32.bf16.bf16.f32 "
        "{%0,%1,%2,%3}, {%4,%5,%6,%7}, {%8,%9}, {%0,%1,%2,%3};"
        : "+f"(c[0]), "+f"(c[1]), "+f"(c[2]), "+f"(c[3])
        : "r"(a[0]), "r"(a[1]), "r"(a[2]), "r"(a[3]), "r"(b[0]), "r"(b[1]));
}
__device__ __forceinline__ void ldm_x4(uint32_t& r0, uint32_t& r1, uint32_t& r2, uint32_t& r3,
                                       uint32_t addr) {
    asm volatile("ldmatrix.sync.aligned.m8n8.x4.shared.b16 {%0,%1,%2,%3}, [%4];"
                 : "=r"(r0), "=r"(r1), "=r"(r2), "=r"(r3) : "r"(addr));
}
__device__ __forceinline__ void ldm_x4_trans(uint32_t& r0, uint32_t& r1, uint32_t& r2, uint32_t& r3,
                                             uint32_t addr) {
    asm volatile("ldmatrix.sync.aligned.m8n8.x4.trans.shared.b16 {%0,%1,%2,%3}, [%4];"
                 : "=r"(r0), "=r"(r1), "=r"(r2), "=r"(r3) : "r"(addr));
}
__device__ __forceinline__ uint32_t pack2h(__nv_bfloat16 a, __nv_bfloat16 b) {
    return ((uint32_t)*(uint16_t*)&b << 16) | *(uint16_t*)&a;
}
__device__ __forceinline__ void split_bf16(float v, __nv_bfloat16& h, __nv_bfloat16& l) {
    h = __float2bfloat16(v);
    l = __float2bfloat16(v - __bfloat162float(h));
}

// ---------------- kernel 0: pack weights (bf16 hi/lo) + bias ----------------
__global__ void pack_kernel(const float* __restrict__ Wv, const float* __restrict__ bv,
                            const float* __restrict__ Wk, const float* __restrict__ bk,
                            const float* __restrict__ Wq, const float* __restrict__ bq,
                            const float* __restrict__ Wa, const float* __restrict__ ba) {
    int idx = blockIdx.x * 256 + threadIdx.x;
    if (idx < NPROJ_P * IN_DIM) {
        int o = idx >> 9, i = idx & 511;
        float v = 0.f;
        if (o < 512)       v = Wv[o * IN_DIM + i];
        else if (o < 576)  v = Wk[(o - 512) * IN_DIM + i];
        else if (o < 640)  v = Wq[(o - 576) * IN_DIM + i];
        else if (o < 704)  v = Wa[(o - 640) * IN_DIM + i];
        __nv_bfloat16 h, l; split_bf16(v, h, l);
        g_Wh[idx] = h;
        g_Wl[idx] = l;
    }
    if (idx < NPROJ) {
        float v;
        if (idx < 512)      v = bv[idx];
        else if (idx < 576) v = bk[idx - 512];
        else if (idx < 640) v = bq[idx - 576];
        else                v = ba[idx - 640];
        g_bias[idx] = v;
    }
}

// ---------------- kernel 1: X -> bf16 hi/lo ----------------
__global__ void __launch_bounds__(256) convx_kernel(const float* __restrict__ X) {
    size_t e0 = ((size_t)blockIdx.x * 256 + threadIdx.x) * 8;
    float4 v0 = *(const float4*)&X[e0];
    float4 v1 = *(const float4*)&X[e0 + 4];
    float f[8] = {v0.x, v0.y, v0.z, v0.w, v1.x, v1.y, v1.z, v1.w};
    __align__(16) __nv_bfloat16 hh[8], ll[8];
#pragma unroll
    for (int i = 0; i < 8; i++) split_bf16(f[i], hh[i], ll[i]);
    *(uint4*)&g_Xh[e0] = *(uint4*)hh;
    *(uint4*)&g_Xl[e0] = *(uint4*)ll;
}

// ---------------- kernel 2: projection GEMM via HMMA bf16, cp.async 2-stage --------
#define GP 72
#define GSTAGE (4 * 128 * GP)                 // bf16 elems per stage
#define GM_SMEM (2 * GSTAGE * 2)              // bytes

__global__ void __launch_bounds__(256) gemm_mma_kernel() {
    extern __shared__ __nv_bfloat16 sm_b[];
    uint32_t sb = smem_u32(sm_b);

    int tid = threadIdx.x, wid = tid >> 5, lane = tid & 31;
    int g = lane >> 2, tig = lane & 3;
    int lq = lane & 7, lseg = lane >> 3;
    int wm = wid >> 2;               // 0..1 -> 64 rows each
    int wn = wid & 3;                // 0..3 -> 32 cols each
    int bx = blockIdx.x;             // n tile 0..5
    int m0 = blockIdx.y * 128;
    int n0 = bx * 128;
    bool active = (n0 + wn * 32 < NPROJ);   // alpha tile: warps 2,3 idle

    float acc[4][4][4];
#pragma unroll
    for (int i = 0; i < 4; i++)
#pragma unroll
        for (int j = 0; j < 4; j++)
#pragma unroll
            for (int k = 0; k < 4; k++) acc[i][j][k] = 0.f;

#define GCOPY(ch, buf) do {                                                              \
    uint32_t base = sb + (uint32_t)(buf) * (GSTAGE * 2);                                 \
    _Pragma("unroll")                                                                    \
    for (int u = 0; u < 4; u++) {                                                        \
        int l = tid + u * 256;                                                           \
        int rr = l >> 3, qq = l & 7;                                                     \
        size_t gx = (size_t)(m0 + rr) * IN_DIM + (ch) * 64 + qq * 8;                     \
        size_t gw = (size_t)(n0 + rr) * IN_DIM + (ch) * 64 + qq * 8;                     \
        uint32_t so = (uint32_t)(rr * GP + qq * 8) * 2;                                  \
        cp16(base + so,                     &g_Xh[gx]);                                  \
        cp16(base + 128 * GP * 2 + so,      &g_Xl[gx]);                                  \
        cp16(base + 2 * 128 * GP * 2 + so,  &g_Wh[gw]);                                  \
        cp16(base + 3 * 128 * GP * 2 + so,  &g_Wl[gw]);                                  \
    }                                                                                    \
} while (0)

    GCOPY(0, 0);
    CP_COMMIT();

    // A frag ldmatrix lane address parts: matrices (rows m..+8, k), (m+8, k), (m, k+8), (m+8, k+8)
    int arow = (lseg & 1) * 8 + lq;
    int asel = (lseg >> 1) * 8;
    // B frag x4 loads TWO n-frags: matrices (n..+8, k), (n..+8, k+8), (n+8, k), (n+8, k+8)
    int brow = (lseg >> 1) * 8 + lq;
    int bsel = (lseg & 1) * 8;

    for (int ch = 0; ch < 8; ch++) {
        if (ch + 1 < 8) { GCOPY(ch + 1, (ch + 1) & 1); CP_COMMIT(); }
        if (ch + 1 < 8) CP_WAIT(1); else CP_WAIT(0);
        __syncthreads();

        uint32_t uXh = sb + (uint32_t)(ch & 1) * (GSTAGE * 2);
        uint32_t uXl = uXh + 128 * GP * 2;
        uint32_t uWh = uXl + 128 * GP * 2;
        uint32_t uWl = uWh + 128 * GP * 2;

        if (active) {
#pragma unroll
            for (int ks = 0; ks < 64; ks += 16) {
                uint32_t Ah[4][4], Al[4][4], Bh[4][2], Bl[4][2];
#pragma unroll
                for (int mi = 0; mi < 4; mi++) {
                    uint32_t off = (uint32_t)((wm * 64 + mi * 16 + arow) * GP + ks + asel) * 2;
                    ldm_x4(Ah[mi][0], Ah[mi][1], Ah[mi][2], Ah[mi][3], uXh + off);
                    ldm_x4(Al[mi][0], Al[mi][1], Al[mi][2], Al[mi][3], uXl + off);
                }
#pragma unroll
                for (int njp = 0; njp < 2; njp++) {
                    uint32_t off = (uint32_t)((wn * 32 + njp * 16 + brow) * GP + ks + bsel) * 2;
                    ldm_x4(Bh[njp * 2][0], Bh[njp * 2][1], Bh[njp * 2 + 1][0], Bh[njp * 2 + 1][1], uWh + off);
                    ldm_x4(Bl[njp * 2][0], Bl[njp * 2][1], Bl[njp * 2 + 1][0], Bl[njp * 2 + 1][1], uWl + off);
                }
#pragma unroll
                for (int mi = 0; mi < 4; mi++)
#pragma unroll
                    for (int nj = 0; nj < 4; nj++) {
                        mma_bf16(acc[mi][nj], Ah[mi], Bh[nj]);
                        mma_bf16(acc[mi][nj], Ah[mi], Bl[nj]);
                        mma_bf16(acc[mi][nj], Al[mi], Bh[nj]);
                    }
            }
        }
        __syncthreads();
    }

#pragma unroll
    for (int mi = 0; mi < 4; mi++) {
        int r0 = m0 + wm * 64 + mi * 16 + g;
#pragma unroll
        for (int nj = 0; nj < 4; nj++) {
            int col = n0 + wn * 32 + nj * 8 + tig * 2;
            if (col >= NPROJ) continue;
            float b0 = g_bias[col], b1 = g_bias[col + 1];
            float v0 = acc[mi][nj][0] + b0, v1 = acc[mi][nj][1] + b1;
            float v2 = acc[mi][nj][2] + b0, v3 = acc[mi][nj][3] + b1;
            if (col >= 640) {
                v0 = 1.f / (1.f + expf(-v0));
                v1 = 1.f / (1.f + expf(-v1));
                v2 = 1.f / (1.f + expf(-v2));
                v3 = 1.f / (1.f + expf(-v3));
            }
            float2 lo; lo.x = v0; lo.y = v1;
            float2 hi; hi.x = v2; hi.y = v3;
            *(float2*)&g_proj[(size_t)r0 * NPROJ + col] = lo;
            *(float2*)&g_proj[(size_t)(r0 + 8) * NPROJ + col] = hi;
        }
    }
#undef GCOPY
}

// ---------------- kernel 3: per-chunk prep -> p, kpe(fp32), AQ(bf16 hi/lo) -------
#define PREP_SMEM (3 * 128 * 65 * 4)
__global__ void __launch_bounds__(256) prep_kernel() {
    extern __shared__ float sm[];
    float* sp  = sm;                 // [128][65] cumulative decay p
    float* sqt = sm + 128 * 65;      // [128][65] q_t
    float* skt = sm + 2 * 128 * 65;  // [128][65] k_t (also alpha temp)

    int b = blockIdx.x, c = blockIdx.y;
    int tid = threadIdx.x;
    size_t aqbase = (size_t)(c * BATCH + b) * CHUNK * AQW;

#pragma unroll
    for (int j = 0; j < 8; j++) {
        int l  = tid + j * 256;
        int t  = l >> 4;
        int c4 = (l & 15) * 4;
        const float* rowp = g_proj + (size_t)((c * CHUNK + t) * BATCH + b) * NPROJ;
        float4 av = *(const float4*)&rowp[640 + c4];
        skt[t * 65 + c4 + 0] = av.x; skt[t * 65 + c4 + 1] = av.y;
        skt[t * 65 + c4 + 2] = av.z; skt[t * 65 + c4 + 3] = av.w;
    }
    __syncthreads();

    if (tid < D_K) {
        float p = 1.f;
        for (int t = 0; t < CHUNK; t++) {
            p *= fmaxf(skt[t * 65 + tid], EPS_F);
            sp[t * 65 + tid] = p;
        }
        g_pend[(c * BATCH + b) * D_K + tid] = p;
    }
    __syncthreads();

    float* gk = g_kpe + (size_t)(c * BATCH + b) * CHUNK * D_K;
#pragma unroll
    for (int j = 0; j < 8; j++) {
        int l  = tid + j * 256;
        int t  = l >> 4;
        int c4 = (l & 15) * 4;
        const float* rowp = g_proj + (size_t)((c * CHUNK + t) * BATCH + b) * NPROJ;
        float4 qv = *(const float4*)&rowp[576 + c4];
        float4 kv = *(const float4*)&rowp[512 + c4];
        float p0 = sp[t * 65 + c4 + 0], p1 = sp[t * 65 + c4 + 1];
        float p2 = sp[t * 65 + c4 + 2], p3 = sp[t * 65 + c4 + 3];
        float pe0 = sp[127 * 65 + c4 + 0], pe1 = sp[127 * 65 + c4 + 1];
        float pe2 = sp[127 * 65 + c4 + 2], pe3 = sp[127 * 65 + c4 + 3];
        float q0 = qv.x * p0, q1 = qv.y * p1, q2 = qv.z * p2, q3 = qv.w * p3;
        float k0 = kv.x / (p0 + EPS_F), k1 = kv.y / (p1 + EPS_F);
        float k2 = kv.z / (p2 + EPS_F), k3 = kv.w / (p3 + EPS_F);
        sqt[t * 65 + c4 + 0] = q0; sqt[t * 65 + c4 + 1] = q1;
        sqt[t * 65 + c4 + 2] = q2; sqt[t * 65 + c4 + 3] = q3;
        skt[t * 65 + c4 + 0] = k0; skt[t * 65 + c4 + 1] = k1;
        skt[t * 65 + c4 + 2] = k2; skt[t * 65 + c4 + 3] = k3;
        __nv_bfloat16 h0, h1, h2, h3, l0, l1, l2, l3;
        split_bf16(q0, h0, l0); split_bf16(q1, h1, l1);
        split_bf16(q2, h2, l2); split_bf16(q3, h3, l3);
        uint32_t* ph = (uint32_t*)&g_AQh[aqbase + t * AQW + 128 + c4];
        uint32_t* pl = (uint32_t*)&g_AQl[aqbase + t * AQW + 128 + c4];
        ph[0] = pack2h(h0, h1); ph[1] = pack2h(h2, h3);
        pl[0] = pack2h(l0, l1); pl[1] = pack2h(l2, l3);
        float4 ok; ok.x = k0 * pe0; ok.y = k1 * pe1; ok.z = k2 * pe2; ok.w = k3 * pe3;
        *(float4*)&gk[t * 64 + c4] = ok;
    }
    __syncthreads();

    // A[t][s] = sum_n q_t[t][n] * k_t[s][n], masked t>=s -> bf16 hi/lo
    int sxl = tid & 15;
    int t0  = (tid >> 4) * 8;
    float acc[8][8];
#pragma unroll
    for (int i = 0; i < 8; i++)
#pragma unroll
        for (int j = 0; j < 8; j++) acc[i][j] = 0.f;

    for (int n = 0; n < D_K; n++) {
        float qv[8], kv[8];
#pragma unroll
        for (int i = 0; i < 8; i++) qv[i] = sqt[(t0 + i) * 65 + n];
#pragma unroll
        for (int j = 0; j < 8; j++) kv[j] = skt[(sxl + 16 * j) * 65 + n];
#pragma unroll
        for (int i = 0; i < 8; i++)
#pragma unroll
            for (int j = 0; j < 8; j++)
                acc[i][j] = fmaf(qv[i], kv[j], acc[i][j]);
    }
#pragma unroll
    for (int i = 0; i < 8; i++) {
        int t = t0 + i;
#pragma unroll
        for (int j = 0; j < 8; j++) {
            int s = sxl + 16 * j;
            float val = (t >= s) ? acc[i][j] : 0.f;
            __nv_bfloat16 h, l; split_bf16(val, h, l);
            g_AQh[aqbase + t * AQW + s] = h;
            g_AQl[aqbase + t * AQW + s] = l;
        }
    }
}

// ---------------- kernel 4: per-chunk state contributions W_c = v^T @ kpe ----------
__global__ void __launch_bounds__(256) contrib_kernel() {
    __shared__ float v_s[32][128];
    __shared__ float k_s[32][64];
    int d0 = blockIdx.x * 128, c = blockIdx.y, b = blockIdx.z;
    int tid = threadIdx.x;
    int tx = tid & 31;           // d group (4 each)
    int ty = tid >> 5;           // n group (8 each)

    float acc[8][4];
#pragma unroll
    for (int i = 0; i < 8; i++)
#pragma unroll
        for (int j = 0; j < 4; j++) acc[i][j] = 0.f;

    const float* kbase = g_kpe + (size_t)(c * BATCH + b) * CHUNK * D_K;

    for (int t0 = 0; t0 < CHUNK; t0 += 32) {
#pragma unroll
        for (int j = 0; j < 4; j++) {
            int l  = tid + j * 256;
            int tt = l >> 5;
            int c4 = (l & 31) * 4;
            float4 v = *(const float4*)&g_proj[(size_t)((c * CHUNK + t0 + tt) * BATCH + b) * NPROJ + d0 + c4];
            *(float4*)&v_s[tt][c4] = v;
        }
#pragma unroll
        for (int j = 0; j < 2; j++) {
            int l  = tid + j * 256;
            int tt = l >> 4;
            int c4 = (l & 15) * 4;
            float4 v = *(const float4*)&kbase[(t0 + tt) * D_K + c4];
            *(float4*)&k_s[tt][c4] = v;
        }
        __syncthreads();
#pragma unroll
        for (int t = 0; t < 32; t++) {
            float4 vv = *(const float4*)&v_s[t][tx * 4];
            float4 k0v = *(const float4*)&k_s[t][ty * 8];
            float4 k1v = *(const float4*)&k_s[t][ty * 8 + 4];
            float kn[8] = {k0v.x, k0v.y, k0v.z, k0v.w, k1v.x, k1v.y, k1v.z, k1v.w};
#pragma unroll
            for (int i = 0; i < 8; i++) {
                acc[i][0] = fmaf(kn[i], vv.x, acc[i][0]);
                acc[i][1] = fmaf(kn[i], vv.y, acc[i][1]);
                acc[i][2] = fmaf(kn[i], vv.z, acc[i][2]);
                acc[i][3] = fmaf(kn[i], vv.w, acc[i][3]);
            }
        }
        __syncthreads();
    }
#pragma unroll
    for (int i = 0; i < 8; i++) {
        float4 o; o.x = acc[i][0]; o.y = acc[i][1]; o.z = acc[i][2]; o.w = acc[i][3];
        *(float4*)&g_Wc[(size_t)((c * BATCH + b) * D_K + ty * 8 + i) * D_V + d0 + tx * 4] = o;
    }
}

// ---------------- kernel 5: elementwise state scan; emit S_start bf16 hi/lo -------
__global__ void __launch_bounds__(256) state_scan_kernel() {
    int g = blockIdx.x * 256 + threadIdx.x;  // g = (b*64+n)*512 + d
    int bn = g >> 9;
    float s = 0.f;
    for (int c = 0; c < NC; c++) {
        size_t idx = (size_t)c * SEG + g;
        __nv_bfloat16 h, l; split_bf16(s, h, l);
        g_Sh[idx] = h;
        g_Sl[idx] = l;
        s = fmaf(s, g_pend[c * (BATCH * D_K) + bn], g_Wc[idx]);
    }
}

// ---------------- kernel 6: Y = [A | q_t] @ [V ; S] via HMMA, ldmatrix both ops ----
#define YP 72
#define YG_SMEM ((2 * 128 * YP + 2 * 64 * YP) * 2)

__global__ void __launch_bounds__(128) ygemm_mma_kernel(float* __restrict__ out) {
    extern __shared__ __nv_bfloat16 ysm[];
    __nv_bfloat16* sAh = ysm;                    // [128][YP]
    __nv_bfloat16* sAl = sAh + 128 * YP;
    __nv_bfloat16* sBh = sAl + 128 * YP;         // [64 k][YP d]
    __nv_bfloat16* sBl = sBh + 64 * YP;
    uint32_t uAh = smem_u32(sAh), uAl = smem_u32(sAl);
    uint32_t uBh = smem_u32(sBh), uBl = smem_u32(sBl);

    int d0 = blockIdx.x * 64;
    int c = blockIdx.y, b = blockIdx.z;
    int tid = threadIdx.x, w = tid >> 5, lane = tid & 31;
    int g = lane >> 2, tig = lane & 3;
    int lq = lane & 7, lseg = lane >> 3;
    int arow = (lseg & 1) * 8 + lq;
    int asel = (lseg >> 1) * 8;

    size_t aqbase = (size_t)(c * BATCH + b) * CHUNK * AQW;
    size_t sbase  = (size_t)(c * BATCH + b) * D_K * D_V;

    float acc[2][8][4];
#pragma unroll
    for (int i = 0; i < 2; i++)
#pragma unroll
        for (int j = 0; j < 8; j++)
#pragma unroll
            for (int k = 0; k < 4; k++) acc[i][j][k] = 0.f;

    for (int ch = 0; ch < 3; ch++) {
        __syncthreads();
        // --- A staging: cp.async 128 rows x 64 bf16 (hi+lo) ---
#pragma unroll
        for (int u = 0; u < 8; u++) {
            int l = tid + u * 128;               // 0..1023
            int rr = l >> 3, qq = l & 7;
            size_t src = aqbase + rr * AQW + ch * 64 + qq * 8;
            uint32_t so = (uint32_t)(rr * YP + qq * 8) * 2;
            cp16(uAh + so, &g_AQh[src]);
            cp16(uAl + so, &g_AQl[src]);
        }
        // --- B staging ---
        if (ch < 2) {
#pragma unroll
            for (int u = 0; u < 8; u++) {
                int l = tid + u * 128;           // 0..1023 float4 ids
                int ss = l >> 4, qq = l & 15;
                float4 v = *(const float4*)&g_proj[(size_t)((c * CHUNK + ch * 64 + ss) * BATCH + b) * NPROJ + d0 + qq * 4];
                __nv_bfloat16 h0, h1, h2, h3, l0, l1, l2, l3;
                split_bf16(v.x, h0, l0); split_bf16(v.y, h1, l1);
                split_bf16(v.z, h2, l2); split_bf16(v.w, h3, l3);
                uint32_t* ph = (uint32_t*)&sBh[ss * YP + qq * 4];
                uint32_t* pl = (uint32_t*)&sBl[ss * YP + qq * 4];
                ph[0] = pack2h(h0, h1); ph[1] = pack2h(h2, h3);
                pl[0] = pack2h(l0, l1); pl[1] = pack2h(l2, l3);
            }
        } else {
#pragma unroll
            for (int u = 0; u < 4; u++) {
                int l = tid + u * 128;           // 0..511
                int rr = l >> 3, qq = l & 7;
                size_t src = sbase + (size_t)rr * D_V + d0 + qq * 8;
                uint32_t so = (uint32_t)(rr * YP + qq * 8) * 2;
                cp16(uBh + so, &g_Sh[src]);
                cp16(uBl + so, &g_Sl[src]);
            }
        }
        CP_COMMIT();
        CP_WAIT(0);
        __syncthreads();

        // --- compute ---
#pragma unroll
        for (int ks = 0; ks < 64; ks += 16) {
            uint32_t Ah[2][4], Al[2][4], Bh[8][2], Bl[8][2];
#pragma unroll
            for (int mi = 0; mi < 2; mi++) {
                uint32_t off = (uint32_t)((w * 32 + mi * 16 + arow) * YP + ks + asel) * 2;
                ldm_x4(Ah[mi][0], Ah[mi][1], Ah[mi][2], Ah[mi][3], uAh + off);
                ldm_x4(Al[mi][0], Al[mi][1], Al[mi][2], Al[mi][3], uAl + off);
            }
            // B frags via ldmatrix.x4.trans from [k][d] layout
            uint32_t row = ks + (lseg & 1) * 8 + lq;
#pragma unroll
            for (int nbs = 0; nbs < 4; nbs++) {
                uint32_t col = nbs * 16 + (lseg >> 1) * 8;
                uint32_t off = (row * YP + col) * 2;
                ldm_x4_trans(Bh[nbs * 2][0], Bh[nbs * 2][1], Bh[nbs * 2 + 1][0], Bh[nbs * 2 + 1][1], uBh + off);
                ldm_x4_trans(Bl[nbs * 2][0], Bl[nbs * 2][1], Bl[nbs * 2 + 1][0], Bl[nbs * 2 + 1][1], uBl + off);
            }
#pragma unroll
            for (int mi = 0; mi < 2; mi++)
#pragma unroll
                for (int nj = 0; nj < 8; nj++) {
                    mma_bf16(acc[mi][nj], Ah[mi], Bh[nj]);
                    mma_bf16(acc[mi][nj], Ah[mi], Bl[nj]);
                    mma_bf16(acc[mi][nj], Al[mi], Bh[nj]);
                }
        }
    }

    // --- epilogue: write Y ---
#pragma unroll
    for (int mi = 0; mi < 2; mi++) {
        int t = w * 32 + mi * 16 + g;
#pragma unroll
        for (int nj = 0; nj < 8; nj++) {
            int col = d0 + nj * 8 + tig * 2;
            float2 lo; lo.x = acc[mi][nj][0]; lo.y = acc[mi][nj][1];
            float2 hi; hi.x = acc[mi][nj][2]; hi.y = acc[mi][nj][3];
            *(float2*)&out[(size_t)((c * CHUNK + t) * BATCH + b) * D_V + col] = lo;
            *(float2*)&out[(size_t)((c * CHUNK + t + 8) * BATCH + b) * D_V + col] = hi;
        }
    }
}

// ---------------- launch ----------------
extern "C" void kernel_launch(void* const* d_in, const int* in_sizes, int n_in,
                              void* d_out, int out_size) {
    const float* x  = (const float*)d_in[0];
    const float* Wv = (const float*)d_in[1];
    const float* bv = (const float*)d_in[2];
    const float* Wk = (const float*)d_in[3];
    const float* bk = (const float*)d_in[4];
    const float* Wq = (const float*)d_in[5];
    const float* bq = (const float*)d_in[6];
    const float* Wa = (const float*)d_in[7];
    const float* ba = (const float*)d_in[8];
    float* out = (float*)d_out;

    cudaFuncSetAttribute(prep_kernel, cudaFuncAttributeMaxDynamicSharedMemorySize, PREP_SMEM);
    cudaFuncSetAttribute(gemm_mma_kernel, cudaFuncAttributeMaxDynamicSharedMemorySize, GM_SMEM);
    cudaFuncSetAttribute(ygemm_mma_kernel, cudaFuncAttributeMaxDynamicSharedMemorySize, YG_SMEM);

    pack_kernel<<<(NPROJ_P * IN_DIM + 255) / 256, 256>>>(Wv, bv, Wk, bk, Wq, bq, Wa, ba);
    convx_kernel<<<(int)(((size_t)MROWS * IN_DIM / 8) / 256), 256>>>(x);
    gemm_mma_kernel<<<dim3(NPROJ_P / 128, MROWS / 128), 256, GM_SMEM>>>();
    prep_kernel<<<dim3(BATCH, NC), 256, PREP_SMEM>>>();
    contrib_kernel<<<dim3(D_V / 128, NC, BATCH), 256>>>();
    state_scan_kernel<<<SEG / 256, 256>>>();
    ygemm_mma_kernel<<<dim3(D_V / 64, NC, BATCH), 128, YG_SMEM>>>(out);
}

// round 9
// speedup vs baseline: 2.7667x; 1.0228x over previous
#include <cuda_runtime.h>
#include <cuda_bf16.h>
#include <math.h>
#include <stdint.h>

#define T_LEN   8192
#define BATCH   4
#define IN_DIM  512
#define D_V     512
#define D_K     64
#define CHUNK   128
#define NC      (T_LEN / CHUNK)          // 64
#define NPROJ   (D_V + 3 * D_K)          // 704
#define NPROJ_P 768                      // padded to 6*128
#define MROWS   (T_LEN * BATCH)          // 32768
#define EPS_F   1e-8f
#define SEG     (BATCH * D_K * D_V)      // 131072 state elements
#define AQW     192                      // A(128) | qt(64) fused row width

// ---------------- static device scratch ----------------
__device__ __align__(128) float g_bias[NPROJ];
__device__ __align__(128) __nv_bfloat16 g_Wh[NPROJ_P * IN_DIM];
__device__ __align__(128) __nv_bfloat16 g_Wl[NPROJ_P * IN_DIM];
__device__ __align__(128) __nv_bfloat16 g_Xh[(size_t)MROWS * IN_DIM];
__device__ __align__(128) __nv_bfloat16 g_Xl[(size_t)MROWS * IN_DIM];
__device__ __align__(128) float g_proj[(size_t)MROWS * NPROJ];             // [t*B+b][704] : v|k|q|sig(a)
__device__ __align__(128) __nv_bfloat16 g_Vh[(size_t)MROWS * D_V];         // v bf16 hi [r][512]
__device__ __align__(128) __nv_bfloat16 g_Vl[(size_t)MROWS * D_V];         // lo
__device__ __align__(128) __nv_bfloat16 g_AQh[(size_t)NC * BATCH * CHUNK * AQW]; // [c][b][t][A|qt] hi
__device__ __align__(128) __nv_bfloat16 g_AQl[(size_t)NC * BATCH * CHUNK * AQW]; // lo
__device__ __align__(128) __nv_bfloat16 g_kpeh[(size_t)NC * BATCH * CHUNK * D_K];
__device__ __align__(128) __nv_bfloat16 g_kpel[(size_t)NC * BATCH * CHUNK * D_K];
__device__ __align__(128) float g_pend[NC * BATCH * D_K];
__device__ __align__(128) float g_Wc[(size_t)NC * SEG];
__device__ __align__(128) __nv_bfloat16 g_Sh[(size_t)NC * SEG];            // S_start hi [c][b][n][d]
__device__ __align__(128) __nv_bfloat16 g_Sl[(size_t)NC * SEG];            // lo

// ---------------- helpers ----------------
__device__ __forceinline__ uint32_t smem_u32(const void* p) {
    uint32_t a;
    asm("{ .reg .u64 t; cvta.to.shared.u64 t, %1; cvt.u32.u64 %0, t; }" : "=r"(a) : "l"(p));
    return a;
}
__device__ __forceinline__ void cp16(uint32_t dst, const void* src) {
    asm volatile("cp.async.cg.shared.global [%0], [%1], 16;" :: "r"(dst), "l"(src));
}
#define CP_COMMIT() asm volatile("cp.async.commit_group;")
#define CP_WAIT(n)  asm volatile("cp.async.wait_group %0;" :: "n"(n))

__device__ __forceinline__ void mma_bf16(float* c, const uint32_t* a, const uint32_t* b) {
    asm volatile(
        "mma.sync.aligned.m16n8k16.row.col.f32.bf16.bf16.f32 "
        "{%0,%1,%2,%3}, {%4,%5,%6,%7}, {%8,%9}, {%0,%1,%2,%3};"
        : "+f"(c[0]), "+f"(c[1]), "+f"(c[2]), "+f"(c[3])
        : "r"(a[0]), "r"(a[1]), "r"(a[2]), "r"(a[3]), "r"(b[0]), "r"(b[1]));
}
__device__ __forceinline__ void ldm_x4(uint32_t& r0, uint32_t& r1, uint32_t& r2, uint32_t& r3,
                                       uint32_t addr) {
    asm volatile("ldmatrix.sync.aligned.m8n8.x4.shared.b16 {%0,%1,%2,%3}, [%4];"
                 : "=r"(r0), "=r"(r1), "=r"(r2), "=r"(r3) : "r"(addr));
}
__device__ __forceinline__ void ldm_x4_trans(uint32_t& r0, uint32_t& r1, uint32_t& r2, uint32_t& r3,
                                             uint32_t addr) {
    asm volatile("ldmatrix.sync.aligned.m8n8.x4.trans.shared.b16 {%0,%1,%2,%3}, [%4];"
                 : "=r"(r0), "=r"(r1), "=r"(r2), "=r"(r3) : "r"(addr));
}
__device__ __forceinline__ uint32_t pack2h(__nv_bfloat16 a, __nv_bfloat16 b) {
    return ((uint32_t)*(uint16_t*)&b << 16) | *(uint16_t*)&a;
}
__device__ __forceinline__ void split_bf16(float v, __nv_bfloat16& h, __nv_bfloat16& l) {
    h = __float2bfloat16(v);
    l = __float2bfloat16(v - __bfloat162float(h));
}

// ---------------- kernel 0: pack weights (bf16 hi/lo) + bias ----------------
__global__ void pack_kernel(const float* __restrict__ Wv, const float* __restrict__ bv,
                            const float* __restrict__ Wk, const float* __restrict__ bk,
                            const float* __restrict__ Wq, const float* __restrict__ bq,
                            const float* __restrict__ Wa, const float* __restrict__ ba) {
    int idx = blockIdx.x * 256 + threadIdx.x;
    if (idx < NPROJ_P * IN_DIM) {
        int o = idx >> 9, i = idx & 511;
        float v = 0.f;
        if (o < 512)       v = Wv[o * IN_DIM + i];
        else if (o < 576)  v = Wk[(o - 512) * IN_DIM + i];
        else if (o < 640)  v = Wq[(o - 576) * IN_DIM + i];
        else if (o < 704)  v = Wa[(o - 640) * IN_DIM + i];
        __nv_bfloat16 h, l; split_bf16(v, h, l);
        g_Wh[idx] = h;
        g_Wl[idx] = l;
    }
    if (idx < NPROJ) {
        float v;
        if (idx < 512)      v = bv[idx];
        else if (idx < 576) v = bk[idx - 512];
        else if (idx < 640) v = bq[idx - 576];
        else                v = ba[idx - 640];
        g_bias[idx] = v;
    }
}

// ---------------- kernel 1: X -> bf16 hi/lo ----------------
__global__ void __launch_bounds__(256) convx_kernel(const float* __restrict__ X) {
    size_t e0 = ((size_t)blockIdx.x * 256 + threadIdx.x) * 8;
    float4 v0 = *(const float4*)&X[e0];
    float4 v1 = *(const float4*)&X[e0 + 4];
    float f[8] = {v0.x, v0.y, v0.z, v0.w, v1.x, v1.y, v1.z, v1.w};
    __align__(16) __nv_bfloat16 hh[8], ll[8];
#pragma unroll
    for (int i = 0; i < 8; i++) split_bf16(f[i], hh[i], ll[i]);
    *(uint4*)&g_Xh[e0] = *(uint4*)hh;
    *(uint4*)&g_Xl[e0] = *(uint4*)ll;
}

// ---------------- kernel 2: projection GEMM via HMMA bf16, cp.async 2-stage --------
#define GP 72
#define GSTAGE (4 * 128 * GP)                 // bf16 elems per stage
#define GM_SMEM (2 * GSTAGE * 2)              // bytes

__global__ void __launch_bounds__(256) gemm_mma_kernel() {
    extern __shared__ __nv_bfloat16 sm_b[];
    uint32_t sb = smem_u32(sm_b);

    int tid = threadIdx.x, wid = tid >> 5, lane = tid & 31;
    int g = lane >> 2, tig = lane & 3;
    int lq = lane & 7, lseg = lane >> 3;
    int wm = wid >> 2;               // 0..1 -> 64 rows each
    int wn = wid & 3;                // 0..3 -> 32 cols each
    int bx = blockIdx.x;             // n tile 0..5
    int m0 = blockIdx.y * 128;
    int n0 = bx * 128;
    bool active = (n0 + wn * 32 < NPROJ);   // alpha tile: warps 2,3 idle

    float acc[4][4][4];
#pragma unroll
    for (int i = 0; i < 4; i++)
#pragma unroll
        for (int j = 0; j < 4; j++)
#pragma unroll
            for (int k = 0; k < 4; k++) acc[i][j][k] = 0.f;

#define GCOPY(ch, buf) do {                                                              \
    uint32_t base = sb + (uint32_t)(buf) * (GSTAGE * 2);                                 \
    _Pragma("unroll")                                                                    \
    for (int u = 0; u < 4; u++) {                                                        \
        int l = tid + u * 256;                                                           \
        int rr = l >> 3, qq = l & 7;                                                     \
        size_t gx = (size_t)(m0 + rr) * IN_DIM + (ch) * 64 + qq * 8;                     \
        size_t gw = (size_t)(n0 + rr) * IN_DIM + (ch) * 64 + qq * 8;                     \
        uint32_t so = (uint32_t)(rr * GP + qq * 8) * 2;                                  \
        cp16(base + so,                     &g_Xh[gx]);                                  \
        cp16(base + 128 * GP * 2 + so,      &g_Xl[gx]);                                  \
        cp16(base + 2 * 128 * GP * 2 + so,  &g_Wh[gw]);                                  \
        cp16(base + 3 * 128 * GP * 2 + so,  &g_Wl[gw]);                                  \
    }                                                                                    \
} while (0)

    GCOPY(0, 0);
    CP_COMMIT();

    int arow = (lseg & 1) * 8 + lq;
    int asel = (lseg >> 1) * 8;
    int brow = (lseg >> 1) * 8 + lq;
    int bsel = (lseg & 1) * 8;

    for (int ch = 0; ch < 8; ch++) {
        if (ch + 1 < 8) { GCOPY(ch + 1, (ch + 1) & 1); CP_COMMIT(); }
        if (ch + 1 < 8) CP_WAIT(1); else CP_WAIT(0);
        __syncthreads();

        uint32_t uXh = sb + (uint32_t)(ch & 1) * (GSTAGE * 2);
        uint32_t uXl = uXh + 128 * GP * 2;
        uint32_t uWh = uXl + 128 * GP * 2;
        uint32_t uWl = uWh + 128 * GP * 2;

        if (active) {
#pragma unroll
            for (int ks = 0; ks < 64; ks += 16) {
                uint32_t Ah[4][4], Al[4][4], Bh[4][2], Bl[4][2];
#pragma unroll
                for (int mi = 0; mi < 4; mi++) {
                    uint32_t off = (uint32_t)((wm * 64 + mi * 16 + arow) * GP + ks + asel) * 2;
                    ldm_x4(Ah[mi][0], Ah[mi][1], Ah[mi][2], Ah[mi][3], uXh + off);
                    ldm_x4(Al[mi][0], Al[mi][1], Al[mi][2], Al[mi][3], uXl + off);
                }
#pragma unroll
                for (int njp = 0; njp < 2; njp++) {
                    uint32_t off = (uint32_t)((wn * 32 + njp * 16 + brow) * GP + ks + bsel) * 2;
                    ldm_x4(Bh[njp * 2][0], Bh[njp * 2][1], Bh[njp * 2 + 1][0], Bh[njp * 2 + 1][1], uWh + off);
                    ldm_x4(Bl[njp * 2][0], Bl[njp * 2][1], Bl[njp * 2 + 1][0], Bl[njp * 2 + 1][1], uWl + off);
                }
#pragma unroll
                for (int mi = 0; mi < 4; mi++)
#pragma unroll
                    for (int nj = 0; nj < 4; nj++) {
                        mma_bf16(acc[mi][nj], Ah[mi], Bh[nj]);
                        mma_bf16(acc[mi][nj], Ah[mi], Bl[nj]);
                        mma_bf16(acc[mi][nj], Al[mi], Bh[nj]);
                    }
            }
        }
        __syncthreads();
    }

#pragma unroll
    for (int mi = 0; mi < 4; mi++) {
        int r0 = m0 + wm * 64 + mi * 16 + g;
#pragma unroll
        for (int nj = 0; nj < 4; nj++) {
            int col = n0 + wn * 32 + nj * 8 + tig * 2;
            if (col >= NPROJ) continue;
            float b0 = g_bias[col], b1 = g_bias[col + 1];
            float v0 = acc[mi][nj][0] + b0, v1 = acc[mi][nj][1] + b1;
            float v2 = acc[mi][nj][2] + b0, v3 = acc[mi][nj][3] + b1;
            if (col >= 640) {
                v0 = 1.f / (1.f + expf(-v0));
                v1 = 1.f / (1.f + expf(-v1));
                v2 = 1.f / (1.f + expf(-v2));
                v3 = 1.f / (1.f + expf(-v3));
            }
            float2 lo; lo.x = v0; lo.y = v1;
            float2 hi; hi.x = v2; hi.y = v3;
            *(float2*)&g_proj[(size_t)r0 * NPROJ + col] = lo;
            *(float2*)&g_proj[(size_t)(r0 + 8) * NPROJ + col] = hi;
            if (col < 512) {   // v cols: also store bf16 hi/lo for downstream HMMA
                __nv_bfloat16 h0, h1, h2, h3, l0, l1, l2, l3;
                split_bf16(v0, h0, l0); split_bf16(v1, h1, l1);
                split_bf16(v2, h2, l2); split_bf16(v3, h3, l3);
                *(uint32_t*)&g_Vh[(size_t)r0 * D_V + col]       = pack2h(h0, h1);
                *(uint32_t*)&g_Vl[(size_t)r0 * D_V + col]       = pack2h(l0, l1);
                *(uint32_t*)&g_Vh[(size_t)(r0 + 8) * D_V + col] = pack2h(h2, h3);
                *(uint32_t*)&g_Vl[(size_t)(r0 + 8) * D_V + col] = pack2h(l2, l3);
            }
        }
    }
#undef GCOPY
}

// ---------------- kernel 3: per-chunk prep -> p, kpe(bf16 hi/lo), AQ(bf16 hi/lo) --
#define PREP_SMEM (3 * 128 * 65 * 4)
__global__ void __launch_bounds__(256) prep_kernel() {
    extern __shared__ float sm[];
    float* sp  = sm;                 // [128][65] cumulative decay p
    float* sqt = sm + 128 * 65;      // [128][65] q_t
    float* skt = sm + 2 * 128 * 65;  // [128][65] k_t (also alpha temp)

    int b = blockIdx.x, c = blockIdx.y;
    int tid = threadIdx.x;
    size_t aqbase = (size_t)(c * BATCH + b) * CHUNK * AQW;
    size_t kbase  = (size_t)(c * BATCH + b) * CHUNK * D_K;

#pragma unroll
    for (int j = 0; j < 8; j++) {
        int l  = tid + j * 256;
        int t  = l >> 4;
        int c4 = (l & 15) * 4;
        const float* rowp = g_proj + (size_t)((c * CHUNK + t) * BATCH + b) * NPROJ;
        float4 av = *(const float4*)&rowp[640 + c4];
        skt[t * 65 + c4 + 0] = av.x; skt[t * 65 + c4 + 1] = av.y;
        skt[t * 65 + c4 + 2] = av.z; skt[t * 65 + c4 + 3] = av.w;
    }
    __syncthreads();

    if (tid < D_K) {
        float p = 1.f;
        for (int t = 0; t < CHUNK; t++) {
            p *= fmaxf(skt[t * 65 + tid], EPS_F);
            sp[t * 65 + tid] = p;
        }
        g_pend[(c * BATCH + b) * D_K + tid] = p;
    }
    __syncthreads();

#pragma unroll
    for (int j = 0; j < 8; j++) {
        int l  = tid + j * 256;
        int t  = l >> 4;
        int c4 = (l & 15) * 4;
        const float* rowp = g_proj + (size_t)((c * CHUNK + t) * BATCH + b) * NPROJ;
        float4 qv = *(const float4*)&rowp[576 + c4];
        float4 kv = *(const float4*)&rowp[512 + c4];
        float p0 = sp[t * 65 + c4 + 0], p1 = sp[t * 65 + c4 + 1];
        float p2 = sp[t * 65 + c4 + 2], p3 = sp[t * 65 + c4 + 3];
        float pe0 = sp[127 * 65 + c4 + 0], pe1 = sp[127 * 65 + c4 + 1];
        float pe2 = sp[127 * 65 + c4 + 2], pe3 = sp[127 * 65 + c4 + 3];
        float q0 = qv.x * p0, q1 = qv.y * p1, q2 = qv.z * p2, q3 = qv.w * p3;
        float k0 = kv.x / (p0 + EPS_F), k1 = kv.y / (p1 + EPS_F);
        float k2 = kv.z / (p2 + EPS_F), k3 = kv.w / (p3 + EPS_F);
        sqt[t * 65 + c4 + 0] = q0; sqt[t * 65 + c4 + 1] = q1;
        sqt[t * 65 + c4 + 2] = q2; sqt[t * 65 + c4 + 3] = q3;
        skt[t * 65 + c4 + 0] = k0; skt[t * 65 + c4 + 1] = k1;
        skt[t * 65 + c4 + 2] = k2; skt[t * 65 + c4 + 3] = k3;
        __nv_bfloat16 h0, h1, h2, h3, l0, l1, l2, l3;
        split_bf16(q0, h0, l0); split_bf16(q1, h1, l1);
        split_bf16(q2, h2, l2); split_bf16(q3, h3, l3);
        uint32_t* ph = (uint32_t*)&g_AQh[aqbase + t * AQW + 128 + c4];
        uint32_t* pl = (uint32_t*)&g_AQl[aqbase + t * AQW + 128 + c4];
        ph[0] = pack2h(h0, h1); ph[1] = pack2h(h2, h3);
        pl[0] = pack2h(l0, l1); pl[1] = pack2h(l2, l3);
        // kpe -> bf16 hi/lo
        split_bf16(k0 * pe0, h0, l0); split_bf16(k1 * pe1, h1, l1);
        split_bf16(k2 * pe2, h2, l2); split_bf16(k3 * pe3, h3, l3);
        uint32_t* kh = (uint32_t*)&g_kpeh[kbase + t * D_K + c4];
        uint32_t* kl = (uint32_t*)&g_kpel[kbase + t * D_K + c4];
        kh[0] = pack2h(h0, h1); kh[1] = pack2h(h2, h3);
        kl[0] = pack2h(l0, l1); kl[1] = pack2h(l2, l3);
    }
    __syncthreads();

    // A[t][s] = sum_n q_t[t][n] * k_t[s][n], masked t>=s -> bf16 hi/lo
    int sxl = tid & 15;
    int t0  = (tid >> 4) * 8;
    float acc[8][8];
#pragma unroll
    for (int i = 0; i < 8; i++)
#pragma unroll
        for (int j = 0; j < 8; j++) acc[i][j] = 0.f;

    for (int n = 0; n < D_K; n++) {
        float qv[8], kv[8];
#pragma unroll
        for (int i = 0; i < 8; i++) qv[i] = sqt[(t0 + i) * 65 + n];
#pragma unroll
        for (int j = 0; j < 8; j++) kv[j] = skt[(sxl + 16 * j) * 65 + n];
#pragma unroll
        for (int i = 0; i < 8; i++)
#pragma unroll
            for (int j = 0; j < 8; j++)
                acc[i][j] = fmaf(qv[i], kv[j], acc[i][j]);
    }
#pragma unroll
    for (int i = 0; i < 8; i++) {
        int t = t0 + i;
#pragma unroll
        for (int j = 0; j < 8; j++) {
            int s = sxl + 16 * j;
            float val = (t >= s) ? acc[i][j] : 0.f;
            __nv_bfloat16 h, l; split_bf16(val, h, l);
            g_AQh[aqbase + t * AQW + s] = h;
            g_AQl[aqbase + t * AQW + s] = l;
        }
    }
}

// ---------------- kernel 4: contrib via HMMA: Wc[n][d] = kpe^T @ v ----------------
// block: 64 n x 64 d for one (c,b); k = t = 128, single staging + 8 ksteps.
#define CPP 72
#define CM_SMEM (4 * 128 * CPP * 2)

__global__ void __launch_bounds__(256) contrib_kernel() {
    extern __shared__ __nv_bfloat16 csm[];
    uint32_t uKh = smem_u32(csm);
    uint32_t uKl = uKh + 128 * CPP * 2;
    uint32_t uVh = uKl + 128 * CPP * 2;
    uint32_t uVl = uVh + 128 * CPP * 2;

    int d0 = blockIdx.x * 64, c = blockIdx.y, b = blockIdx.z;
    int tid = threadIdx.x, wid = tid >> 5, lane = tid & 31;
    int g = lane >> 2, tig = lane & 3;
    int lq = lane & 7, lseg = lane >> 3;
    int wn = wid & 1;                // n half: 32 rows
    int wd = wid >> 1;               // d quarter: 16 cols

    size_t kbase = (size_t)(c * BATCH + b) * CHUNK * D_K;

    // stage kpe [128][64] and v [128][64] (hi+lo)
#pragma unroll
    for (int u = 0; u < 4; u++) {
        int l = tid + u * 256;       // 0..1023
        int rr = l >> 3, qq = l & 7;
        uint32_t so = (uint32_t)(rr * CPP + qq * 8) * 2;
        cp16(uKh + so, &g_kpeh[kbase + rr * D_K + qq * 8]);
        cp16(uKl + so, &g_kpel[kbase + rr * D_K + qq * 8]);
        size_t vs = (size_t)((c * CHUNK + rr) * BATCH + b) * D_V + d0 + qq * 8;
        cp16(uVh + so, &g_Vh[vs]);
        cp16(uVl + so, &g_Vl[vs]);
    }
    CP_COMMIT();
    CP_WAIT(0);
    __syncthreads();

    float acc[2][2][4];
#pragma unroll
    for (int i = 0; i < 2; i++)
#pragma unroll
        for (int j = 0; j < 2; j++)
#pragma unroll
            for (int k = 0; k < 4; k++) acc[i][j][k] = 0.f;

#pragma unroll
    for (int ks = 0; ks < 128; ks += 16) {
        uint32_t Ah[2][4], Al[2][4], Bh[2][2], Bl[2][2];
        // A (m=n dim) via trans from [t][n]: row = ks + (lseg>>1)*8 + lq ; col = m0 + (lseg&1)*8
        uint32_t arow = ks + (lseg >> 1) * 8 + lq;
#pragma unroll
        for (int mi = 0; mi < 2; mi++) {
            uint32_t col = wn * 32 + mi * 16 + (lseg & 1) * 8;
            uint32_t off = (arow * CPP + col) * 2;
            ldm_x4_trans(Ah[mi][0], Ah[mi][1], Ah[mi][2], Ah[mi][3], uKh + off);
            ldm_x4_trans(Al[mi][0], Al[mi][1], Al[mi][2], Al[mi][3], uKl + off);
        }
        // B (n=d dim) via trans from [t][d]: row = ks + (lseg&1)*8 + lq ; col = d + (lseg>>1)*8
        {
            uint32_t brow = ks + (lseg & 1) * 8 + lq;
            uint32_t col = wd * 16 + (lseg >> 1) * 8;
            uint32_t off = (brow * CPP + col) * 2;
            ldm_x4_trans(Bh[0][0], Bh[0][1], Bh[1][0], Bh[1][1], uVh + off);
            ldm_x4_trans(Bl[0][0], Bl[0][1], Bl[1][0], Bl[1][1], uVl + off);
        }
#pragma unroll
        for (int mi = 0; mi < 2; mi++)
#pragma unroll
            for (int nj = 0; nj < 2; nj++) {
                mma_bf16(acc[mi][nj], Ah[mi], Bh[nj]);
                mma_bf16(acc[mi][nj], Ah[mi], Bl[nj]);
                mma_bf16(acc[mi][nj], Al[mi], Bh[nj]);
            }
    }

    // write Wc[n][d] fp32
    float* Wb = g_Wc + (size_t)(c * BATCH + b) * D_K * D_V;
#pragma unroll
    for (int mi = 0; mi < 2; mi++) {
        int n = wn * 32 + mi * 16 + g;
#pragma unroll
        for (int nj = 0; nj < 2; nj++) {
            int d = d0 + wd * 16 + nj * 8 + tig * 2;
            float2 lo; lo.x = acc[mi][nj][0]; lo.y = acc[mi][nj][1];
            float2 hi; hi.x = acc[mi][nj][2]; hi.y = acc[mi][nj][3];
            *(float2*)&Wb[(size_t)n * D_V + d] = lo;
            *(float2*)&Wb[(size_t)(n + 8) * D_V + d] = hi;
        }
    }
}

// ---------------- kernel 5: elementwise state scan; emit S_start bf16 hi/lo -------
__global__ void __launch_bounds__(256) state_scan_kernel() {
    int g = blockIdx.x * 256 + threadIdx.x;  // g = (b*64+n)*512 + d
    int bn = g >> 9;
    float s = 0.f;
    for (int c = 0; c < NC; c++) {
        size_t idx = (size_t)c * SEG + g;
        __nv_bfloat16 h, l; split_bf16(s, h, l);
        g_Sh[idx] = h;
        g_Sl[idx] = l;
        s = fmaf(s, g_pend[c * (BATCH * D_K) + bn], g_Wc[idx]);
    }
}

// ---------------- kernel 6: Y = [A | q_t] @ [V ; S] via HMMA, all-cp.async staging -
#define YP 72
#define YG_SMEM ((2 * 128 * YP + 2 * 64 * YP) * 2)

__global__ void __launch_bounds__(128) ygemm_mma_kernel(float* __restrict__ out) {
    extern __shared__ __nv_bfloat16 ysm[];
    __nv_bfloat16* sAh = ysm;                    // [128][YP]
    __nv_bfloat16* sAl = sAh + 128 * YP;
    __nv_bfloat16* sBh = sAl + 128 * YP;         // [64 k][YP d]
    __nv_bfloat16* sBl = sBh + 64 * YP;
    uint32_t uAh = smem_u32(sAh), uAl = smem_u32(sAl);
    uint32_t uBh = smem_u32(sBh), uBl = smem_u32(sBl);

    int d0 = blockIdx.x * 64;
    int c = blockIdx.y, b = blockIdx.z;
    int tid = threadIdx.x, w = tid >> 5, lane = tid & 31;
    int g = lane >> 2, tig = lane & 3;
    int lq = lane & 7, lseg = lane >> 3;
    int arow = (lseg & 1) * 8 + lq;
    int asel = (lseg >> 1) * 8;

    size_t aqbase = (size_t)(c * BATCH + b) * CHUNK * AQW;
    size_t sbase  = (size_t)(c * BATCH + b) * D_K * D_V;

    float acc[2][8][4];
#pragma unroll
    for (int i = 0; i < 2; i++)
#pragma unroll
        for (int j = 0; j < 8; j++)
#pragma unroll
            for (int k = 0; k < 4; k++) acc[i][j][k] = 0.f;

    for (int ch = 0; ch < 3; ch++) {
        __syncthreads();
        // --- A staging: cp.async 128 rows x 64 bf16 (hi+lo) ---
#pragma unroll
        for (int u = 0; u < 8; u++) {
            int l = tid + u * 128;               // 0..1023
            int rr = l >> 3, qq = l & 7;
            size_t src = aqbase + rr * AQW + ch * 64 + qq * 8;
            uint32_t so = (uint32_t)(rr * YP + qq * 8) * 2;
            cp16(uAh + so, &g_AQh[src]);
            cp16(uAl + so, &g_AQl[src]);
        }
        // --- B staging: pure cp.async (V rows from g_Vh/g_Vl; S rows from g_Sh/g_Sl)
#pragma unroll
        for (int u = 0; u < 4; u++) {
            int l = tid + u * 128;               // 0..511
            int rr = l >> 3, qq = l & 7;
            uint32_t so = (uint32_t)(rr * YP + qq * 8) * 2;
            if (ch < 2) {
                size_t src = (size_t)((c * CHUNK + ch * 64 + rr) * BATCH + b) * D_V + d0 + qq * 8;
                cp16(uBh + so, &g_Vh[src]);
                cp16(uBl + so, &g_Vl[src]);
            } else {
                size_t src = sbase + (size_t)rr * D_V + d0 + qq * 8;
                cp16(uBh + so, &g_Sh[src]);
                cp16(uBl + so, &g_Sl[src]);
            }
        }
        CP_COMMIT();
        CP_WAIT(0);
        __syncthreads();

        // --- compute ---
#pragma unroll
        for (int ks = 0; ks < 64; ks += 16) {
            uint32_t Ah[2][4], Al[2][4], Bh[8][2], Bl[8][2];
#pragma unroll
            for (int mi = 0; mi < 2; mi++) {
                uint32_t off = (uint32_t)((w * 32 + mi * 16 + arow) * YP + ks + asel) * 2;
                ldm_x4(Ah[mi][0], Ah[mi][1], Ah[mi][2], Ah[mi][3], uAh + off);
                ldm_x4(Al[mi][0], Al[mi][1], Al[mi][2], Al[mi][3], uAl + off);
            }
            uint32_t row = ks + (lseg & 1) * 8 + lq;
#pragma unroll
            for (int nbs = 0; nbs < 4; nbs++) {
                uint32_t col = nbs * 16 + (lseg >> 1) * 8;
                uint32_t off = (row * YP + col) * 2;
                ldm_x4_trans(Bh[nbs * 2][0], Bh[nbs * 2][1], Bh[nbs * 2 + 1][0], Bh[nbs * 2 + 1][1], uBh + off);
                ldm_x4_trans(Bl[nbs * 2][0], Bl[nbs * 2][1], Bl[nbs * 2 + 1][0], Bl[nbs * 2 + 1][1], uBl + off);
            }
#pragma unroll
            for (int mi = 0; mi < 2; mi++)
#pragma unroll
                for (int nj = 0; nj < 8; nj++) {
                    mma_bf16(acc[mi][nj], Ah[mi], Bh[nj]);
                    mma_bf16(acc[mi][nj], Ah[mi], Bl[nj]);
                    mma_bf16(acc[mi][nj], Al[mi], Bh[nj]);
                }
        }
    }

    // --- epilogue: write Y ---
#pragma unroll
    for (int mi = 0; mi < 2; mi++) {
        int t = w * 32 + mi * 16 + g;
#pragma unroll
        for (int nj = 0; nj < 8; nj++) {
            int col = d0 + nj * 8 + tig * 2;
            float2 lo; lo.x = acc[mi][nj][0]; lo.y = acc[mi][nj][1];
            float2 hi; hi.x = acc[mi][nj][2]; hi.y = acc[mi][nj][3];
            *(float2*)&out[(size_t)((c * CHUNK + t) * BATCH + b) * D_V + col] = lo;
            *(float2*)&out[(size_t)((c * CHUNK + t + 8) * BATCH + b) * D_V + col] = hi;
        }
    }
}

// ---------------- launch ----------------
extern "C" void kernel_launch(void* const* d_in, const int* in_sizes, int n_in,
                              void* d_out, int out_size) {
    const float* x  = (const float*)d_in[0];
    const float* Wv = (const float*)d_in[1];
    const float* bv = (const float*)d_in[2];
    const float* Wk = (const float*)d_in[3];
    const float* bk = (const float*)d_in[4];
    const float* Wq = (const float*)d_in[5];
    const float* bq = (const float*)d_in[6];
    const float* Wa = (const float*)d_in[7];
    const float* ba = (const float*)d_in[8];
    float* out = (float*)d_out;

    cudaFuncSetAttribute(prep_kernel, cudaFuncAttributeMaxDynamicSharedMemorySize, PREP_SMEM);
    cudaFuncSetAttribute(gemm_mma_kernel, cudaFuncAttributeMaxDynamicSharedMemorySize, GM_SMEM);
    cudaFuncSetAttribute(contrib_kernel, cudaFuncAttributeMaxDynamicSharedMemorySize, CM_SMEM);
    cudaFuncSetAttribute(ygemm_mma_kernel, cudaFuncAttributeMaxDynamicSharedMemorySize, YG_SMEM);

    pack_kernel<<<(NPROJ_P * IN_DIM + 255) / 256, 256>>>(Wv, bv, Wk, bk, Wq, bq, Wa, ba);
    convx_kernel<<<(int)(((size_t)MROWS * IN_DIM / 8) / 256), 256>>>(x);
    gemm_mma_kernel<<<dim3(NPROJ_P / 128, MROWS / 128), 256, GM_SMEM>>>();
    prep_kernel<<<dim3(BATCH, NC), 256, PREP_SMEM>>>();
    contrib_kernel<<<dim3(D_V / 64, NC, BATCH), 256, CM_SMEM>>>();
    state_scan_kernel<<<SEG / 256, 256>>>();
    ygemm_mma_kernel<<<dim3(D_V / 64, NC, BATCH), 128, YG_SMEM>>>(out);
}

// round 10
// speedup vs baseline: 3.0295x; 1.0950x over previous
#include <cuda_runtime.h>
#include <cuda_bf16.h>
#include <math.h>
#include <stdint.h>

#define T_LEN   8192
#define BATCH   4
#define IN_DIM  512
#define D_V     512
#define D_K     64
#define CHUNK   128
#define NC      (T_LEN / CHUNK)          // 64
#define NPROJ   (D_V + 3 * D_K)          // 704 = 11 * 64
#define MROWS   (T_LEN * BATCH)          // 32768
#define EPS_F   1e-8f
#define SEG     (BATCH * D_K * D_V)      // 131072 state elements
#define AQW     192                      // A(128) | qt(64) fused row width

// ---------------- static device scratch ----------------
__device__ __align__(128) float g_bias[NPROJ];
__device__ __align__(128) __nv_bfloat16 g_Wh[NPROJ * IN_DIM];
__device__ __align__(128) __nv_bfloat16 g_Wl[NPROJ * IN_DIM];
__device__ __align__(128) __nv_bfloat16 g_Xh[(size_t)MROWS * IN_DIM];
__device__ __align__(128) __nv_bfloat16 g_Xl[(size_t)MROWS * IN_DIM];
__device__ __align__(128) float g_proj[(size_t)MROWS * NPROJ];             // [t*B+b][704] : v|k|q|sig(a)
__device__ __align__(128) __nv_bfloat16 g_Vh[(size_t)MROWS * D_V];         // v bf16 hi [r][512]
__device__ __align__(128) __nv_bfloat16 g_Vl[(size_t)MROWS * D_V];         // lo
__device__ __align__(128) __nv_bfloat16 g_AQh[(size_t)NC * BATCH * CHUNK * AQW]; // [c][b][t][A|qt] hi
__device__ __align__(128) __nv_bfloat16 g_AQl[(size_t)NC * BATCH * CHUNK * AQW]; // lo
__device__ __align__(128) __nv_bfloat16 g_kpeh[(size_t)NC * BATCH * CHUNK * D_K];
__device__ __align__(128) __nv_bfloat16 g_kpel[(size_t)NC * BATCH * CHUNK * D_K];
__device__ __align__(128) float g_pend[NC * BATCH * D_K];
__device__ __align__(128) float g_Wc[(size_t)NC * SEG];
__device__ __align__(128) __nv_bfloat16 g_Sh[(size_t)NC * SEG];            // S_start hi [c][b][n][d]
__device__ __align__(128) __nv_bfloat16 g_Sl[(size_t)NC * SEG];            // lo

// ---------------- helpers ----------------
__device__ __forceinline__ uint32_t smem_u32(const void* p) {
    uint32_t a;
    asm("{ .reg .u64 t; cvta.to.shared.u64 t, %1; cvt.u32.u64 %0, t; }" : "=r"(a) : "l"(p));
    return a;
}
__device__ __forceinline__ void cp16(uint32_t dst, const void* src) {
    asm volatile("cp.async.cg.shared.global [%0], [%1], 16;" :: "r"(dst), "l"(src));
}
#define CP_COMMIT() asm volatile("cp.async.commit_group;")
#define CP_WAIT(n)  asm volatile("cp.async.wait_group %0;" :: "n"(n))

__device__ __forceinline__ void mma_bf16(float* c, const uint32_t* a, const uint32_t* b) {
    asm volatile(
        "mma.sync.aligned.m16n8k16.row.col.f32.bf16.bf16.f32 "
        "{%0,%1,%2,%3}, {%4,%5,%6,%7}, {%8,%9}, {%0,%1,%2,%3};"
        : "+f"(c[0]), "+f"(c[1]), "+f"(c[2]), "+f"(c[3])
        : "r"(a[0]), "r"(a[1]), "r"(a[2]), "r"(a[3]), "r"(b[0]), "r"(b[1]));
}
__device__ __forceinline__ void ldm_x4(uint32_t& r0, uint32_t& r1, uint32_t& r2, uint32_t& r3,
                                       uint32_t addr) {
    asm volatile("ldmatrix.sync.aligned.m8n8.x4.shared.b16 {%0,%1,%2,%3}, [%4];"
                 : "=r"(r0), "=r"(r1), "=r"(r2), "=r"(r3) : "r"(addr));
}
__device__ __forceinline__ void ldm_x4_trans(uint32_t& r0, uint32_t& r1, uint32_t& r2, uint32_t& r3,
                                             uint32_t addr) {
    asm volatile("ldmatrix.sync.aligned.m8n8.x4.trans.shared.b16 {%0,%1,%2,%3}, [%4];"
                 : "=r"(r0), "=r"(r1), "=r"(r2), "=r"(r3) : "r"(addr));
}
__device__ __forceinline__ uint32_t pack2h(__nv_bfloat16 a, __nv_bfloat16 b) {
    return ((uint32_t)*(uint16_t*)&b << 16) | *(uint16_t*)&a;
}
__device__ __forceinline__ void split_bf16(float v, __nv_bfloat16& h, __nv_bfloat16& l) {
    h = __float2bfloat16(v);
    l = __float2bfloat16(v - __bfloat162float(h));
}

// ---------------- kernel 0: pack weights (bf16 hi/lo) + bias ----------------
__global__ void pack_kernel(const float* __restrict__ Wv, const float* __restrict__ bv,
                            const float* __restrict__ Wk, const float* __restrict__ bk,
                            const float* __restrict__ Wq, const float* __restrict__ bq,
                            const float* __restrict__ Wa, const float* __restrict__ ba) {
    int idx = blockIdx.x * 256 + threadIdx.x;
    if (idx < NPROJ * IN_DIM) {
        int o = idx >> 9, i = idx & 511;
        float v;
        if (o < 512)       v = Wv[o * IN_DIM + i];
        else if (o < 576)  v = Wk[(o - 512) * IN_DIM + i];
        else if (o < 640)  v = Wq[(o - 576) * IN_DIM + i];
        else               v = Wa[(o - 640) * IN_DIM + i];
        __nv_bfloat16 h, l; split_bf16(v, h, l);
        g_Wh[idx] = h;
        g_Wl[idx] = l;
    }
    if (idx < NPROJ) {
        float v;
        if (idx < 512)      v = bv[idx];
        else if (idx < 576) v = bk[idx - 512];
        else if (idx < 640) v = bq[idx - 576];
        else                v = ba[idx - 640];
        g_bias[idx] = v;
    }
}

// ---------------- kernel 1: X -> bf16 hi/lo ----------------
__global__ void __launch_bounds__(256) convx_kernel(const float* __restrict__ X) {
    size_t e0 = ((size_t)blockIdx.x * 256 + threadIdx.x) * 8;
    float4 v0 = *(const float4*)&X[e0];
    float4 v1 = *(const float4*)&X[e0 + 4];
    float f[8] = {v0.x, v0.y, v0.z, v0.w, v1.x, v1.y, v1.z, v1.w};
    __align__(16) __nv_bfloat16 hh[8], ll[8];
#pragma unroll
    for (int i = 0; i < 8; i++) split_bf16(f[i], hh[i], ll[i]);
    *(uint4*)&g_Xh[e0] = *(uint4*)hh;
    *(uint4*)&g_Xl[e0] = *(uint4*)ll;
}

// ---------------- kernel 2: projection GEMM, M=128 N=64 tile, 2 CTA/SM ------------
#define GP 72
#define GSTAGE ((2 * 128 + 2 * 64) * GP)      // bf16 elems per stage (X hi/lo + W hi/lo)
#define GM_SMEM (2 * GSTAGE * 2)              // 110592 bytes -> 2 CTAs/SM

__global__ void __launch_bounds__(256, 2) gemm_mma_kernel() {
    extern __shared__ __nv_bfloat16 sm_b[];
    uint32_t sb = smem_u32(sm_b);

    int tid = threadIdx.x, wid = tid >> 5, lane = tid & 31;
    int g = lane >> 2, tig = lane & 3;
    int lq = lane & 7, lseg = lane >> 3;
    int wm = wid >> 1;               // 0..3 -> 32 rows each
    int wn = wid & 1;                // 0..1 -> 32 cols each
    int bx = blockIdx.x;             // n tile 0..10 (NPROJ exactly)
    int m0 = blockIdx.y * 128;
    int n0 = bx * 64;

    float acc[2][4][4];
#pragma unroll
    for (int i = 0; i < 2; i++)
#pragma unroll
        for (int j = 0; j < 4; j++)
#pragma unroll
            for (int k = 0; k < 4; k++) acc[i][j][k] = 0.f;

    // stage layout: Xh[128][GP], Xl[128][GP], Wh[64][GP], Wl[64][GP]
#define GCOPY(ch, buf) do {                                                              \
    uint32_t base = sb + (uint32_t)(buf) * (GSTAGE * 2);                                 \
    _Pragma("unroll")                                                                    \
    for (int u = 0; u < 4; u++) {                                                        \
        int l = tid + u * 256;               /* 0..1023 */                               \
        int rr = l >> 3, qq = l & 7;                                                     \
        size_t gx = (size_t)(m0 + rr) * IN_DIM + (ch) * 64 + qq * 8;                     \
        uint32_t so = (uint32_t)(rr * GP + qq * 8) * 2;                                  \
        cp16(base + so,                  &g_Xh[gx]);                                     \
        cp16(base + 128 * GP * 2 + so,   &g_Xl[gx]);                                     \
    }                                                                                    \
    _Pragma("unroll")                                                                    \
    for (int u = 0; u < 2; u++) {                                                        \
        int l = tid + u * 256;               /* 0..511 */                                \
        int rr = l >> 3, qq = l & 7;                                                     \
        size_t gw = (size_t)(n0 + rr) * IN_DIM + (ch) * 64 + qq * 8;                     \
        uint32_t so = (uint32_t)(rr * GP + qq * 8) * 2;                                  \
        cp16(base + 2 * 128 * GP * 2 + so,              &g_Wh[gw]);                      \
        cp16(base + (2 * 128 + 64) * GP * 2 + so,       &g_Wl[gw]);                      \
    }                                                                                    \
} while (0)

    GCOPY(0, 0);
    CP_COMMIT();

    int arow = (lseg & 1) * 8 + lq;
    int asel = (lseg >> 1) * 8;
    int brow = (lseg >> 1) * 8 + lq;
    int bsel = (lseg & 1) * 8;

    for (int ch = 0; ch < 8; ch++) {
        if (ch + 1 < 8) { GCOPY(ch + 1, (ch + 1) & 1); CP_COMMIT(); }
        if (ch + 1 < 8) CP_WAIT(1); else CP_WAIT(0);
        __syncthreads();

        uint32_t uXh = sb + (uint32_t)(ch & 1) * (GSTAGE * 2);
        uint32_t uXl = uXh + 128 * GP * 2;
        uint32_t uWh = uXl + 128 * GP * 2;
        uint32_t uWl = uWh + 64 * GP * 2;

#pragma unroll
        for (int ks = 0; ks < 64; ks += 16) {
            uint32_t Ah[2][4], Al[2][4], Bh[4][2], Bl[4][2];
#pragma unroll
            for (int mi = 0; mi < 2; mi++) {
                uint32_t off = (uint32_t)((wm * 32 + mi * 16 + arow) * GP + ks + asel) * 2;
                ldm_x4(Ah[mi][0], Ah[mi][1], Ah[mi][2], Ah[mi][3], uXh + off);
                ldm_x4(Al[mi][0], Al[mi][1], Al[mi][2], Al[mi][3], uXl + off);
            }
#pragma unroll
            for (int njp = 0; njp < 2; njp++) {
                uint32_t off = (uint32_t)((wn * 32 + njp * 16 + brow) * GP + ks + bsel) * 2;
                ldm_x4(Bh[njp * 2][0], Bh[njp * 2][1], Bh[njp * 2 + 1][0], Bh[njp * 2 + 1][1], uWh + off);
                ldm_x4(Bl[njp * 2][0], Bl[njp * 2][1], Bl[njp * 2 + 1][0], Bl[njp * 2 + 1][1], uWl + off);
            }
#pragma unroll
            for (int mi = 0; mi < 2; mi++)
#pragma unroll
                for (int nj = 0; nj < 4; nj++) {
                    mma_bf16(acc[mi][nj], Ah[mi], Bh[nj]);
                    mma_bf16(acc[mi][nj], Ah[mi], Bl[nj]);
                    mma_bf16(acc[mi][nj], Al[mi], Bh[nj]);
                }
        }
        __syncthreads();
    }

    bool alpha_tile = (bx == 10);
    bool v_tile = (bx < 8);
#pragma unroll
    for (int mi = 0; mi < 2; mi++) {
        int r0 = m0 + wm * 32 + mi * 16 + g;
#pragma unroll
        for (int nj = 0; nj < 4; nj++) {
            int col = n0 + wn * 32 + nj * 8 + tig * 2;
            float b0 = g_bias[col], b1 = g_bias[col + 1];
            float v0 = acc[mi][nj][0] + b0, v1 = acc[mi][nj][1] + b1;
            float v2 = acc[mi][nj][2] + b0, v3 = acc[mi][nj][3] + b1;
            if (alpha_tile) {
                v0 = 1.f / (1.f + expf(-v0));
                v1 = 1.f / (1.f + expf(-v1));
                v2 = 1.f / (1.f + expf(-v2));
                v3 = 1.f / (1.f + expf(-v3));
            }
            float2 lo; lo.x = v0; lo.y = v1;
            float2 hi; hi.x = v2; hi.y = v3;
            *(float2*)&g_proj[(size_t)r0 * NPROJ + col] = lo;
            *(float2*)&g_proj[(size_t)(r0 + 8) * NPROJ + col] = hi;
            if (v_tile) {
                __nv_bfloat16 h0, h1, h2, h3, l0, l1, l2, l3;
                split_bf16(v0, h0, l0); split_bf16(v1, h1, l1);
                split_bf16(v2, h2, l2); split_bf16(v3, h3, l3);
                *(uint32_t*)&g_Vh[(size_t)r0 * D_V + col]       = pack2h(h0, h1);
                *(uint32_t*)&g_Vl[(size_t)r0 * D_V + col]       = pack2h(l0, l1);
                *(uint32_t*)&g_Vh[(size_t)(r0 + 8) * D_V + col] = pack2h(h2, h3);
                *(uint32_t*)&g_Vl[(size_t)(r0 + 8) * D_V + col] = pack2h(l2, l3);
            }
        }
    }
#undef GCOPY
}

// ---------------- kernel 3: per-chunk prep -> p, kpe(bf16 hi/lo), AQ(bf16 hi/lo) --
#define PREP_SMEM (3 * 128 * 65 * 4)
__global__ void __launch_bounds__(256) prep_kernel() {
    extern __shared__ float sm[];
    float* sp  = sm;                 // [128][65] cumulative decay p
    float* sqt = sm + 128 * 65;      // [128][65] q_t
    float* skt = sm + 2 * 128 * 65;  // [128][65] k_t (also alpha temp)

    int b = blockIdx.x, c = blockIdx.y;
    int tid = threadIdx.x;
    size_t aqbase = (size_t)(c * BATCH + b) * CHUNK * AQW;
    size_t kbase  = (size_t)(c * BATCH + b) * CHUNK * D_K;

#pragma unroll
    for (int j = 0; j < 8; j++) {
        int l  = tid + j * 256;
        int t  = l >> 4;
        int c4 = (l & 15) * 4;
        const float* rowp = g_proj + (size_t)((c * CHUNK + t) * BATCH + b) * NPROJ;
        float4 av = *(const float4*)&rowp[640 + c4];
        skt[t * 65 + c4 + 0] = av.x; skt[t * 65 + c4 + 1] = av.y;
        skt[t * 65 + c4 + 2] = av.z; skt[t * 65 + c4 + 3] = av.w;
    }
    __syncthreads();

    if (tid < D_K) {
        float p = 1.f;
        for (int t = 0; t < CHUNK; t++) {
            p *= fmaxf(skt[t * 65 + tid], EPS_F);
            sp[t * 65 + tid] = p;
        }
        g_pend[(c * BATCH + b) * D_K + tid] = p;
    }
    __syncthreads();

#pragma unroll
    for (int j = 0; j < 8; j++) {
        int l  = tid + j * 256;
        int t  = l >> 4;
        int c4 = (l & 15) * 4;
        const float* rowp = g_proj + (size_t)((c * CHUNK + t) * BATCH + b) * NPROJ;
        float4 qv = *(const float4*)&rowp[576 + c4];
        float4 kv = *(const float4*)&rowp[512 + c4];
        float p0 = sp[t * 65 + c4 + 0], p1 = sp[t * 65 + c4 + 1];
        float p2 = sp[t * 65 + c4 + 2], p3 = sp[t * 65 + c4 + 3];
        float pe0 = sp[127 * 65 + c4 + 0], pe1 = sp[127 * 65 + c4 + 1];
        float pe2 = sp[127 * 65 + c4 + 2], pe3 = sp[127 * 65 + c4 + 3];
        float q0 = qv.x * p0, q1 = qv.y * p1, q2 = qv.z * p2, q3 = qv.w * p3;
        float k0 = kv.x / (p0 + EPS_F), k1 = kv.y / (p1 + EPS_F);
        float k2 = kv.z / (p2 + EPS_F), k3 = kv.w / (p3 + EPS_F);
        sqt[t * 65 + c4 + 0] = q0; sqt[t * 65 + c4 + 1] = q1;
        sqt[t * 65 + c4 + 2] = q2; sqt[t * 65 + c4 + 3] = q3;
        skt[t * 65 + c4 + 0] = k0; skt[t * 65 + c4 + 1] = k1;
        skt[t * 65 + c4 + 2] = k2; skt[t * 65 + c4 + 3] = k3;
        __nv_bfloat16 h0, h1, h2, h3, l0, l1, l2, l3;
        split_bf16(q0, h0, l0); split_bf16(q1, h1, l1);
        split_bf16(q2, h2, l2); split_bf16(q3, h3, l3);
        uint32_t* ph = (uint32_t*)&g_AQh[aqbase + t * AQW + 128 + c4];
        uint32_t* pl = (uint32_t*)&g_AQl[aqbase + t * AQW + 128 + c4];
        ph[0] = pack2h(h0, h1); ph[1] = pack2h(h2, h3);
        pl[0] = pack2h(l0, l1); pl[1] = pack2h(l2, l3);
        split_bf16(k0 * pe0, h0, l0); split_bf16(k1 * pe1, h1, l1);
        split_bf16(k2 * pe2, h2, l2); split_bf16(k3 * pe3, h3, l3);
        uint32_t* kh = (uint32_t*)&g_kpeh[kbase + t * D_K + c4];
        uint32_t* kl = (uint32_t*)&g_kpel[kbase + t * D_K + c4];
        kh[0] = pack2h(h0, h1); kh[1] = pack2h(h2, h3);
        kl[0] = pack2h(l0, l1); kl[1] = pack2h(l2, l3);
    }
    __syncthreads();

    // A[t][s] = sum_n q_t[t][n] * k_t[s][n], masked t>=s -> bf16 hi/lo
    int sxl = tid & 15;
    int t0  = (tid >> 4) * 8;
    float acc[8][8];
#pragma unroll
    for (int i = 0; i < 8; i++)
#pragma unroll
        for (int j = 0; j < 8; j++) acc[i][j] = 0.f;

    for (int n = 0; n < D_K; n++) {
        float qv[8], kv[8];
#pragma unroll
        for (int i = 0; i < 8; i++) qv[i] = sqt[(t0 + i) * 65 + n];
#pragma unroll
        for (int j = 0; j < 8; j++) kv[j] = skt[(sxl + 16 * j) * 65 + n];
#pragma unroll
        for (int i = 0; i < 8; i++)
#pragma unroll
            for (int j = 0; j < 8; j++)
                acc[i][j] = fmaf(qv[i], kv[j], acc[i][j]);
    }
#pragma unroll
    for (int i = 0; i < 8; i++) {
        int t = t0 + i;
#pragma unroll
        for (int j = 0; j < 8; j++) {
            int s = sxl + 16 * j;
            float val = (t >= s) ? acc[i][j] : 0.f;
            __nv_bfloat16 h, l; split_bf16(val, h, l);
            g_AQh[aqbase + t * AQW + s] = h;
            g_AQl[aqbase + t * AQW + s] = l;
        }
    }
}

// ---------------- kernel 4: contrib via HMMA: Wc[n][d] = kpe^T @ v ----------------
#define CPP 72
#define CM_SMEM (4 * 128 * CPP * 2)

__global__ void __launch_bounds__(256) contrib_kernel() {
    extern __shared__ __nv_bfloat16 csm[];
    uint32_t uKh = smem_u32(csm);
    uint32_t uKl = uKh + 128 * CPP * 2;
    uint32_t uVh = uKl + 128 * CPP * 2;
    uint32_t uVl = uVh + 128 * CPP * 2;

    int d0 = blockIdx.x * 64, c = blockIdx.y, b = blockIdx.z;
    int tid = threadIdx.x, wid = tid >> 5, lane = tid & 31;
    int g = lane >> 2, tig = lane & 3;
    int lq = lane & 7, lseg = lane >> 3;
    int wn = wid & 1;                // n half: 32 rows
    int wd = wid >> 1;               // d quarter: 16 cols

    size_t kbase = (size_t)(c * BATCH + b) * CHUNK * D_K;

#pragma unroll
    for (int u = 0; u < 4; u++) {
        int l = tid + u * 256;       // 0..1023
        int rr = l >> 3, qq = l & 7;
        uint32_t so = (uint32_t)(rr * CPP + qq * 8) * 2;
        cp16(uKh + so, &g_kpeh[kbase + rr * D_K + qq * 8]);
        cp16(uKl + so, &g_kpel[kbase + rr * D_K + qq * 8]);
        size_t vs = (size_t)((c * CHUNK + rr) * BATCH + b) * D_V + d0 + qq * 8;
        cp16(uVh + so, &g_Vh[vs]);
        cp16(uVl + so, &g_Vl[vs]);
    }
    CP_COMMIT();
    CP_WAIT(0);
    __syncthreads();

    float acc[2][2][4];
#pragma unroll
    for (int i = 0; i < 2; i++)
#pragma unroll
        for (int j = 0; j < 2; j++)
#pragma unroll
            for (int k = 0; k < 4; k++) acc[i][j][k] = 0.f;

#pragma unroll
    for (int ks = 0; ks < 128; ks += 16) {
        uint32_t Ah[2][4], Al[2][4], Bh[2][2], Bl[2][2];
        uint32_t arow = ks + (lseg >> 1) * 8 + lq;
#pragma unroll
        for (int mi = 0; mi < 2; mi++) {
            uint32_t col = wn * 32 + mi * 16 + (lseg & 1) * 8;
            uint32_t off = (arow * CPP + col) * 2;
            ldm_x4_trans(Ah[mi][0], Ah[mi][1], Ah[mi][2], Ah[mi][3], uKh + off);
            ldm_x4_trans(Al[mi][0], Al[mi][1], Al[mi][2], Al[mi][3], uKl + off);
        }
        {
            uint32_t brow = ks + (lseg & 1) * 8 + lq;
            uint32_t col = wd * 16 + (lseg >> 1) * 8;
            uint32_t off = (brow * CPP + col) * 2;
            ldm_x4_trans(Bh[0][0], Bh[0][1], Bh[1][0], Bh[1][1], uVh + off);
            ldm_x4_trans(Bl[0][0], Bl[0][1], Bl[1][0], Bl[1][1], uVl + off);
        }
#pragma unroll
        for (int mi = 0; mi < 2; mi++)
#pragma unroll
            for (int nj = 0; nj < 2; nj++) {
                mma_bf16(acc[mi][nj], Ah[mi], Bh[nj]);
                mma_bf16(acc[mi][nj], Ah[mi], Bl[nj]);
                mma_bf16(acc[mi][nj], Al[mi], Bh[nj]);
            }
    }

    float* Wb = g_Wc + (size_t)(c * BATCH + b) * D_K * D_V;
#pragma unroll
    for (int mi = 0; mi < 2; mi++) {
        int n = wn * 32 + mi * 16 + g;
#pragma unroll
        for (int nj = 0; nj < 2; nj++) {
            int d = d0 + wd * 16 + nj * 8 + tig * 2;
            float2 lo; lo.x = acc[mi][nj][0]; lo.y = acc[mi][nj][1];
            float2 hi; hi.x = acc[mi][nj][2]; hi.y = acc[mi][nj][3];
            *(float2*)&Wb[(size_t)n * D_V + d] = lo;
            *(float2*)&Wb[(size_t)(n + 8) * D_V + d] = hi;
        }
    }
}

// ---------------- kernel 5: elementwise state scan; emit S_start bf16 hi/lo -------
__global__ void __launch_bounds__(256) state_scan_kernel() {
    int g = blockIdx.x * 256 + threadIdx.x;  // g = (b*64+n)*512 + d
    int bn = g >> 9;
    float s = 0.f;
    for (int c = 0; c < NC; c++) {
        size_t idx = (size_t)c * SEG + g;
        __nv_bfloat16 h, l; split_bf16(s, h, l);
        g_Sh[idx] = h;
        g_Sl[idx] = l;
        s = fmaf(s, g_pend[c * (BATCH * D_K) + bn], g_Wc[idx]);
    }
}

// ---------------- kernel 6: Y = [A | q_t] @ [V ; S] via HMMA, all-cp.async staging -
#define YP 72
#define YG_SMEM ((2 * 128 * YP + 2 * 64 * YP) * 2)

__global__ void __launch_bounds__(128) ygemm_mma_kernel(float* __restrict__ out) {
    extern __shared__ __nv_bfloat16 ysm[];
    __nv_bfloat16* sAh = ysm;                    // [128][YP]
    __nv_bfloat16* sAl = sAh + 128 * YP;
    __nv_bfloat16* sBh = sAl + 128 * YP;         // [64 k][YP d]
    __nv_bfloat16* sBl = sBh + 64 * YP;
    uint32_t uAh = smem_u32(sAh), uAl = smem_u32(sAl);
    uint32_t uBh = smem_u32(sBh), uBl = smem_u32(sBl);

    int d0 = blockIdx.x * 64;
    int c = blockIdx.y, b = blockIdx.z;
    int tid = threadIdx.x, w = tid >> 5, lane = tid & 31;
    int g = lane >> 2, tig = lane & 3;
    int lq = lane & 7, lseg = lane >> 3;
    int arow = (lseg & 1) * 8 + lq;
    int asel = (lseg >> 1) * 8;

    size_t aqbase = (size_t)(c * BATCH + b) * CHUNK * AQW;
    size_t sbase  = (size_t)(c * BATCH + b) * D_K * D_V;

    float acc[2][8][4];
#pragma unroll
    for (int i = 0; i < 2; i++)
#pragma unroll
        for (int j = 0; j < 8; j++)
#pragma unroll
            for (int k = 0; k < 4; k++) acc[i][j][k] = 0.f;

    for (int ch = 0; ch < 3; ch++) {
        __syncthreads();
#pragma unroll
        for (int u = 0; u < 8; u++) {
            int l = tid + u * 128;               // 0..1023
            int rr = l >> 3, qq = l & 7;
            size_t src = aqbase + rr * AQW + ch * 64 + qq * 8;
            uint32_t so = (uint32_t)(rr * YP + qq * 8) * 2;
            cp16(uAh + so, &g_AQh[src]);
            cp16(uAl + so, &g_AQl[src]);
        }
#pragma unroll
        for (int u = 0; u < 4; u++) {
            int l = tid + u * 128;               // 0..511
            int rr = l >> 3, qq = l & 7;
            uint32_t so = (uint32_t)(rr * YP + qq * 8) * 2;
            if (ch < 2) {
                size_t src = (size_t)((c * CHUNK + ch * 64 + rr) * BATCH + b) * D_V + d0 + qq * 8;
                cp16(uBh + so, &g_Vh[src]);
                cp16(uBl + so, &g_Vl[src]);
            } else {
                size_t src = sbase + (size_t)rr * D_V + d0 + qq * 8;
                cp16(uBh + so, &g_Sh[src]);
                cp16(uBl + so, &g_Sl[src]);
            }
        }
        CP_COMMIT();
        CP_WAIT(0);
        __syncthreads();

#pragma unroll
        for (int ks = 0; ks < 64; ks += 16) {
            uint32_t Ah[2][4], Al[2][4], Bh[8][2], Bl[8][2];
#pragma unroll
            for (int mi = 0; mi < 2; mi++) {
                uint32_t off = (uint32_t)((w * 32 + mi * 16 + arow) * YP + ks + asel) * 2;
                ldm_x4(Ah[mi][0], Ah[mi][1], Ah[mi][2], Ah[mi][3], uAh + off);
                ldm_x4(Al[mi][0], Al[mi][1], Al[mi][2], Al[mi][3], uAl + off);
            }
            uint32_t row = ks + (lseg & 1) * 8 + lq;
#pragma unroll
            for (int nbs = 0; nbs < 4; nbs++) {
                uint32_t col = nbs * 16 + (lseg >> 1) * 8;
                uint32_t off = (row * YP + col) * 2;
                ldm_x4_trans(Bh[nbs * 2][0], Bh[nbs * 2][1], Bh[nbs * 2 + 1][0], Bh[nbs * 2 + 1][1], uBh + off);
                ldm_x4_trans(Bl[nbs * 2][0], Bl[nbs * 2][1], Bl[nbs * 2 + 1][0], Bl[nbs * 2 + 1][1], uBl + off);
            }
#pragma unroll
            for (int mi = 0; mi < 2; mi++)
#pragma unroll
                for (int nj = 0; nj < 8; nj++) {
                    mma_bf16(acc[mi][nj], Ah[mi], Bh[nj]);
                    mma_bf16(acc[mi][nj], Ah[mi], Bl[nj]);
                    mma_bf16(acc[mi][nj], Al[mi], Bh[nj]);
                }
        }
    }

#pragma unroll
    for (int mi = 0; mi < 2; mi++) {
        int t = w * 32 + mi * 16 + g;
#pragma unroll
        for (int nj = 0; nj < 8; nj++) {
            int col = d0 + nj * 8 + tig * 2;
            float2 lo; lo.x = acc[mi][nj][0]; lo.y = acc[mi][nj][1];
            float2 hi; hi.x = acc[mi][nj][2]; hi.y = acc[mi][nj][3];
            *(float2*)&out[(size_t)((c * CHUNK + t) * BATCH + b) * D_V + col] = lo;
            *(float2*)&out[(size_t)((c * CHUNK + t + 8) * BATCH + b) * D_V + col] = hi;
        }
    }
}

// ---------------- launch ----------------
extern "C" void kernel_launch(void* const* d_in, const int* in_sizes, int n_in,
                              void* d_out, int out_size) {
    const float* x  = (const float*)d_in[0];
    const float* Wv = (const float*)d_in[1];
    const float* bv = (const float*)d_in[2];
    const float* Wk = (const float*)d_in[3];
    const float* bk = (const float*)d_in[4];
    const float* Wq = (const float*)d_in[5];
    const float* bq = (const float*)d_in[6];
    const float* Wa = (const float*)d_in[7];
    const float* ba = (const float*)d_in[8];
    float* out = (float*)d_out;

    cudaFuncSetAttribute(prep_kernel, cudaFuncAttributeMaxDynamicSharedMemorySize, PREP_SMEM);
    cudaFuncSetAttribute(gemm_mma_kernel, cudaFuncAttributeMaxDynamicSharedMemorySize, GM_SMEM);
    cudaFuncSetAttribute(contrib_kernel, cudaFuncAttributeMaxDynamicSharedMemorySize, CM_SMEM);
    cudaFuncSetAttribute(ygemm_mma_kernel, cudaFuncAttributeMaxDynamicSharedMemorySize, YG_SMEM);

    pack_kernel<<<(NPROJ * IN_DIM + 255) / 256, 256>>>(Wv, bv, Wk, bk, Wq, bq, Wa, ba);
    convx_kernel<<<(int)(((size_t)MROWS * IN_DIM / 8) / 256), 256>>>(x);
    gemm_mma_kernel<<<dim3(11, MROWS / 128), 256, GM_SMEM>>>();
    prep_kernel<<<dim3(BATCH, NC), 256, PREP_SMEM>>>();
    contrib_kernel<<<dim3(D_V / 64, NC, BATCH), 256, CM_SMEM>>>();
    state_scan_kernel<<<SEG / 256, 256>>>();
    ygemm_mma_kernel<<<dim3(D_V / 64, NC, BATCH), 128, YG_SMEM>>>(out);
}

// round 11
// speedup vs baseline: 3.0918x; 1.0206x over previous
#include <cuda_runtime.h>
#include <cuda_bf16.h>
#include <math.h>
#include <stdint.h>

#define T_LEN   8192
#define BATCH   4
#define IN_DIM  512
#define D_V     512
#define D_K     64
#define CHUNK   128
#define NC      (T_LEN / CHUNK)          // 64
#define NPROJ   (D_V + 3 * D_K)          // 704 = 11 * 64
#define MROWS   (T_LEN * BATCH)          // 32768
#define EPS_F   1e-8f
#define SEG     (BATCH * D_K * D_V)      // 131072 state elements
#define AQW     192                      // A(128) | qt(64) fused row width

// ---------------- static device scratch ----------------
__device__ __align__(128) float g_bias[NPROJ];
__device__ __align__(128) __nv_bfloat16 g_Wh[NPROJ * IN_DIM];
__device__ __align__(128) __nv_bfloat16 g_Wl[NPROJ * IN_DIM];
__device__ __align__(128) __nv_bfloat16 g_Xh[(size_t)MROWS * IN_DIM];
__device__ __align__(128) __nv_bfloat16 g_Xl[(size_t)MROWS * IN_DIM];
__device__ __align__(128) float g_proj[(size_t)MROWS * NPROJ];             // [t*B+b][704] : v|k|q|sig(a)
__device__ __align__(128) __nv_bfloat16 g_Vh[(size_t)MROWS * D_V];         // v bf16 hi [r][512]
__device__ __align__(128) __nv_bfloat16 g_Vl[(size_t)MROWS * D_V];         // lo
__device__ __align__(128) __nv_bfloat16 g_AQh[(size_t)NC * BATCH * CHUNK * AQW]; // [c][b][t][A|qt] hi
__device__ __align__(128) __nv_bfloat16 g_AQl[(size_t)NC * BATCH * CHUNK * AQW]; // lo
__device__ __align__(128) __nv_bfloat16 g_kpeh[(size_t)NC * BATCH * CHUNK * D_K];
__device__ __align__(128) __nv_bfloat16 g_kpel[(size_t)NC * BATCH * CHUNK * D_K];
__device__ __align__(128) float g_pend[NC * BATCH * D_K];
__device__ __align__(128) float g_Wc[(size_t)NC * SEG];
__device__ __align__(128) __nv_bfloat16 g_Sh[(size_t)NC * SEG];            // S_start hi [c][b][n][d]
__device__ __align__(128) __nv_bfloat16 g_Sl[(size_t)NC * SEG];            // lo

// ---------------- helpers ----------------
__device__ __forceinline__ uint32_t smem_u32(const void* p) {
    uint32_t a;
    asm("{ .reg .u64 t; cvta.to.shared.u64 t, %1; cvt.u32.u64 %0, t; }" : "=r"(a) : "l"(p));
    return a;
}
__device__ __forceinline__ void cp16(uint32_t dst, const void* src) {
    asm volatile("cp.async.cg.shared.global [%0], [%1], 16;" :: "r"(dst), "l"(src));
}
#define CP_COMMIT() asm volatile("cp.async.commit_group;")
#define CP_WAIT(n)  asm volatile("cp.async.wait_group %0;" :: "n"(n))

__device__ __forceinline__ void mma_bf16(float* c, const uint32_t* a, const uint32_t* b) {
    asm volatile(
        "mma.sync.aligned.m16n8k16.row.col.f32.bf16.bf16.f32 "
        "{%0,%1,%2,%3}, {%4,%5,%6,%7}, {%8,%9}, {%0,%1,%2,%3};"
        : "+f"(c[0]), "+f"(c[1]), "+f"(c[2]), "+f"(c[3])
        : "r"(a[0]), "r"(a[1]), "r"(a[2]), "r"(a[3]), "r"(b[0]), "r"(b[1]));
}
__device__ __forceinline__ void ldm_x4(uint32_t& r0, uint32_t& r1, uint32_t& r2, uint32_t& r3,
                                       uint32_t addr) {
    asm volatile("ldmatrix.sync.aligned.m8n8.x4.shared.b16 {%0,%1,%2,%3}, [%4];"
                 : "=r"(r0), "=r"(r1), "=r"(r2), "=r"(r3) : "r"(addr));
}
__device__ __forceinline__ void ldm_x4_trans(uint32_t& r0, uint32_t& r1, uint32_t& r2, uint32_t& r3,
                                             uint32_t addr) {
    asm volatile("ldmatrix.sync.aligned.m8n8.x4.trans.shared.b16 {%0,%1,%2,%3}, [%4];"
                 : "=r"(r0), "=r"(r1), "=r"(r2), "=r"(r3) : "r"(addr));
}
__device__ __forceinline__ uint32_t pack2h(__nv_bfloat16 a, __nv_bfloat16 b) {
    return ((uint32_t)*(uint16_t*)&b << 16) | *(uint16_t*)&a;
}
__device__ __forceinline__ void split_bf16(float v, __nv_bfloat16& h, __nv_bfloat16& l) {
    h = __float2bfloat16(v);
    l = __float2bfloat16(v - __bfloat162float(h));
}

// ---------------- kernel 0: pack weights (bf16 hi/lo) + bias ----------------
__global__ void pack_kernel(const float* __restrict__ Wv, const float* __restrict__ bv,
                            const float* __restrict__ Wk, const float* __restrict__ bk,
                            const float* __restrict__ Wq, const float* __restrict__ bq,
                            const float* __restrict__ Wa, const float* __restrict__ ba) {
    int idx = blockIdx.x * 256 + threadIdx.x;
    if (idx < NPROJ * IN_DIM) {
        int o = idx >> 9, i = idx & 511;
        float v;
        if (o < 512)       v = Wv[o * IN_DIM + i];
        else if (o < 576)  v = Wk[(o - 512) * IN_DIM + i];
        else if (o < 640)  v = Wq[(o - 576) * IN_DIM + i];
        else               v = Wa[(o - 640) * IN_DIM + i];
        __nv_bfloat16 h, l; split_bf16(v, h, l);
        g_Wh[idx] = h;
        g_Wl[idx] = l;
    }
    if (idx < NPROJ) {
        float v;
        if (idx < 512)      v = bv[idx];
        else if (idx < 576) v = bk[idx - 512];
        else if (idx < 640) v = bq[idx - 576];
        else                v = ba[idx - 640];
        g_bias[idx] = v;
    }
}

// ---------------- kernel 1: X -> bf16 hi/lo ----------------
__global__ void __launch_bounds__(256) convx_kernel(const float* __restrict__ X) {
    size_t e0 = ((size_t)blockIdx.x * 256 + threadIdx.x) * 8;
    float4 v0 = *(const float4*)&X[e0];
    float4 v1 = *(const float4*)&X[e0 + 4];
    float f[8] = {v0.x, v0.y, v0.z, v0.w, v1.x, v1.y, v1.z, v1.w};
    __align__(16) __nv_bfloat16 hh[8], ll[8];
#pragma unroll
    for (int i = 0; i < 8; i++) split_bf16(f[i], hh[i], ll[i]);
    *(uint4*)&g_Xh[e0] = *(uint4*)hh;
    *(uint4*)&g_Xl[e0] = *(uint4*)ll;
}

// ---------------- kernel 2: projection GEMM, M=128 N=64 tile, 2 CTA/SM ------------
#define GP 72
#define GSTAGE ((2 * 128 + 2 * 64) * GP)      // bf16 elems per stage (X hi/lo + W hi/lo)
#define GM_SMEM (2 * GSTAGE * 2)              // 110592 bytes -> 2 CTAs/SM

__global__ void __launch_bounds__(256, 2) gemm_mma_kernel() {
    extern __shared__ __nv_bfloat16 sm_b[];
    uint32_t sb = smem_u32(sm_b);

    int tid = threadIdx.x, wid = tid >> 5, lane = tid & 31;
    int g = lane >> 2, tig = lane & 3;
    int lq = lane & 7, lseg = lane >> 3;
    int wm = wid >> 1;               // 0..3 -> 32 rows each
    int wn = wid & 1;                // 0..1 -> 32 cols each
    int bx = blockIdx.x;             // n tile 0..10 (NPROJ exactly)
    int m0 = blockIdx.y * 128;
    int n0 = bx * 64;

    float acc[2][4][4];
#pragma unroll
    for (int i = 0; i < 2; i++)
#pragma unroll
        for (int j = 0; j < 4; j++)
#pragma unroll
            for (int k = 0; k < 4; k++) acc[i][j][k] = 0.f;

#define GCOPY(ch, buf) do {                                                              \
    uint32_t base = sb + (uint32_t)(buf) * (GSTAGE * 2);                                 \
    _Pragma("unroll")                                                                    \
    for (int u = 0; u < 4; u++) {                                                        \
        int l = tid + u * 256;               /* 0..1023 */                               \
        int rr = l >> 3, qq = l & 7;                                                     \
        size_t gx = (size_t)(m0 + rr) * IN_DIM + (ch) * 64 + qq * 8;                     \
        uint32_t so = (uint32_t)(rr * GP + qq * 8) * 2;                                  \
        cp16(base + so,                  &g_Xh[gx]);                                     \
        cp16(base + 128 * GP * 2 + so,   &g_Xl[gx]);                                     \
    }                                                                                    \
    _Pragma("unroll")                                                                    \
    for (int u = 0; u < 2; u++) {                                                        \
        int l = tid + u * 256;               /* 0..511 */                                \
        int rr = l >> 3, qq = l & 7;                                                     \
        size_t gw = (size_t)(n0 + rr) * IN_DIM + (ch) * 64 + qq * 8;                     \
        uint32_t so = (uint32_t)(rr * GP + qq * 8) * 2;                                  \
        cp16(base + 2 * 128 * GP * 2 + so,              &g_Wh[gw]);                      \
        cp16(base + (2 * 128 + 64) * GP * 2 + so,       &g_Wl[gw]);                      \
    }                                                                                    \
} while (0)

    GCOPY(0, 0);
    CP_COMMIT();

    int arow = (lseg & 1) * 8 + lq;
    int asel = (lseg >> 1) * 8;
    int brow = (lseg >> 1) * 8 + lq;
    int bsel = (lseg & 1) * 8;

    for (int ch = 0; ch < 8; ch++) {
        if (ch + 1 < 8) { GCOPY(ch + 1, (ch + 1) & 1); CP_COMMIT(); }
        if (ch + 1 < 8) CP_WAIT(1); else CP_WAIT(0);
        __syncthreads();

        uint32_t uXh = sb + (uint32_t)(ch & 1) * (GSTAGE * 2);
        uint32_t uXl = uXh + 128 * GP * 2;
        uint32_t uWh = uXl + 128 * GP * 2;
        uint32_t uWl = uWh + 64 * GP * 2;

#pragma unroll
        for (int ks = 0; ks < 64; ks += 16) {
            uint32_t Ah[2][4], Al[2][4], Bh[4][2], Bl[4][2];
#pragma unroll
            for (int mi = 0; mi < 2; mi++) {
                uint32_t off = (uint32_t)((wm * 32 + mi * 16 + arow) * GP + ks + asel) * 2;
                ldm_x4(Ah[mi][0], Ah[mi][1], Ah[mi][2], Ah[mi][3], uXh + off);
                ldm_x4(Al[mi][0], Al[mi][1], Al[mi][2], Al[mi][3], uXl + off);
            }
#pragma unroll
            for (int njp = 0; njp < 2; njp++) {
                uint32_t off = (uint32_t)((wn * 32 + njp * 16 + brow) * GP + ks + bsel) * 2;
                ldm_x4(Bh[njp * 2][0], Bh[njp * 2][1], Bh[njp * 2 + 1][0], Bh[njp * 2 + 1][1], uWh + off);
                ldm_x4(Bl[njp * 2][0], Bl[njp * 2][1], Bl[njp * 2 + 1][0], Bl[njp * 2 + 1][1], uWl + off);
            }
#pragma unroll
            for (int mi = 0; mi < 2; mi++)
#pragma unroll
                for (int nj = 0; nj < 4; nj++) {
                    mma_bf16(acc[mi][nj], Ah[mi], Bh[nj]);
                    mma_bf16(acc[mi][nj], Ah[mi], Bl[nj]);
                    mma_bf16(acc[mi][nj], Al[mi], Bh[nj]);
                }
        }
        __syncthreads();
    }

    bool alpha_tile = (bx == 10);
    bool v_tile = (bx < 8);
#pragma unroll
    for (int mi = 0; mi < 2; mi++) {
        int r0 = m0 + wm * 32 + mi * 16 + g;
#pragma unroll
        for (int nj = 0; nj < 4; nj++) {
            int col = n0 + wn * 32 + nj * 8 + tig * 2;
            float b0 = g_bias[col], b1 = g_bias[col + 1];
            float v0 = acc[mi][nj][0] + b0, v1 = acc[mi][nj][1] + b1;
            float v2 = acc[mi][nj][2] + b0, v3 = acc[mi][nj][3] + b1;
            if (alpha_tile) {
                v0 = 1.f / (1.f + expf(-v0));
                v1 = 1.f / (1.f + expf(-v1));
                v2 = 1.f / (1.f + expf(-v2));
                v3 = 1.f / (1.f + expf(-v3));
            }
            float2 lo; lo.x = v0; lo.y = v1;
            float2 hi; hi.x = v2; hi.y = v3;
            *(float2*)&g_proj[(size_t)r0 * NPROJ + col] = lo;
            *(float2*)&g_proj[(size_t)(r0 + 8) * NPROJ + col] = hi;
            if (v_tile) {
                __nv_bfloat16 h0, h1, h2, h3, l0, l1, l2, l3;
                split_bf16(v0, h0, l0); split_bf16(v1, h1, l1);
                split_bf16(v2, h2, l2); split_bf16(v3, h3, l3);
                *(uint32_t*)&g_Vh[(size_t)r0 * D_V + col]       = pack2h(h0, h1);
                *(uint32_t*)&g_Vl[(size_t)r0 * D_V + col]       = pack2h(l0, l1);
                *(uint32_t*)&g_Vh[(size_t)(r0 + 8) * D_V + col] = pack2h(h2, h3);
                *(uint32_t*)&g_Vl[(size_t)(r0 + 8) * D_V + col] = pack2h(l2, l3);
            }
        }
    }
#undef GCOPY
}

// ---------------- kernel 3: per-chunk prep -> p, kpe(bf16 hi/lo), AQ(bf16 hi/lo) --
#define PREP_SMEM (3 * 128 * 65 * 4)
__global__ void __launch_bounds__(256) prep_kernel() {
    extern __shared__ float sm[];
    float* sp  = sm;                 // [128][65] cumulative decay p
    float* sqt = sm + 128 * 65;      // [128][65] q_t
    float* skt = sm + 2 * 128 * 65;  // [128][65] k_t (also alpha temp)

    int b = blockIdx.x, c = blockIdx.y;
    int tid = threadIdx.x;
    size_t aqbase = (size_t)(c * BATCH + b) * CHUNK * AQW;
    size_t kbase  = (size_t)(c * BATCH + b) * CHUNK * D_K;

#pragma unroll
    for (int j = 0; j < 8; j++) {
        int l  = tid + j * 256;
        int t  = l >> 4;
        int c4 = (l & 15) * 4;
        const float* rowp = g_proj + (size_t)((c * CHUNK + t) * BATCH + b) * NPROJ;
        float4 av = *(const float4*)&rowp[640 + c4];
        skt[t * 65 + c4 + 0] = av.x; skt[t * 65 + c4 + 1] = av.y;
        skt[t * 65 + c4 + 2] = av.z; skt[t * 65 + c4 + 3] = av.w;
    }
    __syncthreads();

    if (tid < D_K) {
        float p = 1.f;
        for (int t = 0; t < CHUNK; t++) {
            p *= fmaxf(skt[t * 65 + tid], EPS_F);
            sp[t * 65 + tid] = p;
        }
        g_pend[(c * BATCH + b) * D_K + tid] = p;
    }
    __syncthreads();

#pragma unroll
    for (int j = 0; j < 8; j++) {
        int l  = tid + j * 256;
        int t  = l >> 4;
        int c4 = (l & 15) * 4;
        const float* rowp = g_proj + (size_t)((c * CHUNK + t) * BATCH + b) * NPROJ;
        float4 qv = *(const float4*)&rowp[576 + c4];
        float4 kv = *(const float4*)&rowp[512 + c4];
        float p0 = sp[t * 65 + c4 + 0], p1 = sp[t * 65 + c4 + 1];
        float p2 = sp[t * 65 + c4 + 2], p3 = sp[t * 65 + c4 + 3];
        float pe0 = sp[127 * 65 + c4 + 0], pe1 = sp[127 * 65 + c4 + 1];
        float pe2 = sp[127 * 65 + c4 + 2], pe3 = sp[127 * 65 + c4 + 3];
        float q0 = qv.x * p0, q1 = qv.y * p1, q2 = qv.z * p2, q3 = qv.w * p3;
        float k0 = kv.x / (p0 + EPS_F), k1 = kv.y / (p1 + EPS_F);
        float k2 = kv.z / (p2 + EPS_F), k3 = kv.w / (p3 + EPS_F);
        sqt[t * 65 + c4 + 0] = q0; sqt[t * 65 + c4 + 1] = q1;
        sqt[t * 65 + c4 + 2] = q2; sqt[t * 65 + c4 + 3] = q3;
        skt[t * 65 + c4 + 0] = k0; skt[t * 65 + c4 + 1] = k1;
        skt[t * 65 + c4 + 2] = k2; skt[t * 65 + c4 + 3] = k3;
        __nv_bfloat16 h0, h1, h2, h3, l0, l1, l2, l3;
        split_bf16(q0, h0, l0); split_bf16(q1, h1, l1);
        split_bf16(q2, h2, l2); split_bf16(q3, h3, l3);
        uint32_t* ph = (uint32_t*)&g_AQh[aqbase + t * AQW + 128 + c4];
        uint32_t* pl = (uint32_t*)&g_AQl[aqbase + t * AQW + 128 + c4];
        ph[0] = pack2h(h0, h1); ph[1] = pack2h(h2, h3);
        pl[0] = pack2h(l0, l1); pl[1] = pack2h(l2, l3);
        split_bf16(k0 * pe0, h0, l0); split_bf16(k1 * pe1, h1, l1);
        split_bf16(k2 * pe2, h2, l2); split_bf16(k3 * pe3, h3, l3);
        uint32_t* kh = (uint32_t*)&g_kpeh[kbase + t * D_K + c4];
        uint32_t* kl = (uint32_t*)&g_kpel[kbase + t * D_K + c4];
        kh[0] = pack2h(h0, h1); kh[1] = pack2h(h2, h3);
        kl[0] = pack2h(l0, l1); kl[1] = pack2h(l2, l3);
    }
    __syncthreads();

    // A[t][s] = sum_n q_t[t][n] * k_t[s][n], masked t>=s -> bf16 hi/lo
    int sxl = tid & 15;
    int t0  = (tid >> 4) * 8;
    float acc[8][8];
#pragma unroll
    for (int i = 0; i < 8; i++)
#pragma unroll
        for (int j = 0; j < 8; j++) acc[i][j] = 0.f;

    for (int n = 0; n < D_K; n++) {
        float qv[8], kv[8];
#pragma unroll
        for (int i = 0; i < 8; i++) qv[i] = sqt[(t0 + i) * 65 + n];
#pragma unroll
        for (int j = 0; j < 8; j++) kv[j] = skt[(sxl + 16 * j) * 65 + n];
#pragma unroll
        for (int i = 0; i < 8; i++)
#pragma unroll
            for (int j = 0; j < 8; j++)
                acc[i][j] = fmaf(qv[i], kv[j], acc[i][j]);
    }
#pragma unroll
    for (int i = 0; i < 8; i++) {
        int t = t0 + i;
#pragma unroll
        for (int j = 0; j < 8; j++) {
            int s = sxl + 16 * j;
            float val = (t >= s) ? acc[i][j] : 0.f;
            __nv_bfloat16 h, l; split_bf16(val, h, l);
            g_AQh[aqbase + t * AQW + s] = h;
            g_AQl[aqbase + t * AQW + s] = l;
        }
    }
}

// ---------------- kernel 4: contrib via HMMA, split-stage pipeline ----------------
#define CPP 72
#define CM_SMEM (4 * 128 * CPP * 2)

__global__ void __launch_bounds__(256) contrib_kernel() {
    extern __shared__ __nv_bfloat16 csm[];
    uint32_t uKh = smem_u32(csm);
    uint32_t uKl = uKh + 128 * CPP * 2;
    uint32_t uVh = uKl + 128 * CPP * 2;
    uint32_t uVl = uVh + 128 * CPP * 2;

    int d0 = blockIdx.x * 64, c = blockIdx.y, b = blockIdx.z;
    int tid = threadIdx.x, wid = tid >> 5, lane = tid & 31;
    int g = lane >> 2, tig = lane & 3;
    int lq = lane & 7, lseg = lane >> 3;
    int wn = wid & 1;                // n half: 32 rows
    int wd = wid >> 1;               // d quarter: 16 cols

    size_t kbase = (size_t)(c * BATCH + b) * CHUNK * D_K;

    // stage rows 0..63 (group A), then rows 64..127 (group B)
#pragma unroll
    for (int u = 0; u < 2; u++) {
        int l = tid + u * 256;       // 0..511 -> rows 0..63
        int rr = l >> 3, qq = l & 7;
        uint32_t so = (uint32_t)(rr * CPP + qq * 8) * 2;
        cp16(uKh + so, &g_kpeh[kbase + rr * D_K + qq * 8]);
        cp16(uKl + so, &g_kpel[kbase + rr * D_K + qq * 8]);
        size_t vs = (size_t)((c * CHUNK + rr) * BATCH + b) * D_V + d0 + qq * 8;
        cp16(uVh + so, &g_Vh[vs]);
        cp16(uVl + so, &g_Vl[vs]);
    }
    CP_COMMIT();
#pragma unroll
    for (int u = 2; u < 4; u++) {
        int l = tid + u * 256;       // 512..1023 -> rows 64..127
        int rr = l >> 3, qq = l & 7;
        uint32_t so = (uint32_t)(rr * CPP + qq * 8) * 2;
        cp16(uKh + so, &g_kpeh[kbase + rr * D_K + qq * 8]);
        cp16(uKl + so, &g_kpel[kbase + rr * D_K + qq * 8]);
        size_t vs = (size_t)((c * CHUNK + rr) * BATCH + b) * D_V + d0 + qq * 8;
        cp16(uVh + so, &g_Vh[vs]);
        cp16(uVl + so, &g_Vl[vs]);
    }
    CP_COMMIT();

    float acc[2][2][4];
#pragma unroll
    for (int i = 0; i < 2; i++)
#pragma unroll
        for (int j = 0; j < 2; j++)
#pragma unroll
            for (int k = 0; k < 4; k++) acc[i][j][k] = 0.f;

#pragma unroll
    for (int half = 0; half < 2; half++) {
        if (half == 0) CP_WAIT(1); else CP_WAIT(0);
        __syncthreads();
#pragma unroll
        for (int kk = 0; kk < 64; kk += 16) {
            int ks = half * 64 + kk;
            uint32_t Ah[2][4], Al[2][4], Bh[2][2], Bl[2][2];
            uint32_t arow = ks + (lseg >> 1) * 8 + lq;
#pragma unroll
            for (int mi = 0; mi < 2; mi++) {
                uint32_t col = wn * 32 + mi * 16 + (lseg & 1) * 8;
                uint32_t off = (arow * CPP + col) * 2;
                ldm_x4_trans(Ah[mi][0], Ah[mi][1], Ah[mi][2], Ah[mi][3], uKh + off);
                ldm_x4_trans(Al[mi][0], Al[mi][1], Al[mi][2], Al[mi][3], uKl + off);
            }
            {
                uint32_t brow = ks + (lseg & 1) * 8 + lq;
                uint32_t col = wd * 16 + (lseg >> 1) * 8;
                uint32_t off = (brow * CPP + col) * 2;
                ldm_x4_trans(Bh[0][0], Bh[0][1], Bh[1][0], Bh[1][1], uVh + off);
                ldm_x4_trans(Bl[0][0], Bl[0][1], Bl[1][0], Bl[1][1], uVl + off);
            }
#pragma unroll
            for (int mi = 0; mi < 2; mi++)
#pragma unroll
                for (int nj = 0; nj < 2; nj++) {
                    mma_bf16(acc[mi][nj], Ah[mi], Bh[nj]);
                    mma_bf16(acc[mi][nj], Ah[mi], Bl[nj]);
                    mma_bf16(acc[mi][nj], Al[mi], Bh[nj]);
                }
        }
    }

    float* Wb = g_Wc + (size_t)(c * BATCH + b) * D_K * D_V;
#pragma unroll
    for (int mi = 0; mi < 2; mi++) {
        int n = wn * 32 + mi * 16 + g;
#pragma unroll
        for (int nj = 0; nj < 2; nj++) {
            int d = d0 + wd * 16 + nj * 8 + tig * 2;
            float2 lo; lo.x = acc[mi][nj][0]; lo.y = acc[mi][nj][1];
            float2 hi; hi.x = acc[mi][nj][2]; hi.y = acc[mi][nj][3];
            *(float2*)&Wb[(size_t)n * D_V + d] = lo;
            *(float2*)&Wb[(size_t)(n + 8) * D_V + d] = hi;
        }
    }
}

// ---------------- kernel 5: elementwise state scan; emit S_start bf16 hi/lo -------
__global__ void __launch_bounds__(256) state_scan_kernel() {
    int g = blockIdx.x * 256 + threadIdx.x;  // g = (b*64+n)*512 + d
    int bn = g >> 9;
    float s = 0.f;
    for (int c = 0; c < NC; c++) {
        size_t idx = (size_t)c * SEG + g;
        __nv_bfloat16 h, l; split_bf16(s, h, l);
        g_Sh[idx] = h;
        g_Sl[idx] = l;
        s = fmaf(s, g_pend[c * (BATCH * D_K) + bn], g_Wc[idx]);
    }
}

// ---------------- kernel 6: Y = [A | q_t] @ [V ; S], double-buffered chunks -------
#define YP 72
#define YSTAGE ((2 * 128 + 2 * 64) * YP)     // bf16 elems per stage
#define YG_SMEM (2 * YSTAGE * 2)             // 110592 bytes -> 2 CTAs/SM

__global__ void __launch_bounds__(128, 2) ygemm_mma_kernel(float* __restrict__ out) {
    extern __shared__ __nv_bfloat16 ysm[];
    uint32_t sb = smem_u32(ysm);

    int d0 = blockIdx.x * 64;
    int c = blockIdx.y, b = blockIdx.z;
    int tid = threadIdx.x, w = tid >> 5, lane = tid & 31;
    int g = lane >> 2, tig = lane & 3;
    int lq = lane & 7, lseg = lane >> 3;
    int arow = (lseg & 1) * 8 + lq;
    int asel = (lseg >> 1) * 8;

    size_t aqbase = (size_t)(c * BATCH + b) * CHUNK * AQW;
    size_t sbase  = (size_t)(c * BATCH + b) * D_K * D_V;

    float acc[2][8][4];
#pragma unroll
    for (int i = 0; i < 2; i++)
#pragma unroll
        for (int j = 0; j < 8; j++)
#pragma unroll
            for (int k = 0; k < 4; k++) acc[i][j][k] = 0.f;

    // stage layout per buffer: Ah[128][YP], Al[128][YP], Bh[64][YP], Bl[64][YP]
#define YCOPY(ch, buf) do {                                                              \
    uint32_t base = sb + (uint32_t)(buf) * (YSTAGE * 2);                                 \
    _Pragma("unroll")                                                                    \
    for (int u = 0; u < 8; u++) {                                                        \
        int l = tid + u * 128;               /* 0..1023 */                               \
        int rr = l >> 3, qq = l & 7;                                                     \
        size_t src = aqbase + rr * AQW + (ch) * 64 + qq * 8;                             \
        uint32_t so = (uint32_t)(rr * YP + qq * 8) * 2;                                  \
        cp16(base + so,                 &g_AQh[src]);                                    \
        cp16(base + 128 * YP * 2 + so,  &g_AQl[src]);                                    \
    }                                                                                    \
    _Pragma("unroll")                                                                    \
    for (int u = 0; u < 4; u++) {                                                        \
        int l = tid + u * 128;               /* 0..511 */                                \
        int rr = l >> 3, qq = l & 7;                                                     \
        uint32_t so = (uint32_t)(rr * YP + qq * 8) * 2;                                  \
        if ((ch) < 2) {                                                                  \
            size_t src = (size_t)((c * CHUNK + (ch) * 64 + rr) * BATCH + b) * D_V + d0 + qq * 8; \
            cp16(base + 2 * 128 * YP * 2 + so,            &g_Vh[src]);                   \
            cp16(base + (2 * 128 + 64) * YP * 2 + so,     &g_Vl[src]);                   \
        } else {                                                                         \
            size_t src = sbase + (size_t)rr * D_V + d0 + qq * 8;                         \
            cp16(base + 2 * 128 * YP * 2 + so,            &g_Sh[src]);                   \
            cp16(base + (2 * 128 + 64) * YP * 2 + so,     &g_Sl[src]);                   \
        }                                                                                \
    }                                                                                    \
} while (0)

    YCOPY(0, 0);
    CP_COMMIT();

    for (int ch = 0; ch < 3; ch++) {
        if (ch + 1 < 3) { YCOPY(ch + 1, (ch + 1) & 1); CP_COMMIT(); }
        if (ch + 1 < 3) CP_WAIT(1); else CP_WAIT(0);
        __syncthreads();

        uint32_t uAh = sb + (uint32_t)(ch & 1) * (YSTAGE * 2);
        uint32_t uAl = uAh + 128 * YP * 2;
        uint32_t uBh = uAl + 128 * YP * 2;
        uint32_t uBl = uBh + 64 * YP * 2;

#pragma unroll
        for (int ks = 0; ks < 64; ks += 16) {
            uint32_t Ah[2][4], Al[2][4], Bh[8][2], Bl[8][2];
#pragma unroll
            for (int mi = 0; mi < 2; mi++) {
                uint32_t off = (uint32_t)((w * 32 + mi * 16 + arow) * YP + ks + asel) * 2;
                ldm_x4(Ah[mi][0], Ah[mi][1], Ah[mi][2], Ah[mi][3], uAh + off);
                ldm_x4(Al[mi][0], Al[mi][1], Al[mi][2], Al[mi][3], uAl + off);
            }
            uint32_t row = ks + (lseg & 1) * 8 + lq;
#pragma unroll
            for (int nbs = 0; nbs < 4; nbs++) {
                uint32_t col = nbs * 16 + (lseg >> 1) * 8;
                uint32_t off = (row * YP + col) * 2;
                ldm_x4_trans(Bh[nbs * 2][0], Bh[nbs * 2][1], Bh[nbs * 2 + 1][0], Bh[nbs * 2 + 1][1], uBh + off);
                ldm_x4_trans(Bl[nbs * 2][0], Bl[nbs * 2][1], Bl[nbs * 2 + 1][0], Bl[nbs * 2 + 1][1], uBl + off);
            }
#pragma unroll
            for (int mi = 0; mi < 2; mi++)
#pragma unroll
                for (int nj = 0; nj < 8; nj++) {
                    mma_bf16(acc[mi][nj], Ah[mi], Bh[nj]);
                    mma_bf16(acc[mi][nj], Ah[mi], Bl[nj]);
                    mma_bf16(acc[mi][nj], Al[mi], Bh[nj]);
                }
        }
        __syncthreads();
    }
#undef YCOPY

#pragma unroll
    for (int mi = 0; mi < 2; mi++) {
        int t = w * 32 + mi * 16 + g;
#pragma unroll
        for (int nj = 0; nj < 8; nj++) {
            int col = d0 + nj * 8 + tig * 2;
            float2 lo; lo.x = acc[mi][nj][0]; lo.y = acc[mi][nj][1];
            float2 hi; hi.x = acc[mi][nj][2]; hi.y = acc[mi][nj][3];
            *(float2*)&out[(size_t)((c * CHUNK + t) * BATCH + b) * D_V + col] = lo;
            *(float2*)&out[(size_t)((c * CHUNK + t + 8) * BATCH + b) * D_V + col] = hi;
        }
    }
}

// ---------------- launch ----------------
extern "C" void kernel_launch(void* const* d_in, const int* in_sizes, int n_in,
                              void* d_out, int out_size) {
    const float* x  = (const float*)d_in[0];
    const float* Wv = (const float*)d_in[1];
    const float* bv = (const float*)d_in[2];
    const float* Wk = (const float*)d_in[3];
    const float* bk = (const float*)d_in[4];
    const float* Wq = (const float*)d_in[5];
    const float* bq = (const float*)d_in[6];
    const float* Wa = (const float*)d_in[7];
    const float* ba = (const float*)d_in[8];
    float* out = (float*)d_out;

    cudaFuncSetAttribute(prep_kernel, cudaFuncAttributeMaxDynamicSharedMemorySize, PREP_SMEM);
    cudaFuncSetAttribute(gemm_mma_kernel, cudaFuncAttributeMaxDynamicSharedMemorySize, GM_SMEM);
    cudaFuncSetAttribute(contrib_kernel, cudaFuncAttributeMaxDynamicSharedMemorySize, CM_SMEM);
    cudaFuncSetAttribute(ygemm_mma_kernel, cudaFuncAttributeMaxDynamicSharedMemorySize, YG_SMEM);

    pack_kernel<<<(NPROJ * IN_DIM + 255) / 256, 256>>>(Wv, bv, Wk, bk, Wq, bq, Wa, ba);
    convx_kernel<<<(int)(((size_t)MROWS * IN_DIM / 8) / 256), 256>>>(x);
    gemm_mma_kernel<<<dim3(11, MROWS / 128), 256, GM_SMEM>>>();
    prep_kernel<<<dim3(BATCH, NC), 256, PREP_SMEM>>>();
    contrib_kernel<<<dim3(D_V / 64, NC, BATCH), 256, CM_SMEM>>>();
    state_scan_kernel<<<SEG / 256, 256>>>();
    ygemm_mma_kernel<<<dim3(D_V / 64, NC, BATCH), 128, YG_SMEM>>>(out);
}

// round 12
// speedup vs baseline: 3.6101x; 1.1676x over previous
#include <cuda_runtime.h>
#include <cuda_fp16.h>
#include <math.h>
#include <stdint.h>

#define T_LEN   8192
#define BATCH   4
#define IN_DIM  512
#define D_V     512
#define D_K     64
#define CHUNK   128
#define NC      (T_LEN / CHUNK)          // 64
#define NPROJ   (D_V + 3 * D_K)          // 704 = 11 * 64
#define MROWS   (T_LEN * BATCH)          // 32768
#define EPS_F   1e-8f
#define SEG     (BATCH * D_K * D_V)      // 131072 state elements
#define AQW     192                      // A(128) | qt(64) fused row width

// ---------------- static device scratch ----------------
__device__ __align__(128) float g_bias[NPROJ];
__device__ __align__(128) __half g_Wh[NPROJ * IN_DIM];
__device__ __align__(128) __half g_Wl[NPROJ * IN_DIM];
__device__ __align__(128) __half g_Xh[(size_t)MROWS * IN_DIM];
__device__ __align__(128) __half g_Xl[(size_t)MROWS * IN_DIM];
__device__ __align__(128) float g_proj[(size_t)MROWS * NPROJ];             // [t*B+b][704] : v|k|q|sig(a)
__device__ __align__(128) __half g_Vh[(size_t)MROWS * D_V];                // v fp16 hi [r][512]
__device__ __align__(128) __half g_Vl[(size_t)MROWS * D_V];                // lo
__device__ __align__(128) __half g_AQh[(size_t)NC * BATCH * CHUNK * AQW];  // [c][b][t][A|qt] hi only
__device__ __align__(128) __half g_kpeh[(size_t)NC * BATCH * CHUNK * D_K]; // hi only
__device__ __align__(128) float g_pend[NC * BATCH * D_K];
__device__ __align__(128) float g_Wc[(size_t)NC * SEG];
__device__ __align__(128) __half g_Sh[(size_t)NC * SEG];                   // S_start hi [c][b][n][d]
__device__ __align__(128) __half g_Sl[(size_t)NC * SEG];                   // lo

// ---------------- helpers ----------------
__device__ __forceinline__ uint32_t smem_u32(const void* p) {
    uint32_t a;
    asm("{ .reg .u64 t; cvta.to.shared.u64 t, %1; cvt.u32.u64 %0, t; }" : "=r"(a) : "l"(p));
    return a;
}
__device__ __forceinline__ void cp16(uint32_t dst, const void* src) {
    asm volatile("cp.async.cg.shared.global [%0], [%1], 16;" :: "r"(dst), "l"(src));
}
#define CP_COMMIT() asm volatile("cp.async.commit_group;")
#define CP_WAIT(n)  asm volatile("cp.async.wait_group %0;" :: "n"(n))

__device__ __forceinline__ void mma_f16(float* c, const uint32_t* a, const uint32_t* b) {
    asm volatile(
        "mma.sync.aligned.m16n8k16.row.col.f32.f16.f16.f32 "
        "{%0,%1,%2,%3}, {%4,%5,%6,%7}, {%8,%9}, {%0,%1,%2,%3};"
        : "+f"(c[0]), "+f"(c[1]), "+f"(c[2]), "+f"(c[3])
        : "r"(a[0]), "r"(a[1]), "r"(a[2]), "r"(a[3]), "r"(b[0]), "r"(b[1]));
}
__device__ __forceinline__ void ldm_x4(uint32_t& r0, uint32_t& r1, uint32_t& r2, uint32_t& r3,
                                       uint32_t addr) {
    asm volatile("ldmatrix.sync.aligned.m8n8.x4.shared.b16 {%0,%1,%2,%3}, [%4];"
                 : "=r"(r0), "=r"(r1), "=r"(r2), "=r"(r3) : "r"(addr));
}
__device__ __forceinline__ void ldm_x4_trans(uint32_t& r0, uint32_t& r1, uint32_t& r2, uint32_t& r3,
                                             uint32_t addr) {
    asm volatile("ldmatrix.sync.aligned.m8n8.x4.trans.shared.b16 {%0,%1,%2,%3}, [%4];"
                 : "=r"(r0), "=r"(r1), "=r"(r2), "=r"(r3) : "r"(addr));
}
__device__ __forceinline__ uint32_t pack2h(__half a, __half b) {
    return ((uint32_t)*(uint16_t*)&b << 16) | *(uint16_t*)&a;
}
__device__ __forceinline__ void split_f16(float v, __half& h, __half& l) {
    h = __float2half_rn(v);
    l = __float2half_rn(v - __half2float(h));
}

// ---------------- kernel 0: pack weights (fp16 hi/lo) + bias ----------------
__global__ void pack_kernel(const float* __restrict__ Wv, const float* __restrict__ bv,
                            const float* __restrict__ Wk, const float* __restrict__ bk,
                            const float* __restrict__ Wq, const float* __restrict__ bq,
                            const float* __restrict__ Wa, const float* __restrict__ ba) {
    int idx = blockIdx.x * 256 + threadIdx.x;
    if (idx < NPROJ * IN_DIM) {
        int o = idx >> 9, i = idx & 511;
        float v;
        if (o < 512)       v = Wv[o * IN_DIM + i];
        else if (o < 576)  v = Wk[(o - 512) * IN_DIM + i];
        else if (o < 640)  v = Wq[(o - 576) * IN_DIM + i];
        else               v = Wa[(o - 640) * IN_DIM + i];
        __half h, l; split_f16(v, h, l);
        g_Wh[idx] = h;
        g_Wl[idx] = l;
    }
    if (idx < NPROJ) {
        float v;
        if (idx < 512)      v = bv[idx];
        else if (idx < 576) v = bk[idx - 512];
        else if (idx < 640) v = bq[idx - 576];
        else                v = ba[idx - 640];
        g_bias[idx] = v;
    }
}

// ---------------- kernel 1: X -> fp16 hi/lo ----------------
__global__ void __launch_bounds__(256) convx_kernel(const float* __restrict__ X) {
    size_t e0 = ((size_t)blockIdx.x * 256 + threadIdx.x) * 8;
    float4 v0 = *(const float4*)&X[e0];
    float4 v1 = *(const float4*)&X[e0 + 4];
    float f[8] = {v0.x, v0.y, v0.z, v0.w, v1.x, v1.y, v1.z, v1.w};
    __align__(16) __half hh[8], ll[8];
#pragma unroll
    for (int i = 0; i < 8; i++) split_f16(f[i], hh[i], ll[i]);
    *(uint4*)&g_Xh[e0] = *(uint4*)hh;
    *(uint4*)&g_Xl[e0] = *(uint4*)ll;
}

// ---------------- kernel 2: projection GEMM, M=128 N=64 tile ----------------------
// v tiles (bx<8): 2-term fp16 (Xh*Wh + Xh*Wl). k/q/alpha tiles (bx>=8): 3-term.
#define GP 72
#define GSTAGE ((2 * 128 + 2 * 64) * GP)      // fp16 elems per stage
#define GM_SMEM (2 * GSTAGE * 2)              // 110592 bytes -> 2 CTAs/SM

__global__ void __launch_bounds__(256, 2) gemm_mma_kernel() {
    extern __shared__ __half sm_b[];
    uint32_t sb = smem_u32(sm_b);

    int tid = threadIdx.x, wid = tid >> 5, lane = tid & 31;
    int g = lane >> 2, tig = lane & 3;
    int lq = lane & 7, lseg = lane >> 3;
    int wm = wid >> 1;               // 0..3 -> 32 rows each
    int wn = wid & 1;                // 0..1 -> 32 cols each
    int bx = blockIdx.x;             // n tile 0..10
    int m0 = blockIdx.y * 128;
    int n0 = bx * 64;
    bool need3 = (bx >= 8);          // k/q/alpha tiles use 3-term

    float acc[2][4][4];
#pragma unroll
    for (int i = 0; i < 2; i++)
#pragma unroll
        for (int j = 0; j < 4; j++)
#pragma unroll
            for (int k = 0; k < 4; k++) acc[i][j][k] = 0.f;

#define GCOPY(ch, buf) do {                                                              \
    uint32_t base = sb + (uint32_t)(buf) * (GSTAGE * 2);                                 \
    _Pragma("unroll")                                                                    \
    for (int u = 0; u < 4; u++) {                                                        \
        int l = tid + u * 256;               /* 0..1023 */                               \
        int rr = l >> 3, qq = l & 7;                                                     \
        size_t gx = (size_t)(m0 + rr) * IN_DIM + (ch) * 64 + qq * 8;                     \
        uint32_t so = (uint32_t)(rr * GP + qq * 8) * 2;                                  \
        cp16(base + so, &g_Xh[gx]);                                                      \
        if (need3) cp16(base + 128 * GP * 2 + so, &g_Xl[gx]);                            \
    }                                                                                    \
    _Pragma("unroll")                                                                    \
    for (int u = 0; u < 2; u++) {                                                        \
        int l = tid + u * 256;               /* 0..511 */                                \
        int rr = l >> 3, qq = l & 7;                                                     \
        size_t gw = (size_t)(n0 + rr) * IN_DIM + (ch) * 64 + qq * 8;                     \
        uint32_t so = (uint32_t)(rr * GP + qq * 8) * 2;                                  \
        cp16(base + 2 * 128 * GP * 2 + so,              &g_Wh[gw]);                      \
        cp16(base + (2 * 128 + 64) * GP * 2 + so,       &g_Wl[gw]);                      \
    }                                                                                    \
} while (0)

    GCOPY(0, 0);
    CP_COMMIT();

    int arow = (lseg & 1) * 8 + lq;
    int asel = (lseg >> 1) * 8;
    int brow = (lseg >> 1) * 8 + lq;
    int bsel = (lseg & 1) * 8;

    for (int ch = 0; ch < 8; ch++) {
        if (ch + 1 < 8) { GCOPY(ch + 1, (ch + 1) & 1); CP_COMMIT(); }
        if (ch + 1 < 8) CP_WAIT(1); else CP_WAIT(0);
        __syncthreads();

        uint32_t uXh = sb + (uint32_t)(ch & 1) * (GSTAGE * 2);
        uint32_t uXl = uXh + 128 * GP * 2;
        uint32_t uWh = uXl + 128 * GP * 2;
        uint32_t uWl = uWh + 64 * GP * 2;

#pragma unroll
        for (int ks = 0; ks < 64; ks += 16) {
            uint32_t Ah[2][4], Al[2][4], Bh[4][2], Bl[4][2];
#pragma unroll
            for (int mi = 0; mi < 2; mi++) {
                uint32_t off = (uint32_t)((wm * 32 + mi * 16 + arow) * GP + ks + asel) * 2;
                ldm_x4(Ah[mi][0], Ah[mi][1], Ah[mi][2], Ah[mi][3], uXh + off);
                if (need3) ldm_x4(Al[mi][0], Al[mi][1], Al[mi][2], Al[mi][3], uXl + off);
            }
#pragma unroll
            for (int njp = 0; njp < 2; njp++) {
                uint32_t off = (uint32_t)((wn * 32 + njp * 16 + brow) * GP + ks + bsel) * 2;
                ldm_x4(Bh[njp * 2][0], Bh[njp * 2][1], Bh[njp * 2 + 1][0], Bh[njp * 2 + 1][1], uWh + off);
                ldm_x4(Bl[njp * 2][0], Bl[njp * 2][1], Bl[njp * 2 + 1][0], Bl[njp * 2 + 1][1], uWl + off);
            }
#pragma unroll
            for (int mi = 0; mi < 2; mi++)
#pragma unroll
                for (int nj = 0; nj < 4; nj++) {
                    mma_f16(acc[mi][nj], Ah[mi], Bh[nj]);
                    mma_f16(acc[mi][nj], Ah[mi], Bl[nj]);
                    if (need3) mma_f16(acc[mi][nj], Al[mi], Bh[nj]);
                }
        }
        __syncthreads();
    }

    bool alpha_tile = (bx == 10);
    bool v_tile = (bx < 8);
#pragma unroll
    for (int mi = 0; mi < 2; mi++) {
        int r0 = m0 + wm * 32 + mi * 16 + g;
#pragma unroll
        for (int nj = 0; nj < 4; nj++) {
            int col = n0 + wn * 32 + nj * 8 + tig * 2;
            float b0 = g_bias[col], b1 = g_bias[col + 1];
            float v0 = acc[mi][nj][0] + b0, v1 = acc[mi][nj][1] + b1;
            float v2 = acc[mi][nj][2] + b0, v3 = acc[mi][nj][3] + b1;
            if (alpha_tile) {
                v0 = 1.f / (1.f + expf(-v0));
                v1 = 1.f / (1.f + expf(-v1));
                v2 = 1.f / (1.f + expf(-v2));
                v3 = 1.f / (1.f + expf(-v3));
            }
            float2 lo; lo.x = v0; lo.y = v1;
            float2 hi; hi.x = v2; hi.y = v3;
            *(float2*)&g_proj[(size_t)r0 * NPROJ + col] = lo;
            *(float2*)&g_proj[(size_t)(r0 + 8) * NPROJ + col] = hi;
            if (v_tile) {
                __half h0, h1, h2, h3, l0, l1, l2, l3;
                split_f16(v0, h0, l0); split_f16(v1, h1, l1);
                split_f16(v2, h2, l2); split_f16(v3, h3, l3);
                *(uint32_t*)&g_Vh[(size_t)r0 * D_V + col]       = pack2h(h0, h1);
                *(uint32_t*)&g_Vl[(size_t)r0 * D_V + col]       = pack2h(l0, l1);
                *(uint32_t*)&g_Vh[(size_t)(r0 + 8) * D_V + col] = pack2h(h2, h3);
                *(uint32_t*)&g_Vl[(size_t)(r0 + 8) * D_V + col] = pack2h(l2, l3);
            }
        }
    }
#undef GCOPY
}

// ---------------- kernel 3: per-chunk prep -> p, kpe(fp16 hi), AQ(fp16 hi) -------
#define PREP_SMEM (3 * 128 * 65 * 4)
__global__ void __launch_bounds__(256) prep_kernel() {
    extern __shared__ float sm[];
    float* sp  = sm;                 // [128][65] cumulative decay p
    float* sqt = sm + 128 * 65;      // [128][65] q_t
    float* skt = sm + 2 * 128 * 65;  // [128][65] k_t (also alpha temp)

    int b = blockIdx.x, c = blockIdx.y;
    int tid = threadIdx.x;
    size_t aqbase = (size_t)(c * BATCH + b) * CHUNK * AQW;
    size_t kbase  = (size_t)(c * BATCH + b) * CHUNK * D_K;

#pragma unroll
    for (int j = 0; j < 8; j++) {
        int l  = tid + j * 256;
        int t  = l >> 4;
        int c4 = (l & 15) * 4;
        const float* rowp = g_proj + (size_t)((c * CHUNK + t) * BATCH + b) * NPROJ;
        float4 av = *(const float4*)&rowp[640 + c4];
        skt[t * 65 + c4 + 0] = av.x; skt[t * 65 + c4 + 1] = av.y;
        skt[t * 65 + c4 + 2] = av.z; skt[t * 65 + c4 + 3] = av.w;
    }
    __syncthreads();

    if (tid < D_K) {
        float p = 1.f;
        for (int t = 0; t < CHUNK; t++) {
            p *= fmaxf(skt[t * 65 + tid], EPS_F);
            sp[t * 65 + tid] = p;
        }
        g_pend[(c * BATCH + b) * D_K + tid] = p;
    }
    __syncthreads();

#pragma unroll
    for (int j = 0; j < 8; j++) {
        int l  = tid + j * 256;
        int t  = l >> 4;
        int c4 = (l & 15) * 4;
        const float* rowp = g_proj + (size_t)((c * CHUNK + t) * BATCH + b) * NPROJ;
        float4 qv = *(const float4*)&rowp[576 + c4];
        float4 kv = *(const float4*)&rowp[512 + c4];
        float p0 = sp[t * 65 + c4 + 0], p1 = sp[t * 65 + c4 + 1];
        float p2 = sp[t * 65 + c4 + 2], p3 = sp[t * 65 + c4 + 3];
        float pe0 = sp[127 * 65 + c4 + 0], pe1 = sp[127 * 65 + c4 + 1];
        float pe2 = sp[127 * 65 + c4 + 2], pe3 = sp[127 * 65 + c4 + 3];
        float q0 = qv.x * p0, q1 = qv.y * p1, q2 = qv.z * p2, q3 = qv.w * p3;
        float k0 = kv.x / (p0 + EPS_F), k1 = kv.y / (p1 + EPS_F);
        float k2 = kv.z / (p2 + EPS_F), k3 = kv.w / (p3 + EPS_F);
        sqt[t * 65 + c4 + 0] = q0; sqt[t * 65 + c4 + 1] = q1;
        sqt[t * 65 + c4 + 2] = q2; sqt[t * 65 + c4 + 3] = q3;
        skt[t * 65 + c4 + 0] = k0; skt[t * 65 + c4 + 1] = k1;
        skt[t * 65 + c4 + 2] = k2; skt[t * 65 + c4 + 3] = k3;
        // qt -> fp16 hi into fused AQ rows (cols 128..191)
        __half h0 = __float2half_rn(q0), h1 = __float2half_rn(q1);
        __half h2 = __float2half_rn(q2), h3 = __float2half_rn(q3);
        uint32_t* ph = (uint32_t*)&g_AQh[aqbase + t * AQW + 128 + c4];
        ph[0] = pack2h(h0, h1); ph[1] = pack2h(h2, h3);
        // kpe -> fp16 hi
        __half e0 = __float2half_rn(k0 * pe0), e1 = __float2half_rn(k1 * pe1);
        __half e2 = __float2half_rn(k2 * pe2), e3 = __float2half_rn(k3 * pe3);
        uint32_t* kh = (uint32_t*)&g_kpeh[kbase + t * D_K + c4];
        kh[0] = pack2h(e0, e1); kh[1] = pack2h(e2, e3);
    }
    __syncthreads();

    // A[t][s] = sum_n q_t[t][n] * k_t[s][n], masked t>=s -> fp16 hi
    int sxl = tid & 15;
    int t0  = (tid >> 4) * 8;
    float acc[8][8];
#pragma unroll
    for (int i = 0; i < 8; i++)
#pragma unroll
        for (int j = 0; j < 8; j++) acc[i][j] = 0.f;

    for (int n = 0; n < D_K; n++) {
        float qv[8], kv[8];
#pragma unroll
        for (int i = 0; i < 8; i++) qv[i] = sqt[(t0 + i) * 65 + n];
#pragma unroll
        for (int j = 0; j < 8; j++) kv[j] = skt[(sxl + 16 * j) * 65 + n];
#pragma unroll
        for (int i = 0; i < 8; i++)
#pragma unroll
            for (int j = 0; j < 8; j++)
                acc[i][j] = fmaf(qv[i], kv[j], acc[i][j]);
    }
#pragma unroll
    for (int i = 0; i < 8; i++) {
        int t = t0 + i;
#pragma unroll
        for (int j = 0; j < 8; j++) {
            int s = sxl + 16 * j;
            float val = (t >= s) ? acc[i][j] : 0.f;
            g_AQh[aqbase + t * AQW + s] = __float2half_rn(val);
        }
    }
}

// ---------------- kernel 4: contrib via HMMA 2-term: Wc[n][d] = kpe^T @ v ---------
#define CPP 72
#define CM_SMEM (3 * 128 * CPP * 2)

__global__ void __launch_bounds__(256) contrib_kernel() {
    extern __shared__ __half csm[];
    uint32_t uKh = smem_u32(csm);
    uint32_t uVh = uKh + 128 * CPP * 2;
    uint32_t uVl = uVh + 128 * CPP * 2;

    int d0 = blockIdx.x * 64, c = blockIdx.y, b = blockIdx.z;
    int tid = threadIdx.x, wid = tid >> 5, lane = tid & 31;
    int g = lane >> 2, tig = lane & 3;
    int lq = lane & 7, lseg = lane >> 3;
    int wn = wid & 1;                // n half: 32 rows
    int wd = wid >> 1;               // d quarter: 16 cols

    size_t kbase = (size_t)(c * BATCH + b) * CHUNK * D_K;

    // stage rows 0..63, then rows 64..127 (split pipeline)
#pragma unroll
    for (int u = 0; u < 2; u++) {
        int l = tid + u * 256;       // 0..511 -> rows 0..63
        int rr = l >> 3, qq = l & 7;
        uint32_t so = (uint32_t)(rr * CPP + qq * 8) * 2;
        cp16(uKh + so, &g_kpeh[kbase + rr * D_K + qq * 8]);
        size_t vs = (size_t)((c * CHUNK + rr) * BATCH + b) * D_V + d0 + qq * 8;
        cp16(uVh + so, &g_Vh[vs]);
        cp16(uVl + so, &g_Vl[vs]);
    }
    CP_COMMIT();
#pragma unroll
    for (int u = 2; u < 4; u++) {
        int l = tid + u * 256;       // rows 64..127
        int rr = l >> 3, qq = l & 7;
        uint32_t so = (uint32_t)(rr * CPP + qq * 8) * 2;
        cp16(uKh + so, &g_kpeh[kbase + rr * D_K + qq * 8]);
        size_t vs = (size_t)((c * CHUNK + rr) * BATCH + b) * D_V + d0 + qq * 8;
        cp16(uVh + so, &g_Vh[vs]);
        cp16(uVl + so, &g_Vl[vs]);
    }
    CP_COMMIT();

    float acc[2][2][4];
#pragma unroll
    for (int i = 0; i < 2; i++)
#pragma unroll
        for (int j = 0; j < 2; j++)
#pragma unroll
            for (int k = 0; k < 4; k++) acc[i][j][k] = 0.f;

#pragma unroll
    for (int half = 0; half < 2; half++) {
        if (half == 0) CP_WAIT(1); else CP_WAIT(0);
        __syncthreads();
#pragma unroll
        for (int kk = 0; kk < 64; kk += 16) {
            int ks = half * 64 + kk;
            uint32_t Ah[2][4], Bh[2][2], Bl[2][2];
            uint32_t arow = ks + (lseg >> 1) * 8 + lq;
#pragma unroll
            for (int mi = 0; mi < 2; mi++) {
                uint32_t col = wn * 32 + mi * 16 + (lseg & 1) * 8;
                uint32_t off = (arow * CPP + col) * 2;
                ldm_x4_trans(Ah[mi][0], Ah[mi][1], Ah[mi][2], Ah[mi][3], uKh + off);
            }
            {
                uint32_t brow = ks + (lseg & 1) * 8 + lq;
                uint32_t col = wd * 16 + (lseg >> 1) * 8;
                uint32_t off = (brow * CPP + col) * 2;
                ldm_x4_trans(Bh[0][0], Bh[0][1], Bh[1][0], Bh[1][1], uVh + off);
                ldm_x4_trans(Bl[0][0], Bl[0][1], Bl[1][0], Bl[1][1], uVl + off);
            }
#pragma unroll
            for (int mi = 0; mi < 2; mi++)
#pragma unroll
                for (int nj = 0; nj < 2; nj++) {
                    mma_f16(acc[mi][nj], Ah[mi], Bh[nj]);
                    mma_f16(acc[mi][nj], Ah[mi], Bl[nj]);
                }
        }
    }

    float* Wb = g_Wc + (size_t)(c * BATCH + b) * D_K * D_V;
#pragma unroll
    for (int mi = 0; mi < 2; mi++) {
        int n = wn * 32 + mi * 16 + g;
#pragma unroll
        for (int nj = 0; nj < 2; nj++) {
            int d = d0 + wd * 16 + nj * 8 + tig * 2;
            float2 lo; lo.x = acc[mi][nj][0]; lo.y = acc[mi][nj][1];
            float2 hi; hi.x = acc[mi][nj][2]; hi.y = acc[mi][nj][3];
            *(float2*)&Wb[(size_t)n * D_V + d] = lo;
            *(float2*)&Wb[(size_t)(n + 8) * D_V + d] = hi;
        }
    }
}

// ---------------- kernel 5: elementwise state scan; emit S_start fp16 hi/lo -------
__global__ void __launch_bounds__(256) state_scan_kernel() {
    int g = blockIdx.x * 256 + threadIdx.x;  // g = (b*64+n)*512 + d
    int bn = g >> 9;
    float s = 0.f;
    for (int c = 0; c < NC; c++) {
        size_t idx = (size_t)c * SEG + g;
        __half h, l; split_f16(s, h, l);
        g_Sh[idx] = h;
        g_Sl[idx] = l;
        s = fmaf(s, g_pend[c * (BATCH * D_K) + bn], g_Wc[idx]);
    }
}

// ---------------- kernel 6: Y = [A|q_t] @ [V;S], 2-term, double-buffered ----------
#define YP 72
#define YSTAGE ((128 + 2 * 64) * YP)         // fp16 elems per stage (A hi + B hi/lo)
#define YG_SMEM (2 * YSTAGE * 2)             // 73728 bytes -> 3 CTAs/SM

__global__ void __launch_bounds__(128, 3) ygemm_mma_kernel(float* __restrict__ out) {
    extern __shared__ __half ysm[];
    uint32_t sb = smem_u32(ysm);

    int d0 = blockIdx.x * 64;
    int c = blockIdx.y, b = blockIdx.z;
    int tid = threadIdx.x, w = tid >> 5, lane = tid & 31;
    int g = lane >> 2, tig = lane & 3;
    int lq = lane & 7, lseg = lane >> 3;
    int arow = (lseg & 1) * 8 + lq;
    int asel = (lseg >> 1) * 8;

    size_t aqbase = (size_t)(c * BATCH + b) * CHUNK * AQW;
    size_t sbase  = (size_t)(c * BATCH + b) * D_K * D_V;

    float acc[2][8][4];
#pragma unroll
    for (int i = 0; i < 2; i++)
#pragma unroll
        for (int j = 0; j < 8; j++)
#pragma unroll
            for (int k = 0; k < 4; k++) acc[i][j][k] = 0.f;

    // stage layout per buffer: Ah[128][YP], Bh[64][YP], Bl[64][YP]
#define YCOPY(ch, buf) do {                                                              \
    uint32_t base = sb + (uint32_t)(buf) * (YSTAGE * 2);                                 \
    _Pragma("unroll")                                                                    \
    for (int u = 0; u < 8; u++) {                                                        \
        int l = tid + u * 128;               /* 0..1023 */                               \
        int rr = l >> 3, qq = l & 7;                                                     \
        size_t src = aqbase + rr * AQW + (ch) * 64 + qq * 8;                             \
        uint32_t so = (uint32_t)(rr * YP + qq * 8) * 2;                                  \
        cp16(base + so, &g_AQh[src]);                                                    \
    }                                                                                    \
    _Pragma("unroll")                                                                    \
    for (int u = 0; u < 4; u++) {                                                        \
        int l = tid + u * 128;               /* 0..511 */                                \
        int rr = l >> 3, qq = l & 7;                                                     \
        uint32_t so = (uint32_t)(rr * YP + qq * 8) * 2;                                  \
        if ((ch) < 2) {                                                                  \
            size_t src = (size_t)((c * CHUNK + (ch) * 64 + rr) * BATCH + b) * D_V + d0 + qq * 8; \
            cp16(base + 128 * YP * 2 + so,           &g_Vh[src]);                        \
            cp16(base + (128 + 64) * YP * 2 + so,    &g_Vl[src]);                        \
        } else {                                                                         \
            size_t src = sbase + (size_t)rr * D_V + d0 + qq * 8;                         \
            cp16(base + 128 * YP * 2 + so,           &g_Sh[src]);                        \
            cp16(base + (128 + 64) * YP * 2 + so,    &g_Sl[src]);                        \
        }                                                                                \
    }                                                                                    \
} while (0)

    YCOPY(0, 0);
    CP_COMMIT();

    for (int ch = 0; ch < 3; ch++) {
        if (ch + 1 < 3) { YCOPY(ch + 1, (ch + 1) & 1); CP_COMMIT(); }
        if (ch + 1 < 3) CP_WAIT(1); else CP_WAIT(0);
        __syncthreads();

        uint32_t uAh = sb + (uint32_t)(ch & 1) * (YSTAGE * 2);
        uint32_t uBh = uAh + 128 * YP * 2;
        uint32_t uBl = uBh + 64 * YP * 2;

#pragma unroll
        for (int ks = 0; ks < 64; ks += 16) {
            uint32_t Ah[2][4], Bh[8][2], Bl[8][2];
#pragma unroll
            for (int mi = 0; mi < 2; mi++) {
                uint32_t off = (uint32_t)((w * 32 + mi * 16 + arow) * YP + ks + asel) * 2;
                ldm_x4(Ah[mi][0], Ah[mi][1], Ah[mi][2], Ah[mi][3], uAh + off);
            }
            uint32_t row = ks + (lseg & 1) * 8 + lq;
#pragma unroll
            for (int nbs = 0; nbs < 4; nbs++) {
                uint32_t col = nbs * 16 + (lseg >> 1) * 8;
                uint32_t off = (row * YP + col) * 2;
                ldm_x4_trans(Bh[nbs * 2][0], Bh[nbs * 2][1], Bh[nbs * 2 + 1][0], Bh[nbs * 2 + 1][1], uBh + off);
                ldm_x4_trans(Bl[nbs * 2][0], Bl[nbs * 2][1], Bl[nbs * 2 + 1][0], Bl[nbs * 2 + 1][1], uBl + off);
            }
#pragma unroll
            for (int mi = 0; mi < 2; mi++)
#pragma unroll
                for (int nj = 0; nj < 8; nj++) {
                    mma_f16(acc[mi][nj], Ah[mi], Bh[nj]);
                    mma_f16(acc[mi][nj], Ah[mi], Bl[nj]);
                }
        }
        __syncthreads();
    }
#undef YCOPY

#pragma unroll
    for (int mi = 0; mi < 2; mi++) {
        int t = w * 32 + mi * 16 + g;
#pragma unroll
        for (int nj = 0; nj < 8; nj++) {
            int col = d0 + nj * 8 + tig * 2;
            float2 lo; lo.x = acc[mi][nj][0]; lo.y = acc[mi][nj][1];
            float2 hi; hi.x = acc[mi][nj][2]; hi.y = acc[mi][nj][3];
            *(float2*)&out[(size_t)((c * CHUNK + t) * BATCH + b) * D_V + col] = lo;
            *(float2*)&out[(size_t)((c * CHUNK + t + 8) * BATCH + b) * D_V + col] = hi;
        }
    }
}

// ---------------- launch ----------------
extern "C" void kernel_launch(void* const* d_in, const int* in_sizes, int n_in,
                              void* d_out, int out_size) {
    const float* x  = (const float*)d_in[0];
    const float* Wv = (const float*)d_in[1];
    const float* bv = (const float*)d_in[2];
    const float* Wk = (const float*)d_in[3];
    const float* bk = (const float*)d_in[4];
    const float* Wq = (const float*)d_in[5];
    const float* bq = (const float*)d_in[6];
    const float* Wa = (const float*)d_in[7];
    const float* ba = (const float*)d_in[8];
    float* out = (float*)d_out;

    cudaFuncSetAttribute(prep_kernel, cudaFuncAttributeMaxDynamicSharedMemorySize, PREP_SMEM);
    cudaFuncSetAttribute(gemm_mma_kernel, cudaFuncAttributeMaxDynamicSharedMemorySize, GM_SMEM);
    cudaFuncSetAttribute(contrib_kernel, cudaFuncAttributeMaxDynamicSharedMemorySize, CM_SMEM);
    cudaFuncSetAttribute(ygemm_mma_kernel, cudaFuncAttributeMaxDynamicSharedMemorySize, YG_SMEM);

    pack_kernel<<<(NPROJ * IN_DIM + 255) / 256, 256>>>(Wv, bv, Wk, bk, Wq, bq, Wa, ba);
    convx_kernel<<<(int)(((size_t)MROWS * IN_DIM / 8) / 256), 256>>>(x);
    gemm_mma_kernel<<<dim3(11, MROWS / 128), 256, GM_SMEM>>>();
    prep_kernel<<<dim3(BATCH, NC), 256, PREP_SMEM>>>();
    contrib_kernel<<<dim3(D_V / 64, NC, BATCH), 256, CM_SMEM>>>();
    state_scan_kernel<<<SEG / 256, 256>>>();
    ygemm_mma_kernel<<<dim3(D_V / 64, NC, BATCH), 128, YG_SMEM>>>(out);
}

// round 13
// speedup vs baseline: 4.1215x; 1.1416x over previous
#include <cuda_runtime.h>
#include <cuda_fp16.h>
#include <math.h>
#include <stdint.h>

#define T_LEN   8192
#define BATCH   4
#define IN_DIM  512
#define D_V     512
#define D_K     64
#define CHUNK   128
#define NC      (T_LEN / CHUNK)          // 64
#define NPROJ   (D_V + 3 * D_K)          // 704 = 11 * 64
#define MROWS   (T_LEN * BATCH)          // 32768
#define EPS_F   1e-8f
#define SEG     (BATCH * D_K * D_V)      // 131072 state elements
#define AQW     192                      // A(128) | qt(64) fused row width

// ---------------- static device scratch ----------------
__device__ __align__(128) float g_bias[NPROJ];
__device__ __align__(128) __half g_Wh[NPROJ * IN_DIM];
__device__ __align__(128) __half g_Wl[NPROJ * IN_DIM];
__device__ __align__(128) __half g_Xh[(size_t)MROWS * IN_DIM];
__device__ __align__(128) __half g_Xl[(size_t)MROWS * IN_DIM];
__device__ __align__(128) float g_proj[(size_t)MROWS * NPROJ];             // only cols 512.. written/read
__device__ __align__(128) __half g_Vh[(size_t)MROWS * D_V];                // v fp16 [r][512]
__device__ __align__(128) __half g_AQh[(size_t)NC * BATCH * CHUNK * AQW];  // [c][b][t][A|qt]
__device__ __align__(128) __half g_kpeh[(size_t)NC * BATCH * CHUNK * D_K];
__device__ __align__(128) float g_pend[NC * BATCH * D_K];
__device__ __align__(128) float g_Wc[(size_t)NC * SEG];
__device__ __align__(128) __half g_Sh[(size_t)NC * SEG];                   // S_start [c][b][n][d]

// ---------------- helpers ----------------
__device__ __forceinline__ uint32_t smem_u32(const void* p) {
    uint32_t a;
    asm("{ .reg .u64 t; cvta.to.shared.u64 t, %1; cvt.u32.u64 %0, t; }" : "=r"(a) : "l"(p));
    return a;
}
__device__ __forceinline__ void cp16(uint32_t dst, const void* src) {
    asm volatile("cp.async.cg.shared.global [%0], [%1], 16;" :: "r"(dst), "l"(src));
}
#define CP_COMMIT() asm volatile("cp.async.commit_group;")
#define CP_WAIT(n)  asm volatile("cp.async.wait_group %0;" :: "n"(n))

__device__ __forceinline__ void mma_f16(float* c, const uint32_t* a, const uint32_t* b) {
    asm volatile(
        "mma.sync.aligned.m16n8k16.row.col.f32.f16.f16.f32 "
        "{%0,%1,%2,%3}, {%4,%5,%6,%7}, {%8,%9}, {%0,%1,%2,%3};"
        : "+f"(c[0]), "+f"(c[1]), "+f"(c[2]), "+f"(c[3])
        : "r"(a[0]), "r"(a[1]), "r"(a[2]), "r"(a[3]), "r"(b[0]), "r"(b[1]));
}
__device__ __forceinline__ void ldm_x4(uint32_t& r0, uint32_t& r1, uint32_t& r2, uint32_t& r3,
                                       uint32_t addr) {
    asm volatile("ldmatrix.sync.aligned.m8n8.x4.shared.b16 {%0,%1,%2,%3}, [%4];"
                 : "=r"(r0), "=r"(r1), "=r"(r2), "=r"(r3) : "r"(addr));
}
__device__ __forceinline__ void ldm_x4_trans(uint32_t& r0, uint32_t& r1, uint32_t& r2, uint32_t& r3,
                                             uint32_t addr) {
    asm volatile("ldmatrix.sync.aligned.m8n8.x4.trans.shared.b16 {%0,%1,%2,%3}, [%4];"
                 : "=r"(r0), "=r"(r1), "=r"(r2), "=r"(r3) : "r"(addr));
}
__device__ __forceinline__ uint32_t pack2h(__half a, __half b) {
    return ((uint32_t)*(uint16_t*)&b << 16) | *(uint16_t*)&a;
}
__device__ __forceinline__ void split_f16(float v, __half& h, __half& l) {
    h = __float2half_rn(v);
    l = __float2half_rn(v - __half2float(h));
}

// ---------------- kernel 0: pack weights (fp16 hi/lo) + bias ----------------
__global__ void pack_kernel(const float* __restrict__ Wv, const float* __restrict__ bv,
                            const float* __restrict__ Wk, const float* __restrict__ bk,
                            const float* __restrict__ Wq, const float* __restrict__ bq,
                            const float* __restrict__ Wa, const float* __restrict__ ba) {
    int idx = blockIdx.x * 256 + threadIdx.x;
    if (idx < NPROJ * IN_DIM) {
        int o = idx >> 9, i = idx & 511;
        float v;
        if (o < 512)       v = Wv[o * IN_DIM + i];
        else if (o < 576)  v = Wk[(o - 512) * IN_DIM + i];
        else if (o < 640)  v = Wq[(o - 576) * IN_DIM + i];
        else               v = Wa[(o - 640) * IN_DIM + i];
        __half h, l; split_f16(v, h, l);
        g_Wh[idx] = h;
        g_Wl[idx] = l;
    }
    if (idx < NPROJ) {
        float v;
        if (idx < 512)      v = bv[idx];
        else if (idx < 576) v = bk[idx - 512];
        else if (idx < 640) v = bq[idx - 576];
        else                v = ba[idx - 640];
        g_bias[idx] = v;
    }
}

// ---------------- kernel 1: X -> fp16 hi/lo ----------------
__global__ void __launch_bounds__(256) convx_kernel(const float* __restrict__ X) {
    size_t e0 = ((size_t)blockIdx.x * 256 + threadIdx.x) * 8;
    float4 v0 = *(const float4*)&X[e0];
    float4 v1 = *(const float4*)&X[e0 + 4];
    float f[8] = {v0.x, v0.y, v0.z, v0.w, v1.x, v1.y, v1.z, v1.w};
    __align__(16) __half hh[8], ll[8];
#pragma unroll
    for (int i = 0; i < 8; i++) split_f16(f[i], hh[i], ll[i]);
    *(uint4*)&g_Xh[e0] = *(uint4*)hh;
    *(uint4*)&g_Xl[e0] = *(uint4*)ll;
}

// ---------------- kernel 2: projection GEMM, M=128 N=64 tile ----------------------
// v tiles (bx<8): 1-term fp16 (Xh*Wh). k/q/alpha tiles (bx>=8): 3-term.
#define GP 72
#define GSTAGE ((2 * 128 + 2 * 64) * GP)      // fp16 elems per stage
#define GM_SMEM (2 * GSTAGE * 2)              // 110592 bytes -> 2 CTAs/SM

__global__ void __launch_bounds__(256, 2) gemm_mma_kernel() {
    extern __shared__ __half sm_b[];
    uint32_t sb = smem_u32(sm_b);

    int tid = threadIdx.x, wid = tid >> 5, lane = tid & 31;
    int g = lane >> 2, tig = lane & 3;
    int lq = lane & 7, lseg = lane >> 3;
    int wm = wid >> 1;               // 0..3 -> 32 rows each
    int wn = wid & 1;                // 0..1 -> 32 cols each
    int bx = blockIdx.x;             // n tile 0..10
    int m0 = blockIdx.y * 128;
    int n0 = bx * 64;
    bool need3 = (bx >= 8);          // k/q/alpha tiles use 3-term; v tiles 1-term

    float acc[2][4][4];
#pragma unroll
    for (int i = 0; i < 2; i++)
#pragma unroll
        for (int j = 0; j < 4; j++)
#pragma unroll
            for (int k = 0; k < 4; k++) acc[i][j][k] = 0.f;

#define GCOPY(ch, buf) do {                                                              \
    uint32_t base = sb + (uint32_t)(buf) * (GSTAGE * 2);                                 \
    _Pragma("unroll")                                                                    \
    for (int u = 0; u < 4; u++) {                                                        \
        int l = tid + u * 256;               /* 0..1023 */                               \
        int rr = l >> 3, qq = l & 7;                                                     \
        size_t gx = (size_t)(m0 + rr) * IN_DIM + (ch) * 64 + qq * 8;                     \
        uint32_t so = (uint32_t)(rr * GP + qq * 8) * 2;                                  \
        cp16(base + so, &g_Xh[gx]);                                                      \
        if (need3) cp16(base + 128 * GP * 2 + so, &g_Xl[gx]);                            \
    }                                                                                    \
    _Pragma("unroll")                                                                    \
    for (int u = 0; u < 2; u++) {                                                        \
        int l = tid + u * 256;               /* 0..511 */                                \
        int rr = l >> 3, qq = l & 7;                                                     \
        size_t gw = (size_t)(n0 + rr) * IN_DIM + (ch) * 64 + qq * 8;                     \
        uint32_t so = (uint32_t)(rr * GP + qq * 8) * 2;                                  \
        cp16(base + 2 * 128 * GP * 2 + so, &g_Wh[gw]);                                   \
        if (need3) cp16(base + (2 * 128 + 64) * GP * 2 + so, &g_Wl[gw]);                 \
    }                                                                                    \
} while (0)

    GCOPY(0, 0);
    CP_COMMIT();

    int arow = (lseg & 1) * 8 + lq;
    int asel = (lseg >> 1) * 8;
    int brow = (lseg >> 1) * 8 + lq;
    int bsel = (lseg & 1) * 8;

    for (int ch = 0; ch < 8; ch++) {
        if (ch + 1 < 8) { GCOPY(ch + 1, (ch + 1) & 1); CP_COMMIT(); }
        if (ch + 1 < 8) CP_WAIT(1); else CP_WAIT(0);
        __syncthreads();

        uint32_t uXh = sb + (uint32_t)(ch & 1) * (GSTAGE * 2);
        uint32_t uXl = uXh + 128 * GP * 2;
        uint32_t uWh = uXl + 128 * GP * 2;
        uint32_t uWl = uWh + 64 * GP * 2;

#pragma unroll
        for (int ks = 0; ks < 64; ks += 16) {
            uint32_t Ah[2][4], Al[2][4], Bh[4][2], Bl[4][2];
#pragma unroll
            for (int mi = 0; mi < 2; mi++) {
                uint32_t off = (uint32_t)((wm * 32 + mi * 16 + arow) * GP + ks + asel) * 2;
                ldm_x4(Ah[mi][0], Ah[mi][1], Ah[mi][2], Ah[mi][3], uXh + off);
                if (need3) ldm_x4(Al[mi][0], Al[mi][1], Al[mi][2], Al[mi][3], uXl + off);
            }
#pragma unroll
            for (int njp = 0; njp < 2; njp++) {
                uint32_t off = (uint32_t)((wn * 32 + njp * 16 + brow) * GP + ks + bsel) * 2;
                ldm_x4(Bh[njp * 2][0], Bh[njp * 2][1], Bh[njp * 2 + 1][0], Bh[njp * 2 + 1][1], uWh + off);
                if (need3) ldm_x4(Bl[njp * 2][0], Bl[njp * 2][1], Bl[njp * 2 + 1][0], Bl[njp * 2 + 1][1], uWl + off);
            }
#pragma unroll
            for (int mi = 0; mi < 2; mi++)
#pragma unroll
                for (int nj = 0; nj < 4; nj++) {
                    mma_f16(acc[mi][nj], Ah[mi], Bh[nj]);
                    if (need3) {
                        mma_f16(acc[mi][nj], Ah[mi], Bl[nj]);
                        mma_f16(acc[mi][nj], Al[mi], Bh[nj]);
                    }
                }
        }
        __syncthreads();
    }

    bool alpha_tile = (bx == 10);
    bool v_tile = (bx < 8);
#pragma unroll
    for (int mi = 0; mi < 2; mi++) {
        int r0 = m0 + wm * 32 + mi * 16 + g;
#pragma unroll
        for (int nj = 0; nj < 4; nj++) {
            int col = n0 + wn * 32 + nj * 8 + tig * 2;
            float b0 = g_bias[col], b1 = g_bias[col + 1];
            float v0 = acc[mi][nj][0] + b0, v1 = acc[mi][nj][1] + b1;
            float v2 = acc[mi][nj][2] + b0, v3 = acc[mi][nj][3] + b1;
            if (v_tile) {
                // v cols: write fp16 only (g_proj v-cols are never read)
                *(uint32_t*)&g_Vh[(size_t)r0 * D_V + col] =
                    pack2h(__float2half_rn(v0), __float2half_rn(v1));
                *(uint32_t*)&g_Vh[(size_t)(r0 + 8) * D_V + col] =
                    pack2h(__float2half_rn(v2), __float2half_rn(v3));
            } else {
                if (alpha_tile) {
                    v0 = 1.f / (1.f + expf(-v0));
                    v1 = 1.f / (1.f + expf(-v1));
                    v2 = 1.f / (1.f + expf(-v2));
                    v3 = 1.f / (1.f + expf(-v3));
                }
                float2 lo; lo.x = v0; lo.y = v1;
                float2 hi; hi.x = v2; hi.y = v3;
                *(float2*)&g_proj[(size_t)r0 * NPROJ + col] = lo;
                *(float2*)&g_proj[(size_t)(r0 + 8) * NPROJ + col] = hi;
            }
        }
    }
#undef GCOPY
}

// ---------------- kernel 3: per-chunk prep -> p, kpe(fp16), AQ(fp16) -------------
#define PREP_SMEM (3 * 128 * 65 * 4)
__global__ void __launch_bounds__(256) prep_kernel() {
    extern __shared__ float sm[];
    float* sp  = sm;                 // [128][65] cumulative decay p
    float* sqt = sm + 128 * 65;      // [128][65] q_t
    float* skt = sm + 2 * 128 * 65;  // [128][65] k_t (also alpha temp)

    int b = blockIdx.x, c = blockIdx.y;
    int tid = threadIdx.x;
    size_t aqbase = (size_t)(c * BATCH + b) * CHUNK * AQW;
    size_t kbase  = (size_t)(c * BATCH + b) * CHUNK * D_K;

#pragma unroll
    for (int j = 0; j < 8; j++) {
        int l  = tid + j * 256;
        int t  = l >> 4;
        int c4 = (l & 15) * 4;
        const float* rowp = g_proj + (size_t)((c * CHUNK + t) * BATCH + b) * NPROJ;
        float4 av = *(const float4*)&rowp[640 + c4];
        skt[t * 65 + c4 + 0] = av.x; skt[t * 65 + c4 + 1] = av.y;
        skt[t * 65 + c4 + 2] = av.z; skt[t * 65 + c4 + 3] = av.w;
    }
    __syncthreads();

    if (tid < D_K) {
        float p = 1.f;
        for (int t = 0; t < CHUNK; t++) {
            p *= fmaxf(skt[t * 65 + tid], EPS_F);
            sp[t * 65 + tid] = p;
        }
        g_pend[(c * BATCH + b) * D_K + tid] = p;
    }
    __syncthreads();

#pragma unroll
    for (int j = 0; j < 8; j++) {
        int l  = tid + j * 256;
        int t  = l >> 4;
        int c4 = (l & 15) * 4;
        const float* rowp = g_proj + (size_t)((c * CHUNK + t) * BATCH + b) * NPROJ;
        float4 qv = *(const float4*)&rowp[576 + c4];
        float4 kv = *(const float4*)&rowp[512 + c4];
        float p0 = sp[t * 65 + c4 + 0], p1 = sp[t * 65 + c4 + 1];
        float p2 = sp[t * 65 + c4 + 2], p3 = sp[t * 65 + c4 + 3];
        float pe0 = sp[127 * 65 + c4 + 0], pe1 = sp[127 * 65 + c4 + 1];
        float pe2 = sp[127 * 65 + c4 + 2], pe3 = sp[127 * 65 + c4 + 3];
        float q0 = qv.x * p0, q1 = qv.y * p1, q2 = qv.z * p2, q3 = qv.w * p3;
        float k0 = kv.x / (p0 + EPS_F), k1 = kv.y / (p1 + EPS_F);
        float k2 = kv.z / (p2 + EPS_F), k3 = kv.w / (p3 + EPS_F);
        sqt[t * 65 + c4 + 0] = q0; sqt[t * 65 + c4 + 1] = q1;
        sqt[t * 65 + c4 + 2] = q2; sqt[t * 65 + c4 + 3] = q3;
        skt[t * 65 + c4 + 0] = k0; skt[t * 65 + c4 + 1] = k1;
        skt[t * 65 + c4 + 2] = k2; skt[t * 65 + c4 + 3] = k3;
        __half h0 = __float2half_rn(q0), h1 = __float2half_rn(q1);
        __half h2 = __float2half_rn(q2), h3 = __float2half_rn(q3);
        uint32_t* ph = (uint32_t*)&g_AQh[aqbase + t * AQW + 128 + c4];
        ph[0] = pack2h(h0, h1); ph[1] = pack2h(h2, h3);
        __half e0 = __float2half_rn(k0 * pe0), e1 = __float2half_rn(k1 * pe1);
        __half e2 = __float2half_rn(k2 * pe2), e3 = __float2half_rn(k3 * pe3);
        uint32_t* kh = (uint32_t*)&g_kpeh[kbase + t * D_K + c4];
        kh[0] = pack2h(e0, e1); kh[1] = pack2h(e2, e3);
    }
    __syncthreads();

    // A[t][s] = sum_n q_t[t][n] * k_t[s][n], masked t>=s -> fp16
    int sxl = tid & 15;
    int t0  = (tid >> 4) * 8;
    float acc[8][8];
#pragma unroll
    for (int i = 0; i < 8; i++)
#pragma unroll
        for (int j = 0; j < 8; j++) acc[i][j] = 0.f;

    for (int n = 0; n < D_K; n++) {
        float qv[8], kv[8];
#pragma unroll
        for (int i = 0; i < 8; i++) qv[i] = sqt[(t0 + i) * 65 + n];
#pragma unroll
        for (int j = 0; j < 8; j++) kv[j] = skt[(sxl + 16 * j) * 65 + n];
#pragma unroll
        for (int i = 0; i < 8; i++)
#pragma unroll
            for (int j = 0; j < 8; j++)
                acc[i][j] = fmaf(qv[i], kv[j], acc[i][j]);
    }
#pragma unroll
    for (int i = 0; i < 8; i++) {
        int t = t0 + i;
#pragma unroll
        for (int j = 0; j < 8; j++) {
            int s = sxl + 16 * j;
            float val = (t >= s) ? acc[i][j] : 0.f;
            g_AQh[aqbase + t * AQW + s] = __float2half_rn(val);
        }
    }
}

// ---------------- kernel 4: contrib via HMMA 1-term: Wc[n][d] = kpe^T @ v ---------
#define CPP 72
#define CM_SMEM (2 * 128 * CPP * 2)

__global__ void __launch_bounds__(256) contrib_kernel() {
    extern __shared__ __half csm[];
    uint32_t uKh = smem_u32(csm);
    uint32_t uVh = uKh + 128 * CPP * 2;

    int d0 = blockIdx.x * 64, c = blockIdx.y, b = blockIdx.z;
    int tid = threadIdx.x, wid = tid >> 5, lane = tid & 31;
    int g = lane >> 2, tig = lane & 3;
    int lq = lane & 7, lseg = lane >> 3;
    int wn = wid & 1;                // n half: 32 rows
    int wd = wid >> 1;               // d quarter: 16 cols

    size_t kbase = (size_t)(c * BATCH + b) * CHUNK * D_K;

#pragma unroll
    for (int u = 0; u < 2; u++) {
        int l = tid + u * 256;       // rows 0..63
        int rr = l >> 3, qq = l & 7;
        uint32_t so = (uint32_t)(rr * CPP + qq * 8) * 2;
        cp16(uKh + so, &g_kpeh[kbase + rr * D_K + qq * 8]);
        size_t vs = (size_t)((c * CHUNK + rr) * BATCH + b) * D_V + d0 + qq * 8;
        cp16(uVh + so, &g_Vh[vs]);
    }
    CP_COMMIT();
#pragma unroll
    for (int u = 2; u < 4; u++) {
        int l = tid + u * 256;       // rows 64..127
        int rr = l >> 3, qq = l & 7;
        uint32_t so = (uint32_t)(rr * CPP + qq * 8) * 2;
        cp16(uKh + so, &g_kpeh[kbase + rr * D_K + qq * 8]);
        size_t vs = (size_t)((c * CHUNK + rr) * BATCH + b) * D_V + d0 + qq * 8;
        cp16(uVh + so, &g_Vh[vs]);
    }
    CP_COMMIT();

    float acc[2][2][4];
#pragma unroll
    for (int i = 0; i < 2; i++)
#pragma unroll
        for (int j = 0; j < 2; j++)
#pragma unroll
            for (int k = 0; k < 4; k++) acc[i][j][k] = 0.f;

#pragma unroll
    for (int half = 0; half < 2; half++) {
        if (half == 0) CP_WAIT(1); else CP_WAIT(0);
        __syncthreads();
#pragma unroll
        for (int kk = 0; kk < 64; kk += 16) {
            int ks = half * 64 + kk;
            uint32_t Ah[2][4], Bh[2][2];
            uint32_t arow = ks + (lseg >> 1) * 8 + lq;
#pragma unroll
            for (int mi = 0; mi < 2; mi++) {
                uint32_t col = wn * 32 + mi * 16 + (lseg & 1) * 8;
                uint32_t off = (arow * CPP + col) * 2;
                ldm_x4_trans(Ah[mi][0], Ah[mi][1], Ah[mi][2], Ah[mi][3], uKh + off);
            }
            {
                uint32_t brow = ks + (lseg & 1) * 8 + lq;
                uint32_t col = wd * 16 + (lseg >> 1) * 8;
                uint32_t off = (brow * CPP + col) * 2;
                ldm_x4_trans(Bh[0][0], Bh[0][1], Bh[1][0], Bh[1][1], uVh + off);
            }
#pragma unroll
            for (int mi = 0; mi < 2; mi++)
#pragma unroll
                for (int nj = 0; nj < 2; nj++)
                    mma_f16(acc[mi][nj], Ah[mi], Bh[nj]);
        }
    }

    float* Wb = g_Wc + (size_t)(c * BATCH + b) * D_K * D_V;
#pragma unroll
    for (int mi = 0; mi < 2; mi++) {
        int n = wn * 32 + mi * 16 + g;
#pragma unroll
        for (int nj = 0; nj < 2; nj++) {
            int d = d0 + wd * 16 + nj * 8 + tig * 2;
            float2 lo; lo.x = acc[mi][nj][0]; lo.y = acc[mi][nj][1];
            float2 hi; hi.x = acc[mi][nj][2]; hi.y = acc[mi][nj][3];
            *(float2*)&Wb[(size_t)n * D_V + d] = lo;
            *(float2*)&Wb[(size_t)(n + 8) * D_V + d] = hi;
        }
    }
}

// ---------------- kernel 5: elementwise state scan; emit S_start fp16 -------------
__global__ void __launch_bounds__(256) state_scan_kernel() {
    int g = blockIdx.x * 256 + threadIdx.x;  // g = (b*64+n)*512 + d
    int bn = g >> 9;
    float s = 0.f;
    for (int c = 0; c < NC; c++) {
        size_t idx = (size_t)c * SEG + g;
        g_Sh[idx] = __float2half_rn(s);
        s = fmaf(s, g_pend[c * (BATCH * D_K) + bn], g_Wc[idx]);
    }
}

// ---------------- kernel 6: Y = [A|q_t] @ [V;S], 1-term, double-buffered ----------
#define YP 72
#define YSTAGE ((128 + 64) * YP)             // fp16 elems per stage (A + B, hi only)
#define YG_SMEM (2 * YSTAGE * 2)             // 55296 bytes -> 4 CTAs/SM

__global__ void __launch_bounds__(128, 4) ygemm_mma_kernel(float* __restrict__ out) {
    extern __shared__ __half ysm[];
    uint32_t sb = smem_u32(ysm);

    int d0 = blockIdx.x * 64;
    int c = blockIdx.y, b = blockIdx.z;
    int tid = threadIdx.x, w = tid >> 5, lane = tid & 31;
    int g = lane >> 2, tig = lane & 3;
    int lq = lane & 7, lseg = lane >> 3;
    int arow = (lseg & 1) * 8 + lq;
    int asel = (lseg >> 1) * 8;

    size_t aqbase = (size_t)(c * BATCH + b) * CHUNK * AQW;
    size_t sbase  = (size_t)(c * BATCH + b) * D_K * D_V;

    float acc[2][8][4];
#pragma unroll
    for (int i = 0; i < 2; i++)
#pragma unroll
        for (int j = 0; j < 8; j++)
#pragma unroll
            for (int k = 0; k < 4; k++) acc[i][j][k] = 0.f;

    // stage layout per buffer: Ah[128][YP], Bh[64][YP]
#define YCOPY(ch, buf) do {                                                              \
    uint32_t base = sb + (uint32_t)(buf) * (YSTAGE * 2);                                 \
    _Pragma("unroll")                                                                    \
    for (int u = 0; u < 8; u++) {                                                        \
        int l = tid + u * 128;               /* 0..1023 */                               \
        int rr = l >> 3, qq = l & 7;                                                     \
        size_t src = aqbase + rr * AQW + (ch) * 64 + qq * 8;                             \
        uint32_t so = (uint32_t)(rr * YP + qq * 8) * 2;                                  \
        cp16(base + so, &g_AQh[src]);                                                    \
    }                                                                                    \
    _Pragma("unroll")                                                                    \
    for (int u = 0; u < 4; u++) {                                                        \
        int l = tid + u * 128;               /* 0..511 */                                \
        int rr = l >> 3, qq = l & 7;                                                     \
        uint32_t so = (uint32_t)(rr * YP + qq * 8) * 2;                                  \
        if ((ch) < 2) {                                                                  \
            size_t src = (size_t)((c * CHUNK + (ch) * 64 + rr) * BATCH + b) * D_V + d0 + qq * 8; \
            cp16(base + 128 * YP * 2 + so, &g_Vh[src]);                                  \
        } else {                                                                         \
            size_t src = sbase + (size_t)rr * D_V + d0 + qq * 8;                         \
            cp16(base + 128 * YP * 2 + so, &g_Sh[src]);                                  \
        }                                                                                \
    }                                                                                    \
} while (0)

    YCOPY(0, 0);
    CP_COMMIT();

    for (int ch = 0; ch < 3; ch++) {
        if (ch + 1 < 3) { YCOPY(ch + 1, (ch + 1) & 1); CP_COMMIT(); }
        if (ch + 1 < 3) CP_WAIT(1); else CP_WAIT(0);
        __syncthreads();

        uint32_t uAh = sb + (uint32_t)(ch & 1) * (YSTAGE * 2);
        uint32_t uBh = uAh + 128 * YP * 2;

#pragma unroll
        for (int ks = 0; ks < 64; ks += 16) {
            uint32_t Ah[2][4], Bh[8][2];
#pragma unroll
            for (int mi = 0; mi < 2; mi++) {
                uint32_t off = (uint32_t)((w * 32 + mi * 16 + arow) * YP + ks + asel) * 2;
                ldm_x4(Ah[mi][0], Ah[mi][1], Ah[mi][2], Ah[mi][3], uAh + off);
            }
            uint32_t row = ks + (lseg & 1) * 8 + lq;
#pragma unroll
            for (int nbs = 0; nbs < 4; nbs++) {
                uint32_t col = nbs * 16 + (lseg >> 1) * 8;
                uint32_t off = (row * YP + col) * 2;
                ldm_x4_trans(Bh[nbs * 2][0], Bh[nbs * 2][1], Bh[nbs * 2 + 1][0], Bh[nbs * 2 + 1][1], uBh + off);
            }
#pragma unroll
            for (int mi = 0; mi < 2; mi++)
#pragma unroll
                for (int nj = 0; nj < 8; nj++)
                    mma_f16(acc[mi][nj], Ah[mi], Bh[nj]);
        }
        __syncthreads();
    }
#undef YCOPY

#pragma unroll
    for (int mi = 0; mi < 2; mi++) {
        int t = w * 32 + mi * 16 + g;
#pragma unroll
        for (int nj = 0; nj < 8; nj++) {
            int col = d0 + nj * 8 + tig * 2;
            float2 lo; lo.x = acc[mi][nj][0]; lo.y = acc[mi][nj][1];
            float2 hi; hi.x = acc[mi][nj][2]; hi.y = acc[mi][nj][3];
            *(float2*)&out[(size_t)((c * CHUNK + t) * BATCH + b) * D_V + col] = lo;
            *(float2*)&out[(size_t)((c * CHUNK + t + 8) * BATCH + b) * D_V + col] = hi;
        }
    }
}

// ---------------- launch ----------------
extern "C" void kernel_launch(void* const* d_in, const int* in_sizes, int n_in,
                              void* d_out, int out_size) {
    const float* x  = (const float*)d_in[0];
    const float* Wv = (const float*)d_in[1];
    const float* bv = (const float*)d_in[2];
    const float* Wk = (const float*)d_in[3];
    const float* bk = (const float*)d_in[4];
    const float* Wq = (const float*)d_in[5];
    const float* bq = (const float*)d_in[6];
    const float* Wa = (const float*)d_in[7];
    const float* ba = (const float*)d_in[8];
    float* out = (float*)d_out;

    cudaFuncSetAttribute(prep_kernel, cudaFuncAttributeMaxDynamicSharedMemorySize, PREP_SMEM);
    cudaFuncSetAttribute(gemm_mma_kernel, cudaFuncAttributeMaxDynamicSharedMemorySize, GM_SMEM);
    cudaFuncSetAttribute(contrib_kernel, cudaFuncAttributeMaxDynamicSharedMemorySize, CM_SMEM);
    cudaFuncSetAttribute(ygemm_mma_kernel, cudaFuncAttributeMaxDynamicSharedMemorySize, YG_SMEM);

    pack_kernel<<<(NPROJ * IN_DIM + 255) / 256, 256>>>(Wv, bv, Wk, bk, Wq, bq, Wa, ba);
    convx_kernel<<<(int)(((size_t)MROWS * IN_DIM / 8) / 256), 256>>>(x);
    gemm_mma_kernel<<<dim3(11, MROWS / 128), 256, GM_SMEM>>>();
    prep_kernel<<<dim3(BATCH, NC), 256, PREP_SMEM>>>();
    contrib_kernel<<<dim3(D_V / 64, NC, BATCH), 256, CM_SMEM>>>();
    state_scan_kernel<<<SEG / 256, 256>>>();
    ygemm_mma_kernel<<<dim3(D_V / 64, NC, BATCH), 128, YG_SMEM>>>(out);
}

// round 14
// speedup vs baseline: 4.5691x; 1.1086x over previous
#include <cuda_runtime.h>
#include <cuda_fp16.h>
#include <math.h>
#include <stdint.h>

#define T_LEN   8192
#define BATCH   4
#define IN_DIM  512
#define D_V     512
#define D_K     64
#define CHUNK   128
#define NC      (T_LEN / CHUNK)          // 64
#define NPROJ   (D_V + 3 * D_K)          // 704 = 11 * 64
#define MROWS   (T_LEN * BATCH)          // 32768
#define EPS_F   1e-8f
#define SEG     (BATCH * D_K * D_V)      // 131072 state elements
#define AQW     192                      // A(128) | qt(64) fused row width

// ---------------- static device scratch ----------------
__device__ __align__(128) float g_bias[NPROJ];
__device__ __align__(128) __half g_Wh[NPROJ * IN_DIM];
__device__ __align__(128) __half g_Wl[NPROJ * IN_DIM];
__device__ __align__(128) __half g_Xh[(size_t)MROWS * IN_DIM];
__device__ __align__(128) __half g_Xl[(size_t)MROWS * IN_DIM];
__device__ __align__(128) float g_proj[(size_t)MROWS * NPROJ];             // only cols 512.. written/read
__device__ __align__(128) __half g_Vh[(size_t)MROWS * D_V];                // v fp16 [r][512]
__device__ __align__(128) __half g_AQh[(size_t)NC * BATCH * CHUNK * AQW];  // [c][b][t][A|qt]
__device__ __align__(128) __half g_kpeh[(size_t)NC * BATCH * CHUNK * D_K];
__device__ __align__(128) float g_pend[NC * BATCH * D_K];
__device__ __align__(128) float g_Wc[(size_t)NC * SEG];
__device__ __align__(128) __half g_Sh[(size_t)NC * SEG];                   // S_start [c][b][n][d]

// ---------------- helpers ----------------
__device__ __forceinline__ uint32_t smem_u32(const void* p) {
    uint32_t a;
    asm("{ .reg .u64 t; cvta.to.shared.u64 t, %1; cvt.u32.u64 %0, t; }" : "=r"(a) : "l"(p));
    return a;
}
__device__ __forceinline__ void cp16(uint32_t dst, const void* src) {
    asm volatile("cp.async.cg.shared.global [%0], [%1], 16;" :: "r"(dst), "l"(src));
}
#define CP_COMMIT() asm volatile("cp.async.commit_group;")
#define CP_WAIT(n)  asm volatile("cp.async.wait_group %0;" :: "n"(n))

__device__ __forceinline__ void mma_f16(float* c, const uint32_t* a, const uint32_t* b) {
    asm volatile(
        "mma.sync.aligned.m16n8k16.row.col.f32.f16.f16.f32 "
        "{%0,%1,%2,%3}, {%4,%5,%6,%7}, {%8,%9}, {%0,%1,%2,%3};"
        : "+f"(c[0]), "+f"(c[1]), "+f"(c[2]), "+f"(c[3])
        : "r"(a[0]), "r"(a[1]), "r"(a[2]), "r"(a[3]), "r"(b[0]), "r"(b[1]));
}
__device__ __forceinline__ void ldm_x4(uint32_t& r0, uint32_t& r1, uint32_t& r2, uint32_t& r3,
                                       uint32_t addr) {
    asm volatile("ldmatrix.sync.aligned.m8n8.x4.shared.b16 {%0,%1,%2,%3}, [%4];"
                 : "=r"(r0), "=r"(r1), "=r"(r2), "=r"(r3) : "r"(addr));
}
__device__ __forceinline__ void ldm_x4_trans(uint32_t& r0, uint32_t& r1, uint32_t& r2, uint32_t& r3,
                                             uint32_t addr) {
    asm volatile("ldmatrix.sync.aligned.m8n8.x4.trans.shared.b16 {%0,%1,%2,%3}, [%4];"
                 : "=r"(r0), "=r"(r1), "=r"(r2), "=r"(r3) : "r"(addr));
}
__device__ __forceinline__ uint32_t pack2h(__half a, __half b) {
    return ((uint32_t)*(uint16_t*)&b << 16) | *(uint16_t*)&a;
}
__device__ __forceinline__ void split_f16(float v, __half& h, __half& l) {
    h = __float2half_rn(v);
    l = __float2half_rn(v - __half2float(h));
}

// ---------------- kernel 0: fused convx + pack ----------------
// blocks [0, CONV_BLOCKS): X -> fp16 hi/lo ; blocks [CONV_BLOCKS, +PACK_BLOCKS): weights+bias
#define CONV_BLOCKS ((int)(((size_t)MROWS * IN_DIM / 8) / 256))   // 8192
#define PACK_BLOCKS ((NPROJ * IN_DIM + 255) / 256)                // 1408

__global__ void __launch_bounds__(256) convpack_kernel(
    const float* __restrict__ X,
    const float* __restrict__ Wv, const float* __restrict__ bv,
    const float* __restrict__ Wk, const float* __restrict__ bk,
    const float* __restrict__ Wq, const float* __restrict__ bq,
    const float* __restrict__ Wa, const float* __restrict__ ba) {
    if (blockIdx.x < CONV_BLOCKS) {
        size_t e0 = ((size_t)blockIdx.x * 256 + threadIdx.x) * 8;
        float4 v0 = *(const float4*)&X[e0];
        float4 v1 = *(const float4*)&X[e0 + 4];
        float f[8] = {v0.x, v0.y, v0.z, v0.w, v1.x, v1.y, v1.z, v1.w};
        __align__(16) __half hh[8], ll[8];
#pragma unroll
        for (int i = 0; i < 8; i++) split_f16(f[i], hh[i], ll[i]);
        *(uint4*)&g_Xh[e0] = *(uint4*)hh;
        *(uint4*)&g_Xl[e0] = *(uint4*)ll;
    } else {
        int idx = (blockIdx.x - CONV_BLOCKS) * 256 + threadIdx.x;
        if (idx < NPROJ * IN_DIM) {
            int o = idx >> 9, i = idx & 511;
            float v;
            if (o < 512)       v = Wv[o * IN_DIM + i];
            else if (o < 576)  v = Wk[(o - 512) * IN_DIM + i];
            else if (o < 640)  v = Wq[(o - 576) * IN_DIM + i];
            else               v = Wa[(o - 640) * IN_DIM + i];
            __half h, l; split_f16(v, h, l);
            g_Wh[idx] = h;
            g_Wl[idx] = l;
        }
        if (idx < NPROJ) {
            float v;
            if (idx < 512)      v = bv[idx];
            else if (idx < 576) v = bk[idx - 512];
            else if (idx < 640) v = bq[idx - 576];
            else                v = ba[idx - 640];
            g_bias[idx] = v;
        }
    }
}

// ---------------- kernel 2: projection GEMM, M=128 N=64 tile ----------------------
// v tiles (bx<8): 1-term. k/q tiles (bx=8,9): 2-term (Xh*Wh + Xh*Wl). alpha (bx=10): 3-term.
#define GP 72
#define GSTAGE ((2 * 128 + 2 * 64) * GP)      // fp16 elems per stage
#define GM_SMEM (2 * GSTAGE * 2)              // 110592 bytes -> 2 CTAs/SM

__global__ void __launch_bounds__(256, 2) gemm_mma_kernel() {
    extern __shared__ __half sm_b[];
    uint32_t sb = smem_u32(sm_b);

    int tid = threadIdx.x, wid = tid >> 5, lane = tid & 31;
    int g = lane >> 2, tig = lane & 3;
    int lq = lane & 7, lseg = lane >> 3;
    int wm = wid >> 1;               // 0..3 -> 32 rows each
    int wn = wid & 1;                // 0..1 -> 32 cols each
    int bx = blockIdx.x;             // n tile 0..10
    int m0 = blockIdx.y * 128;
    int n0 = bx * 64;
    bool need2 = (bx >= 8);          // k/q/alpha: use W lo term
    bool need3 = (bx == 10);         // alpha only: also X lo term

    float acc[2][4][4];
#pragma unroll
    for (int i = 0; i < 2; i++)
#pragma unroll
        for (int j = 0; j < 4; j++)
#pragma unroll
            for (int k = 0; k < 4; k++) acc[i][j][k] = 0.f;

#define GCOPY(ch, buf) do {                                                              \
    uint32_t base = sb + (uint32_t)(buf) * (GSTAGE * 2);                                 \
    _Pragma("unroll")                                                                    \
    for (int u = 0; u < 4; u++) {                                                        \
        int l = tid + u * 256;               /* 0..1023 */                               \
        int rr = l >> 3, qq = l & 7;                                                     \
        size_t gx = (size_t)(m0 + rr) * IN_DIM + (ch) * 64 + qq * 8;                     \
        uint32_t so = (uint32_t)(rr * GP + qq * 8) * 2;                                  \
        cp16(base + so, &g_Xh[gx]);                                                      \
        if (need3) cp16(base + 128 * GP * 2 + so, &g_Xl[gx]);                            \
    }                                                                                    \
    _Pragma("unroll")                                                                    \
    for (int u = 0; u < 2; u++) {                                                        \
        int l = tid + u * 256;               /* 0..511 */                                \
        int rr = l >> 3, qq = l & 7;                                                     \
        size_t gw = (size_t)(n0 + rr) * IN_DIM + (ch) * 64 + qq * 8;                     \
        uint32_t so = (uint32_t)(rr * GP + qq * 8) * 2;                                  \
        cp16(base + 2 * 128 * GP * 2 + so, &g_Wh[gw]);                                   \
        if (need2) cp16(base + (2 * 128 + 64) * GP * 2 + so, &g_Wl[gw]);                 \
    }                                                                                    \
} while (0)

    GCOPY(0, 0);
    CP_COMMIT();

    int arow = (lseg & 1) * 8 + lq;
    int asel = (lseg >> 1) * 8;
    int brow = (lseg >> 1) * 8 + lq;
    int bsel = (lseg & 1) * 8;

    for (int ch = 0; ch < 8; ch++) {
        if (ch + 1 < 8) { GCOPY(ch + 1, (ch + 1) & 1); CP_COMMIT(); }
        if (ch + 1 < 8) CP_WAIT(1); else CP_WAIT(0);
        __syncthreads();

        uint32_t uXh = sb + (uint32_t)(ch & 1) * (GSTAGE * 2);
        uint32_t uXl = uXh + 128 * GP * 2;
        uint32_t uWh = uXl + 128 * GP * 2;
        uint32_t uWl = uWh + 64 * GP * 2;

#pragma unroll
        for (int ks = 0; ks < 64; ks += 16) {
            uint32_t Ah[2][4], Al[2][4], Bh[4][2], Bl[4][2];
#pragma unroll
            for (int mi = 0; mi < 2; mi++) {
                uint32_t off = (uint32_t)((wm * 32 + mi * 16 + arow) * GP + ks + asel) * 2;
                ldm_x4(Ah[mi][0], Ah[mi][1], Ah[mi][2], Ah[mi][3], uXh + off);
                if (need3) ldm_x4(Al[mi][0], Al[mi][1], Al[mi][2], Al[mi][3], uXl + off);
            }
#pragma unroll
            for (int njp = 0; njp < 2; njp++) {
                uint32_t off = (uint32_t)((wn * 32 + njp * 16 + brow) * GP + ks + bsel) * 2;
                ldm_x4(Bh[njp * 2][0], Bh[njp * 2][1], Bh[njp * 2 + 1][0], Bh[njp * 2 + 1][1], uWh + off);
                if (need2) ldm_x4(Bl[njp * 2][0], Bl[njp * 2][1], Bl[njp * 2 + 1][0], Bl[njp * 2 + 1][1], uWl + off);
            }
#pragma unroll
            for (int mi = 0; mi < 2; mi++)
#pragma unroll
                for (int nj = 0; nj < 4; nj++) {
                    mma_f16(acc[mi][nj], Ah[mi], Bh[nj]);
                    if (need2) mma_f16(acc[mi][nj], Ah[mi], Bl[nj]);
                    if (need3) mma_f16(acc[mi][nj], Al[mi], Bh[nj]);
                }
        }
        __syncthreads();
    }

    bool alpha_tile = (bx == 10);
    bool v_tile = (bx < 8);
#pragma unroll
    for (int mi = 0; mi < 2; mi++) {
        int r0 = m0 + wm * 32 + mi * 16 + g;
#pragma unroll
        for (int nj = 0; nj < 4; nj++) {
            int col = n0 + wn * 32 + nj * 8 + tig * 2;
            float b0 = g_bias[col], b1 = g_bias[col + 1];
            float v0 = acc[mi][nj][0] + b0, v1 = acc[mi][nj][1] + b1;
            float v2 = acc[mi][nj][2] + b0, v3 = acc[mi][nj][3] + b1;
            if (v_tile) {
                *(uint32_t*)&g_Vh[(size_t)r0 * D_V + col] =
                    pack2h(__float2half_rn(v0), __float2half_rn(v1));
                *(uint32_t*)&g_Vh[(size_t)(r0 + 8) * D_V + col] =
                    pack2h(__float2half_rn(v2), __float2half_rn(v3));
            } else {
                if (alpha_tile) {
                    v0 = 1.f / (1.f + expf(-v0));
                    v1 = 1.f / (1.f + expf(-v1));
                    v2 = 1.f / (1.f + expf(-v2));
                    v3 = 1.f / (1.f + expf(-v3));
                }
                float2 lo; lo.x = v0; lo.y = v1;
                float2 hi; hi.x = v2; hi.y = v3;
                *(float2*)&g_proj[(size_t)r0 * NPROJ + col] = lo;
                *(float2*)&g_proj[(size_t)(r0 + 8) * NPROJ + col] = hi;
            }
        }
    }
#undef GCOPY
}

// ---------------- kernel 3: per-chunk prep -> p, kpe(fp16), AQ(fp16) -------------
#define PREP_SMEM (3 * 128 * 65 * 4)
__global__ void __launch_bounds__(256) prep_kernel() {
    extern __shared__ float sm[];
    float* sp  = sm;                 // [128][65] cumulative decay p
    float* sqt = sm + 128 * 65;      // [128][65] q_t
    float* skt = sm + 2 * 128 * 65;  // [128][65] k_t (also alpha temp)

    int b = blockIdx.x, c = blockIdx.y;
    int tid = threadIdx.x;
    size_t aqbase = (size_t)(c * BATCH + b) * CHUNK * AQW;
    size_t kbase  = (size_t)(c * BATCH + b) * CHUNK * D_K;

#pragma unroll
    for (int j = 0; j < 8; j++) {
        int l  = tid + j * 256;
        int t  = l >> 4;
        int c4 = (l & 15) * 4;
        const float* rowp = g_proj + (size_t)((c * CHUNK + t) * BATCH + b) * NPROJ;
        float4 av = *(const float4*)&rowp[640 + c4];
        skt[t * 65 + c4 + 0] = av.x; skt[t * 65 + c4 + 1] = av.y;
        skt[t * 65 + c4 + 2] = av.z; skt[t * 65 + c4 + 3] = av.w;
    }
    __syncthreads();

    if (tid < D_K) {
        float p = 1.f;
        for (int t = 0; t < CHUNK; t++) {
            p *= fmaxf(skt[t * 65 + tid], EPS_F);
            sp[t * 65 + tid] = p;
        }
        g_pend[(c * BATCH + b) * D_K + tid] = p;
    }
    __syncthreads();

#pragma unroll
    for (int j = 0; j < 8; j++) {
        int l  = tid + j * 256;
        int t  = l >> 4;
        int c4 = (l & 15) * 4;
        const float* rowp = g_proj + (size_t)((c * CHUNK + t) * BATCH + b) * NPROJ;
        float4 qv = *(const float4*)&rowp[576 + c4];
        float4 kv = *(const float4*)&rowp[512 + c4];
        float p0 = sp[t * 65 + c4 + 0], p1 = sp[t * 65 + c4 + 1];
        float p2 = sp[t * 65 + c4 + 2], p3 = sp[t * 65 + c4 + 3];
        float pe0 = sp[127 * 65 + c4 + 0], pe1 = sp[127 * 65 + c4 + 1];
        float pe2 = sp[127 * 65 + c4 + 2], pe3 = sp[127 * 65 + c4 + 3];
        float q0 = qv.x * p0, q1 = qv.y * p1, q2 = qv.z * p2, q3 = qv.w * p3;
        float k0 = kv.x / (p0 + EPS_F), k1 = kv.y / (p1 + EPS_F);
        float k2 = kv.z / (p2 + EPS_F), k3 = kv.w / (p3 + EPS_F);
        sqt[t * 65 + c4 + 0] = q0; sqt[t * 65 + c4 + 1] = q1;
        sqt[t * 65 + c4 + 2] = q2; sqt[t * 65 + c4 + 3] = q3;
        skt[t * 65 + c4 + 0] = k0; skt[t * 65 + c4 + 1] = k1;
        skt[t * 65 + c4 + 2] = k2; skt[t * 65 + c4 + 3] = k3;
        __half h0 = __float2half_rn(q0), h1 = __float2half_rn(q1);
        __half h2 = __float2half_rn(q2), h3 = __float2half_rn(q3);
        uint32_t* ph = (uint32_t*)&g_AQh[aqbase + t * AQW + 128 + c4];
        ph[0] = pack2h(h0, h1); ph[1] = pack2h(h2, h3);
        __half e0 = __float2half_rn(k0 * pe0), e1 = __float2half_rn(k1 * pe1);
        __half e2 = __float2half_rn(k2 * pe2), e3 = __float2half_rn(k3 * pe3);
        uint32_t* kh = (uint32_t*)&g_kpeh[kbase + t * D_K + c4];
        kh[0] = pack2h(e0, e1); kh[1] = pack2h(e2, e3);
    }
    __syncthreads();

    // A[t][s] = sum_n q_t[t][n] * k_t[s][n], masked t>=s -> fp16
    int sxl = tid & 15;
    int t0  = (tid >> 4) * 8;
    float acc[8][8];
#pragma unroll
    for (int i = 0; i < 8; i++)
#pragma unroll
        for (int j = 0; j < 8; j++) acc[i][j] = 0.f;

    for (int n = 0; n < D_K; n++) {
        float qv[8], kv[8];
#pragma unroll
        for (int i = 0; i < 8; i++) qv[i] = sqt[(t0 + i) * 65 + n];
#pragma unroll
        for (int j = 0; j < 8; j++) kv[j] = skt[(sxl + 16 * j) * 65 + n];
#pragma unroll
        for (int i = 0; i < 8; i++)
#pragma unroll
            for (int j = 0; j < 8; j++)
                acc[i][j] = fmaf(qv[i], kv[j], acc[i][j]);
    }
#pragma unroll
    for (int i = 0; i < 8; i++) {
        int t = t0 + i;
#pragma unroll
        for (int j = 0; j < 8; j++) {
            int s = sxl + 16 * j;
            float val = (t >= s) ? acc[i][j] : 0.f;
            g_AQh[aqbase + t * AQW + s] = __float2half_rn(val);
        }
    }
}

// ---------------- kernel 4: contrib via HMMA 1-term: Wc[n][d] = kpe^T @ v ---------
#define CPP 72
#define CM_SMEM (2 * 128 * CPP * 2)

__global__ void __launch_bounds__(256) contrib_kernel() {
    extern __shared__ __half csm[];
    uint32_t uKh = smem_u32(csm);
    uint32_t uVh = uKh + 128 * CPP * 2;

    int d0 = blockIdx.x * 64, c = blockIdx.y, b = blockIdx.z;
    int tid = threadIdx.x, wid = tid >> 5, lane = tid & 31;
    int g = lane >> 2, tig = lane & 3;
    int lq = lane & 7, lseg = lane >> 3;
    int wn = wid & 1;                // n half: 32 rows
    int wd = wid >> 1;               // d quarter: 16 cols

    size_t kbase = (size_t)(c * BATCH + b) * CHUNK * D_K;

#pragma unroll
    for (int u = 0; u < 2; u++) {
        int l = tid + u * 256;       // rows 0..63
        int rr = l >> 3, qq = l & 7;
        uint32_t so = (uint32_t)(rr * CPP + qq * 8) * 2;
        cp16(uKh + so, &g_kpeh[kbase + rr * D_K + qq * 8]);
        size_t vs = (size_t)((c * CHUNK + rr) * BATCH + b) * D_V + d0 + qq * 8;
        cp16(uVh + so, &g_Vh[vs]);
    }
    CP_COMMIT();
#pragma unroll
    for (int u = 2; u < 4; u++) {
        int l = tid + u * 256;       // rows 64..127
        int rr = l >> 3, qq = l & 7;
        uint32_t so = (uint32_t)(rr * CPP + qq * 8) * 2;
        cp16(uKh + so, &g_kpeh[kbase + rr * D_K + qq * 8]);
        size_t vs = (size_t)((c * CHUNK + rr) * BATCH + b) * D_V + d0 + qq * 8;
        cp16(uVh + so, &g_Vh[vs]);
    }
    CP_COMMIT();

    float acc[2][2][4];
#pragma unroll
    for (int i = 0; i < 2; i++)
#pragma unroll
        for (int j = 0; j < 2; j++)
#pragma unroll
            for (int k = 0; k < 4; k++) acc[i][j][k] = 0.f;

#pragma unroll
    for (int half = 0; half < 2; half++) {
        if (half == 0) CP_WAIT(1); else CP_WAIT(0);
        __syncthreads();
#pragma unroll
        for (int kk = 0; kk < 64; kk += 16) {
            int ks = half * 64 + kk;
            uint32_t Ah[2][4], Bh[2][2];
            uint32_t arow = ks + (lseg >> 1) * 8 + lq;
#pragma unroll
            for (int mi = 0; mi < 2; mi++) {
                uint32_t col = wn * 32 + mi * 16 + (lseg & 1) * 8;
                uint32_t off = (arow * CPP + col) * 2;
                ldm_x4_trans(Ah[mi][0], Ah[mi][1], Ah[mi][2], Ah[mi][3], uKh + off);
            }
            {
                uint32_t brow = ks + (lseg & 1) * 8 + lq;
                uint32_t col = wd * 16 + (lseg >> 1) * 8;
                uint32_t off = (brow * CPP + col) * 2;
                ldm_x4_trans(Bh[0][0], Bh[0][1], Bh[1][0], Bh[1][1], uVh + off);
            }
#pragma unroll
            for (int mi = 0; mi < 2; mi++)
#pragma unroll
                for (int nj = 0; nj < 2; nj++)
                    mma_f16(acc[mi][nj], Ah[mi], Bh[nj]);
        }
    }

    float* Wb = g_Wc + (size_t)(c * BATCH + b) * D_K * D_V;
#pragma unroll
    for (int mi = 0; mi < 2; mi++) {
        int n = wn * 32 + mi * 16 + g;
#pragma unroll
        for (int nj = 0; nj < 2; nj++) {
            int d = d0 + wd * 16 + nj * 8 + tig * 2;
            float2 lo; lo.x = acc[mi][nj][0]; lo.y = acc[mi][nj][1];
            float2 hi; hi.x = acc[mi][nj][2]; hi.y = acc[mi][nj][3];
            *(float2*)&Wb[(size_t)n * D_V + d] = lo;
            *(float2*)&Wb[(size_t)(n + 8) * D_V + d] = hi;
        }
    }
}

// ---------------- kernel 5: elementwise state scan; emit S_start fp16 -------------
__global__ void __launch_bounds__(256) state_scan_kernel() {
    int g = blockIdx.x * 256 + threadIdx.x;  // g = (b*64+n)*512 + d
    int bn = g >> 9;
    float s = 0.f;
    for (int c = 0; c < NC; c++) {
        size_t idx = (size_t)c * SEG + g;
        g_Sh[idx] = __float2half_rn(s);
        s = fmaf(s, g_pend[c * (BATCH * D_K) + bn], g_Wc[idx]);
    }
}

// ---------------- kernel 6: Y = [A|q_t] @ [V;S], 1-term, causal-zero skip ---------
#define YP 72
#define YSTAGE ((128 + 64) * YP)             // fp16 elems per stage (A + B)
#define YG_SMEM (2 * YSTAGE * 2)             // 55296 bytes -> 4 CTAs/SM

__global__ void __launch_bounds__(128, 4) ygemm_mma_kernel(float* __restrict__ out) {
    extern __shared__ __half ysm[];
    uint32_t sb = smem_u32(ysm);

    int d0 = blockIdx.x * 64;
    int c = blockIdx.y, b = blockIdx.z;
    int tid = threadIdx.x, w = tid >> 5, lane = tid & 31;
    int g = lane >> 2, tig = lane & 3;
    int lq = lane & 7, lseg = lane >> 3;
    int arow = (lseg & 1) * 8 + lq;
    int asel = (lseg >> 1) * 8;

    size_t aqbase = (size_t)(c * BATCH + b) * CHUNK * AQW;
    size_t sbase  = (size_t)(c * BATCH + b) * D_K * D_V;

    float acc[2][8][4];
#pragma unroll
    for (int i = 0; i < 2; i++)
#pragma unroll
        for (int j = 0; j < 8; j++)
#pragma unroll
            for (int k = 0; k < 4; k++) acc[i][j][k] = 0.f;

#define YCOPY(ch, buf) do {                                                              \
    uint32_t base = sb + (uint32_t)(buf) * (YSTAGE * 2);                                 \
    _Pragma("unroll")                                                                    \
    for (int u = 0; u < 8; u++) {                                                        \
        int l = tid + u * 128;               /* 0..1023 */                               \
        int rr = l >> 3, qq = l & 7;                                                     \
        size_t src = aqbase + rr * AQW + (ch) * 64 + qq * 8;                             \
        uint32_t so = (uint32_t)(rr * YP + qq * 8) * 2;                                  \
        cp16(base + so, &g_AQh[src]);                                                    \
    }                                                                                    \
    _Pragma("unroll")                                                                    \
    for (int u = 0; u < 4; u++) {                                                        \
        int l = tid + u * 128;               /* 0..511 */                                \
        int rr = l >> 3, qq = l & 7;                                                     \
        uint32_t so = (uint32_t)(rr * YP + qq * 8) * 2;                                  \
        if ((ch) < 2) {                                                                  \
            size_t src = (size_t)((c * CHUNK + (ch) * 64 + rr) * BATCH + b) * D_V + d0 + qq * 8; \
            cp16(base + 128 * YP * 2 + so, &g_Vh[src]);                                  \
        } else {                                                                         \
            size_t src = sbase + (size_t)rr * D_V + d0 + qq * 8;                         \
            cp16(base + 128 * YP * 2 + so, &g_Sh[src]);                                  \
        }                                                                                \
    }                                                                                    \
} while (0)

    YCOPY(0, 0);
    CP_COMMIT();

    for (int ch = 0; ch < 3; ch++) {
        if (ch + 1 < 3) { YCOPY(ch + 1, (ch + 1) & 1); CP_COMMIT(); }
        if (ch + 1 < 3) CP_WAIT(1); else CP_WAIT(0);
        __syncthreads();

        // causal-zero skip: ch==1 uses A cols s=64..127 which are zero for t<64
        // (warps 0,1); ch==2 uses S which is identically zero for c==0.
        bool active = !(ch == 1 && w < 2) && !(ch == 2 && c == 0);
        if (active) {
            uint32_t uAh = sb + (uint32_t)(ch & 1) * (YSTAGE * 2);
            uint32_t uBh = uAh + 128 * YP * 2;

#pragma unroll
            for (int ks = 0; ks < 64; ks += 16) {
                uint32_t Ah[2][4], Bh[8][2];
#pragma unroll
                for (int mi = 0; mi < 2; mi++) {
                    uint32_t off = (uint32_t)((w * 32 + mi * 16 + arow) * YP + ks + asel) * 2;
                    ldm_x4(Ah[mi][0], Ah[mi][1], Ah[mi][2], Ah[mi][3], uAh + off);
                }
                uint32_t row = ks + (lseg & 1) * 8 + lq;
#pragma unroll
                for (int nbs = 0; nbs < 4; nbs++) {
                    uint32_t col = nbs * 16 + (lseg >> 1) * 8;
                    uint32_t off = (row * YP + col) * 2;
                    ldm_x4_trans(Bh[nbs * 2][0], Bh[nbs * 2][1], Bh[nbs * 2 + 1][0], Bh[nbs * 2 + 1][1], uBh + off);
                }
#pragma unroll
                for (int mi = 0; mi < 2; mi++)
#pragma unroll
                    for (int nj = 0; nj < 8; nj++)
                        mma_f16(acc[mi][nj], Ah[mi], Bh[nj]);
            }
        }
        __syncthreads();
    }
#undef YCOPY

#pragma unroll
    for (int mi = 0; mi < 2; mi++) {
        int t = w * 32 + mi * 16 + g;
#pragma unroll
        for (int nj = 0; nj < 8; nj++) {
            int col = d0 + nj * 8 + tig * 2;
            float2 lo; lo.x = acc[mi][nj][0]; lo.y = acc[mi][nj][1];
            float2 hi; hi.x = acc[mi][nj][2]; hi.y = acc[mi][nj][3];
            *(float2*)&out[(size_t)((c * CHUNK + t) * BATCH + b) * D_V + col] = lo;
            *(float2*)&out[(size_t)((c * CHUNK + t + 8) * BATCH + b) * D_V + col] = hi;
        }
    }
}

// ---------------- launch ----------------
extern "C" void kernel_launch(void* const* d_in, const int* in_sizes, int n_in,
                              void* d_out, int out_size) {
    const float* x  = (const float*)d_in[0];
    const float* Wv = (const float*)d_in[1];
    const float* bv = (const float*)d_in[2];
    const float* Wk = (const float*)d_in[3];
    const float* bk = (const float*)d_in[4];
    const float* Wq = (const float*)d_in[5];
    const float* bq = (const float*)d_in[6];
    const float* Wa = (const float*)d_in[7];
    const float* ba = (const float*)d_in[8];
    float* out = (float*)d_out;

    cudaFuncSetAttribute(prep_kernel, cudaFuncAttributeMaxDynamicSharedMemorySize, PREP_SMEM);
    cudaFuncSetAttribute(gemm_mma_kernel, cudaFuncAttributeMaxDynamicSharedMemorySize, GM_SMEM);
    cudaFuncSetAttribute(contrib_kernel, cudaFuncAttributeMaxDynamicSharedMemorySize, CM_SMEM);
    cudaFuncSetAttribute(ygemm_mma_kernel, cudaFuncAttributeMaxDynamicSharedMemorySize, YG_SMEM);

    convpack_kernel<<<CONV_BLOCKS + PACK_BLOCKS, 256>>>(x, Wv, bv, Wk, bk, Wq, bq, Wa, ba);
    gemm_mma_kernel<<<dim3(11, MROWS / 128), 256, GM_SMEM>>>();
    prep_kernel<<<dim3(BATCH, NC), 256, PREP_SMEM>>>();
    contrib_kernel<<<dim3(D_V / 64, NC, BATCH), 256, CM_SMEM>>>();
    state_scan_kernel<<<SEG / 256, 256>>>();
    ygemm_mma_kernel<<<dim3(D_V / 64, NC, BATCH), 128, YG_SMEM>>>(out);
}

// round 15
// speedup vs baseline: 4.5788x; 1.0021x over previous
#include <cuda_runtime.h>
#include <cuda_fp16.h>
#include <math.h>
#include <stdint.h>

#define T_LEN   8192
#define BATCH   4
#define IN_DIM  512
#define D_V     512
#define D_K     64
#define CHUNK   128
#define NC      (T_LEN / CHUNK)          // 64
#define NPROJ   (D_V + 3 * D_K)          // 704 = 11 * 64
#define MROWS   (T_LEN * BATCH)          // 32768
#define EPS_F   1e-8f
#define SEG     (BATCH * D_K * D_V)      // 131072 state elements
#define AQW     192                      // A(128) | qt(64) fused row width

// ---------------- static device scratch ----------------
__device__ __align__(128) float g_bias[NPROJ];
__device__ __align__(128) __half g_Wh[NPROJ * IN_DIM];
__device__ __align__(128) __half g_Wl[NPROJ * IN_DIM];
__device__ __align__(128) __half g_Xh[(size_t)MROWS * IN_DIM];
__device__ __align__(128) __half g_Xl[(size_t)MROWS * IN_DIM];
__device__ __align__(128) float g_proj[(size_t)MROWS * NPROJ];             // only cols 512.. written/read
__device__ __align__(128) __half g_Vh[(size_t)MROWS * D_V];                // v fp16 [r][512]
__device__ __align__(128) __half g_AQh[(size_t)NC * BATCH * CHUNK * AQW];  // [c][b][t][A|qt]
__device__ __align__(128) __half g_kpeh[(size_t)NC * BATCH * CHUNK * D_K];
__device__ __align__(128) float g_pend[NC * BATCH * D_K];
__device__ __align__(128) float g_Wc[(size_t)NC * SEG];
__device__ __align__(128) __half g_Sh[(size_t)NC * SEG];                   // S_start [c][b][n][d]

// ---------------- helpers ----------------
__device__ __forceinline__ uint32_t smem_u32(const void* p) {
    uint32_t a;
    asm("{ .reg .u64 t; cvta.to.shared.u64 t, %1; cvt.u32.u64 %0, t; }" : "=r"(a) : "l"(p));
    return a;
}
__device__ __forceinline__ void cp16(uint32_t dst, const void* src) {
    asm volatile("cp.async.cg.shared.global [%0], [%1], 16;" :: "r"(dst), "l"(src));
}
#define CP_COMMIT() asm volatile("cp.async.commit_group;")
#define CP_WAIT(n)  asm volatile("cp.async.wait_group %0;" :: "n"(n))

__device__ __forceinline__ void mma_f16(float* c, const uint32_t* a, const uint32_t* b) {
    asm volatile(
        "mma.sync.aligned.m16n8k16.row.col.f32.f16.f16.f32 "
        "{%0,%1,%2,%3}, {%4,%5,%6,%7}, {%8,%9}, {%0,%1,%2,%3};"
        : "+f"(c[0]), "+f"(c[1]), "+f"(c[2]), "+f"(c[3])
        : "r"(a[0]), "r"(a[1]), "r"(a[2]), "r"(a[3]), "r"(b[0]), "r"(b[1]));
}
__device__ __forceinline__ void ldm_x4(uint32_t& r0, uint32_t& r1, uint32_t& r2, uint32_t& r3,
                                       uint32_t addr) {
    asm volatile("ldmatrix.sync.aligned.m8n8.x4.shared.b16 {%0,%1,%2,%3}, [%4];"
                 : "=r"(r0), "=r"(r1), "=r"(r2), "=r"(r3) : "r"(addr));
}
__device__ __forceinline__ void ldm_x4_trans(uint32_t& r0, uint32_t& r1, uint32_t& r2, uint32_t& r3,
                                             uint32_t addr) {
    asm volatile("ldmatrix.sync.aligned.m8n8.x4.trans.shared.b16 {%0,%1,%2,%3}, [%4];"
                 : "=r"(r0), "=r"(r1), "=r"(r2), "=r"(r3) : "r"(addr));
}
__device__ __forceinline__ uint32_t pack2h(__half a, __half b) {
    return ((uint32_t)*(uint16_t*)&b << 16) | *(uint16_t*)&a;
}
__device__ __forceinline__ void split_f16(float v, __half& h, __half& l) {
    h = __float2half_rn(v);
    l = __float2half_rn(v - __half2float(h));
}

// ---------------- kernel 0: fused convx + pack ----------------
#define CONV_BLOCKS ((int)(((size_t)MROWS * IN_DIM / 8) / 256))   // 8192
#define PACK_BLOCKS ((NPROJ * IN_DIM + 255) / 256)                // 1408

__global__ void __launch_bounds__(256) convpack_kernel(
    const float* __restrict__ X,
    const float* __restrict__ Wv, const float* __restrict__ bv,
    const float* __restrict__ Wk, const float* __restrict__ bk,
    const float* __restrict__ Wq, const float* __restrict__ bq,
    const float* __restrict__ Wa, const float* __restrict__ ba) {
    if (blockIdx.x < CONV_BLOCKS) {
        size_t e0 = ((size_t)blockIdx.x * 256 + threadIdx.x) * 8;
        float4 v0 = *(const float4*)&X[e0];
        float4 v1 = *(const float4*)&X[e0 + 4];
        float f[8] = {v0.x, v0.y, v0.z, v0.w, v1.x, v1.y, v1.z, v1.w};
        __align__(16) __half hh[8], ll[8];
#pragma unroll
        for (int i = 0; i < 8; i++) split_f16(f[i], hh[i], ll[i]);
        *(uint4*)&g_Xh[e0] = *(uint4*)hh;
        *(uint4*)&g_Xl[e0] = *(uint4*)ll;
    } else {
        int idx = (blockIdx.x - CONV_BLOCKS) * 256 + threadIdx.x;
        if (idx < NPROJ * IN_DIM) {
            int o = idx >> 9, i = idx & 511;
            float v;
            if (o < 512)       v = Wv[o * IN_DIM + i];
            else if (o < 576)  v = Wk[(o - 512) * IN_DIM + i];
            else if (o < 640)  v = Wq[(o - 576) * IN_DIM + i];
            else               v = Wa[(o - 640) * IN_DIM + i];
            __half h, l; split_f16(v, h, l);
            g_Wh[idx] = h;
            g_Wl[idx] = l;
        }
        if (idx < NPROJ) {
            float v;
            if (idx < 512)      v = bv[idx];
            else if (idx < 576) v = bk[idx - 512];
            else if (idx < 640) v = bq[idx - 576];
            else                v = ba[idx - 640];
            g_bias[idx] = v;
        }
    }
}

// ---------------- kernel 2: projection GEMM, M=128 N=64 tile ----------------------
// v tiles (bx<8): 1-term. k/q tiles (bx=8,9): 2-term. alpha (bx=10): 3-term.
#define GP 72
#define GSTAGE ((2 * 128 + 2 * 64) * GP)
#define GM_SMEM (2 * GSTAGE * 2)

__global__ void __launch_bounds__(256, 2) gemm_mma_kernel() {
    extern __shared__ __half sm_b[];
    uint32_t sb = smem_u32(sm_b);

    int tid = threadIdx.x, wid = tid >> 5, lane = tid & 31;
    int g = lane >> 2, tig = lane & 3;
    int lq = lane & 7, lseg = lane >> 3;
    int wm = wid >> 1;
    int wn = wid & 1;
    int bx = blockIdx.x;
    int m0 = blockIdx.y * 128;
    int n0 = bx * 64;
    bool need2 = (bx >= 8);
    bool need3 = (bx == 10);

    float acc[2][4][4];
#pragma unroll
    for (int i = 0; i < 2; i++)
#pragma unroll
        for (int j = 0; j < 4; j++)
#pragma unroll
            for (int k = 0; k < 4; k++) acc[i][j][k] = 0.f;

#define GCOPY(ch, buf) do {                                                              \
    uint32_t base = sb + (uint32_t)(buf) * (GSTAGE * 2);                                 \
    _Pragma("unroll")                                                                    \
    for (int u = 0; u < 4; u++) {                                                        \
        int l = tid + u * 256;                                                           \
        int rr = l >> 3, qq = l & 7;                                                     \
        size_t gx = (size_t)(m0 + rr) * IN_DIM + (ch) * 64 + qq * 8;                     \
        uint32_t so = (uint32_t)(rr * GP + qq * 8) * 2;                                  \
        cp16(base + so, &g_Xh[gx]);                                                      \
        if (need3) cp16(base + 128 * GP * 2 + so, &g_Xl[gx]);                            \
    }                                                                                    \
    _Pragma("unroll")                                                                    \
    for (int u = 0; u < 2; u++) {                                                        \
        int l = tid + u * 256;                                                           \
        int rr = l >> 3, qq = l & 7;                                                     \
        size_t gw = (size_t)(n0 + rr) * IN_DIM + (ch) * 64 + qq * 8;                     \
        uint32_t so = (uint32_t)(rr * GP + qq * 8) * 2;                                  \
        cp16(base + 2 * 128 * GP * 2 + so, &g_Wh[gw]);                                   \
        if (need2) cp16(base + (2 * 128 + 64) * GP * 2 + so, &g_Wl[gw]);                 \
    }                                                                                    \
} while (0)

    GCOPY(0, 0);
    CP_COMMIT();

    int arow = (lseg & 1) * 8 + lq;
    int asel = (lseg >> 1) * 8;
    int brow = (lseg >> 1) * 8 + lq;
    int bsel = (lseg & 1) * 8;

    for (int ch = 0; ch < 8; ch++) {
        if (ch + 1 < 8) { GCOPY(ch + 1, (ch + 1) & 1); CP_COMMIT(); }
        if (ch + 1 < 8) CP_WAIT(1); else CP_WAIT(0);
        __syncthreads();

        uint32_t uXh = sb + (uint32_t)(ch & 1) * (GSTAGE * 2);
        uint32_t uXl = uXh + 128 * GP * 2;
        uint32_t uWh = uXl + 128 * GP * 2;
        uint32_t uWl = uWh + 64 * GP * 2;

#pragma unroll
        for (int ks = 0; ks < 64; ks += 16) {
            uint32_t Ah[2][4], Al[2][4], Bh[4][2], Bl[4][2];
#pragma unroll
            for (int mi = 0; mi < 2; mi++) {
                uint32_t off = (uint32_t)((wm * 32 + mi * 16 + arow) * GP + ks + asel) * 2;
                ldm_x4(Ah[mi][0], Ah[mi][1], Ah[mi][2], Ah[mi][3], uXh + off);
                if (need3) ldm_x4(Al[mi][0], Al[mi][1], Al[mi][2], Al[mi][3], uXl + off);
            }
#pragma unroll
            for (int njp = 0; njp < 2; njp++) {
                uint32_t off = (uint32_t)((wn * 32 + njp * 16 + brow) * GP + ks + bsel) * 2;
                ldm_x4(Bh[njp * 2][0], Bh[njp * 2][1], Bh[njp * 2 + 1][0], Bh[njp * 2 + 1][1], uWh + off);
                if (need2) ldm_x4(Bl[njp * 2][0], Bl[njp * 2][1], Bl[njp * 2 + 1][0], Bl[njp * 2 + 1][1], uWl + off);
            }
#pragma unroll
            for (int mi = 0; mi < 2; mi++)
#pragma unroll
                for (int nj = 0; nj < 4; nj++) {
                    mma_f16(acc[mi][nj], Ah[mi], Bh[nj]);
                    if (need2) mma_f16(acc[mi][nj], Ah[mi], Bl[nj]);
                    if (need3) mma_f16(acc[mi][nj], Al[mi], Bh[nj]);
                }
        }
        __syncthreads();
    }

    bool alpha_tile = (bx == 10);
    bool v_tile = (bx < 8);
#pragma unroll
    for (int mi = 0; mi < 2; mi++) {
        int r0 = m0 + wm * 32 + mi * 16 + g;
#pragma unroll
        for (int nj = 0; nj < 4; nj++) {
            int col = n0 + wn * 32 + nj * 8 + tig * 2;
            float b0 = g_bias[col], b1 = g_bias[col + 1];
            float v0 = acc[mi][nj][0] + b0, v1 = acc[mi][nj][1] + b1;
            float v2 = acc[mi][nj][2] + b0, v3 = acc[mi][nj][3] + b1;
            if (v_tile) {
                *(uint32_t*)&g_Vh[(size_t)r0 * D_V + col] =
                    pack2h(__float2half_rn(v0), __float2half_rn(v1));
                *(uint32_t*)&g_Vh[(size_t)(r0 + 8) * D_V + col] =
                    pack2h(__float2half_rn(v2), __float2half_rn(v3));
            } else {
                if (alpha_tile) {
                    v0 = 1.f / (1.f + expf(-v0));
                    v1 = 1.f / (1.f + expf(-v1));
                    v2 = 1.f / (1.f + expf(-v2));
                    v3 = 1.f / (1.f + expf(-v3));
                }
                float2 lo; lo.x = v0; lo.y = v1;
                float2 hi; hi.x = v2; hi.y = v3;
                *(float2*)&g_proj[(size_t)r0 * NPROJ + col] = lo;
                *(float2*)&g_proj[(size_t)(r0 + 8) * NPROJ + col] = hi;
            }
        }
    }
#undef GCOPY
}

// ---------------- kernel 3: per-chunk prep -> p, kpe(fp16), AQ(fp16) -------------
#define PREP_SMEM (3 * 128 * 65 * 4)
__global__ void __launch_bounds__(256) prep_kernel() {
    extern __shared__ float sm[];
    float* sp  = sm;
    float* sqt = sm + 128 * 65;
    float* skt = sm + 2 * 128 * 65;

    int b = blockIdx.x, c = blockIdx.y;
    int tid = threadIdx.x;
    size_t aqbase = (size_t)(c * BATCH + b) * CHUNK * AQW;
    size_t kbase  = (size_t)(c * BATCH + b) * CHUNK * D_K;

#pragma unroll
    for (int j = 0; j < 8; j++) {
        int l  = tid + j * 256;
        int t  = l >> 4;
        int c4 = (l & 15) * 4;
        const float* rowp = g_proj + (size_t)((c * CHUNK + t) * BATCH + b) * NPROJ;
        float4 av = *(const float4*)&rowp[640 + c4];
        skt[t * 65 + c4 + 0] = av.x; skt[t * 65 + c4 + 1] = av.y;
        skt[t * 65 + c4 + 2] = av.z; skt[t * 65 + c4 + 3] = av.w;
    }
    __syncthreads();

    if (tid < D_K) {
        float p = 1.f;
        for (int t = 0; t < CHUNK; t++) {
            p *= fmaxf(skt[t * 65 + tid], EPS_F);
            sp[t * 65 + tid] = p;
        }
        g_pend[(c * BATCH + b) * D_K + tid] = p;
    }
    __syncthreads();

#pragma unroll
    for (int j = 0; j < 8; j++) {
        int l  = tid + j * 256;
        int t  = l >> 4;
        int c4 = (l & 15) * 4;
        const float* rowp = g_proj + (size_t)((c * CHUNK + t) * BATCH + b) * NPROJ;
        float4 qv = *(const float4*)&rowp[576 + c4];
        float4 kv = *(const float4*)&rowp[512 + c4];
        float p0 = sp[t * 65 + c4 + 0], p1 = sp[t * 65 + c4 + 1];
        float p2 = sp[t * 65 + c4 + 2], p3 = sp[t * 65 + c4 + 3];
        float pe0 = sp[127 * 65 + c4 + 0], pe1 = sp[127 * 65 + c4 + 1];
        float pe2 = sp[127 * 65 + c4 + 2], pe3 = sp[127 * 65 + c4 + 3];
        float q0 = qv.x * p0, q1 = qv.y * p1, q2 = qv.z * p2, q3 = qv.w * p3;
        float k0 = kv.x / (p0 + EPS_F), k1 = kv.y / (p1 + EPS_F);
        float k2 = kv.z / (p2 + EPS_F), k3 = kv.w / (p3 + EPS_F);
        sqt[t * 65 + c4 + 0] = q0; sqt[t * 65 + c4 + 1] = q1;
        sqt[t * 65 + c4 + 2] = q2; sqt[t * 65 + c4 + 3] = q3;
        skt[t * 65 + c4 + 0] = k0; skt[t * 65 + c4 + 1] = k1;
        skt[t * 65 + c4 + 2] = k2; skt[t * 65 + c4 + 3] = k3;
        __half h0 = __float2half_rn(q0), h1 = __float2half_rn(q1);
        __half h2 = __float2half_rn(q2), h3 = __float2half_rn(q3);
        uint32_t* ph = (uint32_t*)&g_AQh[aqbase + t * AQW + 128 + c4];
        ph[0] = pack2h(h0, h1); ph[1] = pack2h(h2, h3);
        __half e0 = __float2half_rn(k0 * pe0), e1 = __float2half_rn(k1 * pe1);
        __half e2 = __float2half_rn(k2 * pe2), e3 = __float2half_rn(k3 * pe3);
        uint32_t* kh = (uint32_t*)&g_kpeh[kbase + t * D_K + c4];
        kh[0] = pack2h(e0, e1); kh[1] = pack2h(e2, e3);
    }
    __syncthreads();

    int sxl = tid & 15;
    int t0  = (tid >> 4) * 8;
    float acc[8][8];
#pragma unroll
    for (int i = 0; i < 8; i++)
#pragma unroll
        for (int j = 0; j < 8; j++) acc[i][j] = 0.f;

    for (int n = 0; n < D_K; n++) {
        float qv[8], kv[8];
#pragma unroll
        for (int i = 0; i < 8; i++) qv[i] = sqt[(t0 + i) * 65 + n];
#pragma unroll
        for (int j = 0; j < 8; j++) kv[j] = skt[(sxl + 16 * j) * 65 + n];
#pragma unroll
        for (int i = 0; i < 8; i++)
#pragma unroll
            for (int j = 0; j < 8; j++)
                acc[i][j] = fmaf(qv[i], kv[j], acc[i][j]);
    }
#pragma unroll
    for (int i = 0; i < 8; i++) {
        int t = t0 + i;
#pragma unroll
        for (int j = 0; j < 8; j++) {
            int s = sxl + 16 * j;
            float val = (t >= s) ? acc[i][j] : 0.f;
            g_AQh[aqbase + t * AQW + s] = __float2half_rn(val);
        }
    }
}

// ---------------- kernel 4: contrib via HMMA 1-term ----------------
#define CPP 72
#define CM_SMEM (2 * 128 * CPP * 2)

__global__ void __launch_bounds__(256) contrib_kernel() {
    extern __shared__ __half csm[];
    uint32_t uKh = smem_u32(csm);
    uint32_t uVh = uKh + 128 * CPP * 2;

    int d0 = blockIdx.x * 64, c = blockIdx.y, b = blockIdx.z;
    int tid = threadIdx.x, wid = tid >> 5, lane = tid & 31;
    int g = lane >> 2, tig = lane & 3;
    int lq = lane & 7, lseg = lane >> 3;
    int wn = wid & 1;
    int wd = wid >> 1;

    size_t kbase = (size_t)(c * BATCH + b) * CHUNK * D_K;

#pragma unroll
    for (int u = 0; u < 2; u++) {
        int l = tid + u * 256;
        int rr = l >> 3, qq = l & 7;
        uint32_t so = (uint32_t)(rr * CPP + qq * 8) * 2;
        cp16(uKh + so, &g_kpeh[kbase + rr * D_K + qq * 8]);
        size_t vs = (size_t)((c * CHUNK + rr) * BATCH + b) * D_V + d0 + qq * 8;
        cp16(uVh + so, &g_Vh[vs]);
    }
    CP_COMMIT();
#pragma unroll
    for (int u = 2; u < 4; u++) {
        int l = tid + u * 256;
        int rr = l >> 3, qq = l & 7;
        uint32_t so = (uint32_t)(rr * CPP + qq * 8) * 2;
        cp16(uKh + so, &g_kpeh[kbase + rr * D_K + qq * 8]);
        size_t vs = (size_t)((c * CHUNK + rr) * BATCH + b) * D_V + d0 + qq * 8;
        cp16(uVh + so, &g_Vh[vs]);
    }
    CP_COMMIT();

    float acc[2][2][4];
#pragma unroll
    for (int i = 0; i < 2; i++)
#pragma unroll
        for (int j = 0; j < 2; j++)
#pragma unroll
            for (int k = 0; k < 4; k++) acc[i][j][k] = 0.f;

#pragma unroll
    for (int half = 0; half < 2; half++) {
        if (half == 0) CP_WAIT(1); else CP_WAIT(0);
        __syncthreads();
#pragma unroll
        for (int kk = 0; kk < 64; kk += 16) {
            int ks = half * 64 + kk;
            uint32_t Ah[2][4], Bh[2][2];
            uint32_t arow = ks + (lseg >> 1) * 8 + lq;
#pragma unroll
            for (int mi = 0; mi < 2; mi++) {
                uint32_t col = wn * 32 + mi * 16 + (lseg & 1) * 8;
                uint32_t off = (arow * CPP + col) * 2;
                ldm_x4_trans(Ah[mi][0], Ah[mi][1], Ah[mi][2], Ah[mi][3], uKh + off);
            }
            {
                uint32_t brow = ks + (lseg & 1) * 8 + lq;
                uint32_t col = wd * 16 + (lseg >> 1) * 8;
                uint32_t off = (brow * CPP + col) * 2;
                ldm_x4_trans(Bh[0][0], Bh[0][1], Bh[1][0], Bh[1][1], uVh + off);
            }
#pragma unroll
            for (int mi = 0; mi < 2; mi++)
#pragma unroll
                for (int nj = 0; nj < 2; nj++)
                    mma_f16(acc[mi][nj], Ah[mi], Bh[nj]);
        }
    }

    float* Wb = g_Wc + (size_t)(c * BATCH + b) * D_K * D_V;
#pragma unroll
    for (int mi = 0; mi < 2; mi++) {
        int n = wn * 32 + mi * 16 + g;
#pragma unroll
        for (int nj = 0; nj < 2; nj++) {
            int d = d0 + wd * 16 + nj * 8 + tig * 2;
            float2 lo; lo.x = acc[mi][nj][0]; lo.y = acc[mi][nj][1];
            float2 hi; hi.x = acc[mi][nj][2]; hi.y = acc[mi][nj][3];
            *(float2*)&Wb[(size_t)n * D_V + d] = lo;
            *(float2*)&Wb[(size_t)(n + 8) * D_V + d] = hi;
        }
    }
}

// ---------------- kernel 5: elementwise state scan; emit S_start fp16 -------------
__global__ void __launch_bounds__(256) state_scan_kernel() {
    int g = blockIdx.x * 256 + threadIdx.x;
    int bn = g >> 9;
    float s = 0.f;
    for (int c = 0; c < NC; c++) {
        size_t idx = (size_t)c * SEG + g;
        g_Sh[idx] = __float2half_rn(s);
        s = fmaf(s, g_pend[c * (BATCH * D_K) + bn], g_Wc[idx]);
    }
}

// ---------------- kernel 6: Y = [A|q_t] @ [V;S], d-tile 128, causal-zero skip -----
#define YPA 72                               // A pitch (128 rows x 64 k)
#define YPB 136                              // B pitch (64 k rows x 128 d)
#define YSTAGE (128 * YPA + 64 * YPB)        // 17920 fp16 elems = 35840 B
#define YG_SMEM (2 * YSTAGE * 2)             // 71680 B -> 2 CTAs/SM

__global__ void __launch_bounds__(128, 2) ygemm_mma_kernel(float* __restrict__ out) {
    extern __shared__ __half ysm[];
    uint32_t sb = smem_u32(ysm);

    int d0 = blockIdx.x * 128;
    int c = blockIdx.y, b = blockIdx.z;
    int tid = threadIdx.x, w = tid >> 5, lane = tid & 31;
    int g = lane >> 2, tig = lane & 3;
    int lq = lane & 7, lseg = lane >> 3;
    int arow = (lseg & 1) * 8 + lq;
    int asel = (lseg >> 1) * 8;

    size_t aqbase = (size_t)(c * BATCH + b) * CHUNK * AQW;
    size_t sbase  = (size_t)(c * BATCH + b) * D_K * D_V;

    float acc[2][16][4];
#pragma unroll
    for (int i = 0; i < 2; i++)
#pragma unroll
        for (int j = 0; j < 16; j++)
#pragma unroll
            for (int k = 0; k < 4; k++) acc[i][j][k] = 0.f;

    // stage layout per buffer: A[128][YPA], B[64][YPB]
#define YCOPY(ch, buf) do {                                                              \
    uint32_t base = sb + (uint32_t)(buf) * (YSTAGE * 2);                                 \
    _Pragma("unroll")                                                                    \
    for (int u = 0; u < 8; u++) {                                                        \
        int l = tid + u * 128;               /* 0..1023 : A 128x64 */                    \
        int rr = l >> 3, qq = l & 7;                                                     \
        size_t src = aqbase + rr * AQW + (ch) * 64 + qq * 8;                             \
        uint32_t so = (uint32_t)(rr * YPA + qq * 8) * 2;                                 \
        cp16(base + so, &g_AQh[src]);                                                    \
    }                                                                                    \
    _Pragma("unroll")                                                                    \
    for (int u = 0; u < 8; u++) {                                                        \
        int l = tid + u * 128;               /* 0..1023 : B 64x128 */                    \
        int rr = l >> 4, qq = l & 15;                                                    \
        uint32_t so = (uint32_t)(128 * YPA + rr * YPB + qq * 8) * 2;                     \
        if ((ch) < 2) {                                                                  \
            size_t src = (size_t)((c * CHUNK + (ch) * 64 + rr) * BATCH + b) * D_V + d0 + qq * 8; \
            cp16(base + so, &g_Vh[src]);                                                 \
        } else {                                                                         \
            size_t src = sbase + (size_t)rr * D_V + d0 + qq * 8;                         \
            cp16(base + so, &g_Sh[src]);                                                 \
        }                                                                                \
    }                                                                                    \
} while (0)

    YCOPY(0, 0);
    CP_COMMIT();

    for (int ch = 0; ch < 3; ch++) {
        if (ch + 1 < 3) { YCOPY(ch + 1, (ch + 1) & 1); CP_COMMIT(); }
        if (ch + 1 < 3) CP_WAIT(1); else CP_WAIT(0);
        __syncthreads();

        // causal-zero skip: ch==1 A cols are zero for t<64 (warps 0,1);
        // ch==2 uses S which is identically zero for c==0.
        bool active = !(ch == 1 && w < 2) && !(ch == 2 && c == 0);
        if (active) {
            uint32_t uA = sb + (uint32_t)(ch & 1) * (YSTAGE * 2);
            uint32_t uB = uA + 128 * YPA * 2;

#pragma unroll
            for (int ks = 0; ks < 64; ks += 16) {
                uint32_t Ah[2][4], Bh[16][2];
#pragma unroll
                for (int mi = 0; mi < 2; mi++) {
                    uint32_t off = (uint32_t)((w * 32 + mi * 16 + arow) * YPA + ks + asel) * 2;
                    ldm_x4(Ah[mi][0], Ah[mi][1], Ah[mi][2], Ah[mi][3], uA + off);
                }
                uint32_t row = ks + (lseg & 1) * 8 + lq;
#pragma unroll
                for (int nbs = 0; nbs < 8; nbs++) {
                    uint32_t col = nbs * 16 + (lseg >> 1) * 8;
                    uint32_t off = (row * YPB + col) * 2;
                    ldm_x4_trans(Bh[nbs * 2][0], Bh[nbs * 2][1], Bh[nbs * 2 + 1][0], Bh[nbs * 2 + 1][1], uB + off);
                }
#pragma unroll
                for (int mi = 0; mi < 2; mi++)
#pragma unroll
                    for (int nj = 0; nj < 16; nj++)
                        mma_f16(acc[mi][nj], Ah[mi], Bh[nj]);
            }
        }
        __syncthreads();
    }
#undef YCOPY

#pragma unroll
    for (int mi = 0; mi < 2; mi++) {
        int t = w * 32 + mi * 16 + g;
#pragma unroll
        for (int nj = 0; nj < 16; nj++) {
            int col = d0 + nj * 8 + tig * 2;
            float2 lo; lo.x = acc[mi][nj][0]; lo.y = acc[mi][nj][1];
            float2 hi; hi.x = acc[mi][nj][2]; hi.y = acc[mi][nj][3];
            *(float2*)&out[(size_t)((c * CHUNK + t) * BATCH + b) * D_V + col] = lo;
            *(float2*)&out[(size_t)((c * CHUNK + t + 8) * BATCH + b) * D_V + col] = hi;
        }
    }
}

// ---------------- launch ----------------
extern "C" void kernel_launch(void* const* d_in, const int* in_sizes, int n_in,
                              void* d_out, int out_size) {
    const float* x  = (const float*)d_in[0];
    const float* Wv = (const float*)d_in[1];
    const float* bv = (const float*)d_in[2];
    const float* Wk = (const float*)d_in[3];
    const float* bk = (const float*)d_in[4];
    const float* Wq = (const float*)d_in[5];
    const float* bq = (const float*)d_in[6];
    const float* Wa = (const float*)d_in[7];
    const float* ba = (const float*)d_in[8];
    float* out = (float*)d_out;

    cudaFuncSetAttribute(prep_kernel, cudaFuncAttributeMaxDynamicSharedMemorySize, PREP_SMEM);
    cudaFuncSetAttribute(gemm_mma_kernel, cudaFuncAttributeMaxDynamicSharedMemorySize, GM_SMEM);
    cudaFuncSetAttribute(contrib_kernel, cudaFuncAttributeMaxDynamicSharedMemorySize, CM_SMEM);
    cudaFuncSetAttribute(ygemm_mma_kernel, cudaFuncAttributeMaxDynamicSharedMemorySize, YG_SMEM);

    convpack_kernel<<<CONV_BLOCKS + PACK_BLOCKS, 256>>>(x, Wv, bv, Wk, bk, Wq, bq, Wa, ba);
    gemm_mma_kernel<<<dim3(11, MROWS / 128), 256, GM_SMEM>>>();
    prep_kernel<<<dim3(BATCH, NC), 256, PREP_SMEM>>>();
    contrib_kernel<<<dim3(D_V / 64, NC, BATCH), 256, CM_SMEM>>>();
    state_scan_kernel<<<SEG / 256, 256>>>();
    ygemm_mma_kernel<<<dim3(D_V / 128, NC, BATCH), 128, YG_SMEM>>>(out);
}